// round 2
// baseline (speedup 1.0000x reference)
#include <cuda_runtime.h>
#include <math.h>

// Problem constants
#define Tn   1536
#define Bn   4
#define Hn   8
#define DKn  64
#define DVn  192
#define Ln   3071          // 2T-1
#define HDK  512           // H*DK
#define HDV  1536          // H*DV
#define BT   6144          // B*T
#define NBH  32            // B*H

// ---------------- device scratch ----------------
__device__ float  g_Q[BT * HDK];
__device__ float  g_K[BT * HDK];
__device__ float  g_V[BT * HDV];
__device__ float  g_pe[Ln * 192];
__device__ float  g_rK[Ln * HDK];
__device__ float  g_bK[Bn * Hn * Tn];
__device__ float  g_bR[Hn * Ln];
__device__ float  g_logits[75497472];      // B*H*T*T = 4*8*1536*1536
__device__ float  g_attout[BT * HDV];
__device__ double g_gmax[32];

// ---------------- positional basis ----------------
// gamma basis: conc = (2(j+1))^2, rate = (j+1)/12 (derived from T=1536, NB=32)
__global__ void gamma_max_kernel(double* gmax) {
    __shared__ double red[256];
    int j = blockIdx.x, t = threadIdx.x;
    double conc  = 4.0 * (j + 1) * (j + 1);
    double rate  = (double)(j + 1) / 12.0;
    double lnorm = lgamma(conc) - conc * log(rate);
    double best = 0.0;
    for (int i = t; i < Ln; i += 256) {
        double pos = fabs((double)(i - (Tn - 1)));
        double lu = (conc - 1.0) * log(pos) - rate * pos;   // pos=0 -> -inf -> exp=0
        double pr = exp(lu - lnorm);
        if (pr > best) best = pr;
    }
    red[t] = best;
    __syncthreads();
    for (int s = 128; s; s >>= 1) {
        if (t < s) red[t] = fmax(red[t], red[t + s]);
        __syncthreads();
    }
    if (t == 0) gmax[j] = red[0] + 1e-8;
}

__global__ void pe_kernel(const double* __restrict__ gmax, float* __restrict__ pe) {
    int idx = blockIdx.x * blockDim.x + threadIdx.x;
    if (idx >= Ln * 32) return;
    int i = idx / 32, j = idx % 32;
    int dist = i - (Tn - 1);
    double pos = fabs((double)dist);
    // exponential
    double mr = log2((double)Tn);
    double hl = exp2(3.0 + (double)j * (mr - 3.0) / 31.0);
    double fe = exp2(-pos / hl);
    // central mask
    double width = exp2((double)(j + 1)) - 1.0;
    double fc = (width > pos) ? 1.0 : 0.0;
    // gamma
    double conc  = 4.0 * (j + 1) * (j + 1);
    double rate  = (double)(j + 1) / 12.0;
    double lnorm = lgamma(conc) - conc * log(rate);
    double pr = exp((conc - 1.0) * log(pos) - rate * pos - lnorm) + 1e-8;
    double fg = pr / gmax[j];
    float sgn = (dist > 0) ? 1.f : ((dist < 0) ? -1.f : 0.f);
    float* row = pe + (size_t)i * 192;
    row[j]       = (float)fe;
    row[32 + j]  = (float)fc;
    row[64 + j]  = (float)fg;
    row[96 + j]  = sgn * (float)fe;
    row[128 + j] = sgn * (float)fc;
    row[160 + j] = sgn * (float)fg;
}

// ---------------- generic tiled sgemm: C = scale*(A@B) (+bias) ----------------
// A[M,K] lda, B[K,N] ldb, C[M,N] ldc. N%64==0, K%16==0 required; M guarded.
__global__ void sgemm_kernel(const float* __restrict__ A, int lda,
                             const float* __restrict__ B, int ldb,
                             float* __restrict__ C, int ldc,
                             int M, int N, int K, float scale,
                             const float* __restrict__ bias) {
    __shared__ float As[16][68];
    __shared__ float Bs[16][68];
    int t  = threadIdx.x;
    int tx = t & 15, ty = t >> 4;
    int m0 = blockIdx.y * 64, n0 = blockIdx.x * 64;
    int ar = t >> 2, ac = (t & 3) * 4;     // A panel 64x16
    int br = t >> 4, bc = (t & 15) * 4;    // B panel 16x64
    float s[4][4] = {};

    for (int k0 = 0; k0 < K; k0 += 16) {
        float4 av = make_float4(0.f, 0.f, 0.f, 0.f);
        if (m0 + ar < M)
            av = *(const float4*)(A + (size_t)(m0 + ar) * lda + k0 + ac);
        float4 bv = *(const float4*)(B + (size_t)(k0 + br) * ldb + n0 + bc);
        __syncthreads();
        As[ac + 0][ar] = av.x;
        As[ac + 1][ar] = av.y;
        As[ac + 2][ar] = av.z;
        As[ac + 3][ar] = av.w;
        *(float4*)&Bs[br][bc] = bv;
        __syncthreads();
#pragma unroll
        for (int kk = 0; kk < 16; kk++) {
            float4 a = *(const float4*)&As[kk][ty * 4];
            float4 b = *(const float4*)&Bs[kk][tx * 4];
            s[0][0] += a.x * b.x; s[0][1] += a.x * b.y; s[0][2] += a.x * b.z; s[0][3] += a.x * b.w;
            s[1][0] += a.y * b.x; s[1][1] += a.y * b.y; s[1][2] += a.y * b.z; s[1][3] += a.y * b.w;
            s[2][0] += a.z * b.x; s[2][1] += a.z * b.y; s[2][2] += a.z * b.z; s[2][3] += a.z * b.w;
            s[3][0] += a.w * b.x; s[3][1] += a.w * b.y; s[3][2] += a.w * b.z; s[3][3] += a.w * b.w;
        }
    }
#pragma unroll
    for (int i = 0; i < 4; i++) {
        int m = m0 + ty * 4 + i;
        if (m < M) {
            float* cp = C + (size_t)m * ldc + n0 + tx * 4;
#pragma unroll
            for (int j = 0; j < 4; j++) {
                float r = scale * s[i][j];
                if (bias) r += bias[n0 + tx * 4 + j];
                cp[j] = r;
            }
        }
    }
}

// ---------------- bias tables ----------------
__global__ void bk_kernel(const float* __restrict__ rwb, const float* __restrict__ Kmat,
                          float* __restrict__ bK) {
    int n = blockIdx.x * 256 + threadIdx.x;
    if (n >= Bn * Hn * Tn) return;
    int k = n % Tn;
    int h = (n / Tn) & 7;
    int b = n / (Tn * Hn);
    const float* kp = Kmat + ((size_t)(b * Tn + k)) * HDK + h * DKn;
    const float* wp = rwb + h * DKn;
    float s = 0.f;
#pragma unroll
    for (int d = 0; d < DKn; d++) s += wp[d] * kp[d];
    bK[n] = s;
}

__global__ void br_kernel(const float* __restrict__ rrb, const float* __restrict__ rKmat,
                          float* __restrict__ bR) {
    int n = blockIdx.x * 256 + threadIdx.x;
    if (n >= Hn * Ln) return;
    int l = n % Ln;
    int h = n / Ln;
    const float* rp = rKmat + (size_t)l * HDK + h * DKn;
    const float* wp = rrb + h * DKn;
    float s = 0.f;
#pragma unroll
    for (int d = 0; d < DKn; d++) s += wp[d] * rp[d];
    bR[n] = s;
}

// ---------------- scores: logits[b,h,q,k] = Q.K + Q.rK[k-q+T-1] + bK + bR ----------------
// block: 256 threads, tile 64(q) x 64(k). smem: Q 64x68, K 64x68, R 128x68 + bias rows.
__global__ void scores_kernel(const float* __restrict__ Q, const float* __restrict__ K,
                              const float* __restrict__ rK, const float* __restrict__ bK,
                              const float* __restrict__ bR, float* __restrict__ logits) {
    extern __shared__ float sm[];
    float (*Qs)[68] = (float(*)[68])sm;                 // 64 rows
    float (*Ks)[68] = (float(*)[68])(sm + 64 * 68);     // 64 rows
    float (*Rs)[68] = (float(*)[68])(sm + 128 * 68);    // 128 rows (127 used)
    float* bKs = sm + 256 * 68;                         // 64
    float* bRs = bKs + 64;                              // 127

    int bh = blockIdx.z;
    int h = bh & 7, b = bh >> 3;
    int Q0 = blockIdx.y * 64, K0 = blockIdx.x * 64;
    int t = threadIdx.x;
    int lbase = K0 - Q0 + (Tn - 1) - 63;   // l for band row m=0; in [0, 2944]

    int lr = t >> 4, lc = (t & 15) * 4;
#pragma unroll
    for (int p = 0; p < 4; p++) {
        int r = lr + p * 16;
        *(float4*)&Qs[r][lc] = *(const float4*)(Q + ((size_t)(b * Tn + Q0 + r)) * HDK + h * DKn + lc);
        *(float4*)&Ks[r][lc] = *(const float4*)(K + ((size_t)(b * Tn + K0 + r)) * HDK + h * DKn + lc);
    }
#pragma unroll
    for (int p = 0; p < 8; p++) {
        int r = lr + p * 16;
        if (r < 127)
            *(float4*)&Rs[r][lc] = *(const float4*)(rK + (size_t)(lbase + r) * HDK + h * DKn + lc);
    }
    if (t < 64) bKs[t] = bK[(size_t)bh * Tn + K0 + t];
    if (t >= 64 && t < 64 + 127) bRs[t - 64] = bR[(size_t)h * Ln + lbase + (t - 64)];
    __syncthreads();

    int tx = t & 15, ty = t >> 4;
    int ty4 = ty * 4, tx4 = tx * 4;
    int mb3 = tx4 - ty4 + 60;   // (mbase-3), mbase = tx4-ty4+63; in [0,120]
    float s[4][4] = {};

#pragma unroll 2
    for (int dd = 0; dd < 64; dd += 4) {
        float4 q4[4], k4[4], r4[7];
#pragma unroll
        for (int i = 0; i < 4; i++) q4[i] = *(const float4*)&Qs[ty4 + i][dd];
#pragma unroll
        for (int j = 0; j < 4; j++) k4[j] = *(const float4*)&Ks[tx4 + j][dd];
#pragma unroll
        for (int u = 0; u < 7; u++) r4[u] = *(const float4*)&Rs[mb3 + u][dd];
#pragma unroll
        for (int i = 0; i < 4; i++)
#pragma unroll
            for (int j = 0; j < 4; j++) {
                float4 r = r4[j - i + 3];
                s[i][j] += q4[i].x * (k4[j].x + r.x) + q4[i].y * (k4[j].y + r.y)
                         + q4[i].z * (k4[j].z + r.z) + q4[i].w * (k4[j].w + r.w);
            }
    }

#pragma unroll
    for (int i = 0; i < 4; i++) {
        int q = Q0 + ty4 + i;
        float* lp = logits + ((size_t)bh * Tn + q) * Tn + K0 + tx4;
#pragma unroll
        for (int j = 0; j < 4; j++) {
            int m = tx4 + j - ty4 - i + 63;
            lp[j] = s[i][j] + bKs[tx4 + j] + bRs[m];
        }
    }
}

// ---------------- softmax over last dim (row = b,h,q; 1536 elems) ----------------
__global__ void softmax_kernel(float* __restrict__ logits) {
    __shared__ float red[8];
    size_t row = blockIdx.x;
    float* p = logits + row * Tn;
    int t = threadIdx.x;
    float v[6];
    float mx = -1e30f;
#pragma unroll
    for (int k = 0; k < 6; k++) {
        v[k] = p[t + k * 256];
        mx = fmaxf(mx, v[k]);
    }
#pragma unroll
    for (int o = 16; o; o >>= 1) mx = fmaxf(mx, __shfl_xor_sync(0xffffffffu, mx, o));
    if ((t & 31) == 0) red[t >> 5] = mx;
    __syncthreads();
    mx = red[0];
#pragma unroll
    for (int i = 1; i < 8; i++) mx = fmaxf(mx, red[i]);
    __syncthreads();
    float sum = 0.f;
#pragma unroll
    for (int k = 0; k < 6; k++) {
        v[k] = expf(v[k] - mx);
        sum += v[k];
    }
#pragma unroll
    for (int o = 16; o; o >>= 1) sum += __shfl_xor_sync(0xffffffffu, sum, o);
    if ((t & 31) == 0) red[t >> 5] = sum;
    __syncthreads();
    float tot = 0.f;
#pragma unroll
    for (int i = 0; i < 8; i++) tot += red[i];
    float inv = 1.0f / tot;
#pragma unroll
    for (int k = 0; k < 6; k++) p[t + k * 256] = v[k] * inv;
}

// ---------------- attn @ V, batched over (b,h) via blockIdx.z ----------------
__global__ void av_gemm_kernel(const float* __restrict__ logits, const float* __restrict__ V,
                               float* __restrict__ attout) {
    __shared__ float As[16][68];
    __shared__ float Bs[16][68];
    int z = blockIdx.z;
    int h = z & 7, b = z >> 3;
    const float* A  = logits + (size_t)z * Tn * Tn;                 // [T,T] lda=T
    const float* Bp = V + (size_t)b * Tn * HDV + h * DVn;           // ldb=HDV
    float* Cp = attout + (size_t)b * Tn * HDV + h * DVn;            // ldc=HDV
    int t = threadIdx.x;
    int tx = t & 15, ty = t >> 4;
    int m0 = blockIdx.y * 64, n0 = blockIdx.x * 64;                 // N=192 -> 3 tiles
    int ar = t >> 2, ac = (t & 3) * 4;
    int br = t >> 4, bc = (t & 15) * 4;
    float s[4][4] = {};

    for (int k0 = 0; k0 < Tn; k0 += 16) {
        float4 av = *(const float4*)(A + (size_t)(m0 + ar) * Tn + k0 + ac);
        float4 bv = *(const float4*)(Bp + (size_t)(k0 + br) * HDV + n0 + bc);
        __syncthreads();
        As[ac + 0][ar] = av.x;
        As[ac + 1][ar] = av.y;
        As[ac + 2][ar] = av.z;
        As[ac + 3][ar] = av.w;
        *(float4*)&Bs[br][bc] = bv;
        __syncthreads();
#pragma unroll
        for (int kk = 0; kk < 16; kk++) {
            float4 a = *(const float4*)&As[kk][ty * 4];
            float4 b4 = *(const float4*)&Bs[kk][tx * 4];
            s[0][0] += a.x * b4.x; s[0][1] += a.x * b4.y; s[0][2] += a.x * b4.z; s[0][3] += a.x * b4.w;
            s[1][0] += a.y * b4.x; s[1][1] += a.y * b4.y; s[1][2] += a.y * b4.z; s[1][3] += a.y * b4.w;
            s[2][0] += a.z * b4.x; s[2][1] += a.z * b4.y; s[2][2] += a.z * b4.z; s[2][3] += a.z * b4.w;
            s[3][0] += a.w * b4.x; s[3][1] += a.w * b4.y; s[3][2] += a.w * b4.z; s[3][3] += a.w * b4.w;
        }
    }
#pragma unroll
    for (int i = 0; i < 4; i++) {
        float* cp = Cp + (size_t)(m0 + ty * 4 + i) * HDV + n0 + tx * 4;
#pragma unroll
        for (int j = 0; j < 4; j++) cp[j] = s[i][j];
    }
}

// ---------------- launch ----------------
extern "C" void kernel_launch(void* const* d_in, const int* in_sizes, int n_in,
                              void* d_out, int out_size) {
    const float* x       = (const float*)d_in[0];
    const float* W_q     = (const float*)d_in[1];
    const float* W_k     = (const float*)d_in[2];
    const float* W_v     = (const float*)d_in[3];
    const float* W_rel_k = (const float*)d_in[4];
    const float* W_out   = (const float*)d_in[5];
    const float* b_out   = (const float*)d_in[6];
    const float* rwb     = (const float*)d_in[7];
    const float* rrb     = (const float*)d_in[8];
    float* out = (float*)d_out;

    float *Q, *K, *V, *pe, *rK, *bK, *bR, *logits, *attout;
    double* gmax;
    cudaGetSymbolAddress((void**)&Q, g_Q);
    cudaGetSymbolAddress((void**)&K, g_K);
    cudaGetSymbolAddress((void**)&V, g_V);
    cudaGetSymbolAddress((void**)&pe, g_pe);
    cudaGetSymbolAddress((void**)&rK, g_rK);
    cudaGetSymbolAddress((void**)&bK, g_bK);
    cudaGetSymbolAddress((void**)&bR, g_bR);
    cudaGetSymbolAddress((void**)&logits, g_logits);
    cudaGetSymbolAddress((void**)&attout, g_attout);
    cudaGetSymbolAddress((void**)&gmax, g_gmax);

    // scores kernel needs > 48KB dynamic smem
    int score_smem = (256 * 68 + 64 + 128) * (int)sizeof(float);
    cudaFuncSetAttribute(scores_kernel, cudaFuncAttributeMaxDynamicSharedMemorySize, score_smem);

    // 1) positional basis
    gamma_max_kernel<<<32, 256>>>(gmax);
    pe_kernel<<<(Ln * 32 + 255) / 256, 256>>>(gmax, pe);

    // 2) rK = pe @ W_rel_k   [3071,192]x[192,512]
    sgemm_kernel<<<dim3(HDK / 64, (Ln + 63) / 64), 256>>>(pe, 192, W_rel_k, HDK, rK, HDK,
                                                          Ln, HDK, 192, 1.0f, nullptr);

    // 3) Q/K/V projections
    sgemm_kernel<<<dim3(HDK / 64, BT / 64), 256>>>(x, 1536, W_q, HDK, Q, HDK,
                                                   BT, HDK, 1536, 0.125f, nullptr);
    sgemm_kernel<<<dim3(HDK / 64, BT / 64), 256>>>(x, 1536, W_k, HDK, K, HDK,
                                                   BT, HDK, 1536, 1.0f, nullptr);
    sgemm_kernel<<<dim3(HDV / 64, BT / 64), 256>>>(x, 1536, W_v, HDV, V, HDV,
                                                   BT, HDV, 1536, 1.0f, nullptr);

    // 4) bias tables
    bk_kernel<<<(Bn * Hn * Tn + 255) / 256, 256>>>(rwb, K, bK);
    br_kernel<<<(Hn * Ln + 255) / 256, 256>>>(rrb, rK, bR);

    // 5) logits
    scores_kernel<<<dim3(Tn / 64, Tn / 64, NBH), 256, score_smem>>>(Q, K, rK, bK, bR, logits);

    // 6) softmax
    softmax_kernel<<<NBH * Tn, 256>>>(logits);

    // 7) attn @ V
    av_gemm_kernel<<<dim3(DVn / 64, Tn / 64, NBH), 256>>>(logits, V, attout);

    // 8) final projection + bias
    sgemm_kernel<<<dim3(HDV / 64, BT / 64), 256>>>(attout, HDV, W_out, HDV, out, HDV,
                                                   BT, HDV, 1536, 1.0f, b_out);
}

// round 4
// speedup vs baseline: 4.3531x; 4.3531x over previous
#include <cuda_runtime.h>
#include <cuda_bf16.h>
#include <math.h>
#include <stdint.h>

// Problem constants
#define Tn   1536
#define Bn   4
#define Hn   8
#define DKn  64
#define DVn  192
#define Ln   3071          // 2T-1
#define Lp   3072          // padded
#define HDK  512           // H*DK
#define HDV  1536          // H*DV
#define BT   6144          // B*T
#define NBH  32            // B*H
#define Cin  1536
#define VPAD 256           // padded DV rows for AV gemm

typedef __nv_bfloat16 bf16;

// ---------------- device scratch ----------------
__device__ float  g_pe[Ln * 192];
__device__ float  g_rK[Ln * HDK];
__device__ double g_gmax[32];

__device__ float  g_Qf[BT * HDK];
__device__ float  g_Kf[BT * HDK];
__device__ float  g_Vf[BT * HDV];

__device__ bf16   g_xh[BT * Cin], g_xl[BT * Cin];
__device__ bf16   g_wqth[HDK * Cin], g_wqtl[HDK * Cin];
__device__ bf16   g_wkth[HDK * Cin], g_wktl[HDK * Cin];
__device__ bf16   g_wvth[HDV * Cin], g_wvtl[HDV * Cin];
__device__ bf16   g_woth[HDV * HDV], g_wotl[HDV * HDV];

__device__ bf16   g_qwh[NBH * Tn * DKn], g_qwl[NBH * Tn * DKn];
__device__ bf16   g_qrh[NBH * Tn * DKn], g_qrl[NBH * Tn * DKn];
__device__ bf16   g_kh [NBH * Tn * DKn], g_kl [NBH * Tn * DKn];
__device__ bf16   g_rkth[NBH * Lp * DKn], g_rktl[NBH * Lp * DKn];
__device__ bf16   g_vth[NBH * VPAD * Tn], g_vtl[NBH * VPAD * Tn];  // pad rows stay 0 (BSS)

__device__ float  g_content[75497472];            // 32*1536*1536
__device__ float  g_rel[150994944];               // 32*1536*3072
__device__ bf16   g_ah[75497472], g_al[75497472]; // attn hi/lo
__device__ float  g_ao[BT * HDV];
__device__ bf16   g_aoh[BT * HDV], g_aol[BT * HDV];

// ============================================================
// helpers
// ============================================================
__device__ __forceinline__ uint32_t smem_u32(const void* p) {
    uint32_t a;
    asm("{ .reg .u64 t; cvta.to.shared.u64 t, %1; cvt.u32.u64 %0, t; }" : "=r"(a) : "l"(p));
    return a;
}
__device__ __forceinline__ void cp16(uint32_t s, const void* g) {
    asm volatile("cp.async.ca.shared.global [%0], [%1], 16;" :: "r"(s), "l"(g));
}
#define CP_COMMIT() asm volatile("cp.async.commit_group;" ::: "memory")
#define CP_WAIT0()  asm volatile("cp.async.wait_group 0;" ::: "memory")

#define LDSM4(r, addr) \
    asm volatile("ldmatrix.sync.aligned.m8n8.x4.shared.b16 {%0,%1,%2,%3}, [%4];" \
        : "=r"((r)[0]), "=r"((r)[1]), "=r"((r)[2]), "=r"((r)[3]) : "r"(addr))

#define MMA(acc, a, b) \
    asm volatile("mma.sync.aligned.m16n8k16.row.col.f32.bf16.bf16.f32 " \
        "{%0,%1,%2,%3},{%4,%5,%6,%7},{%8,%9},{%0,%1,%2,%3};" \
        : "+f"((acc)[0]), "+f"((acc)[1]), "+f"((acc)[2]), "+f"((acc)[3]) \
        : "r"((a)[0]), "r"((a)[1]), "r"((a)[2]), "r"((a)[3]), "r"((b)[0]), "r"((b)[1]))

// ---------------- positional basis (validated) ----------------
__global__ void gamma_max_kernel(double* gmax) {
    __shared__ double red[256];
    int j = blockIdx.x, t = threadIdx.x;
    double conc  = 4.0 * (j + 1) * (j + 1);
    double rate  = (double)(j + 1) / 12.0;
    double lnorm = lgamma(conc) - conc * log(rate);
    double best = 0.0;
    for (int i = t; i < Ln; i += 256) {
        double pos = fabs((double)(i - (Tn - 1)));
        double lu = (conc - 1.0) * log(pos) - rate * pos;
        double pr = exp(lu - lnorm);
        if (pr > best) best = pr;
    }
    red[t] = best;
    __syncthreads();
    for (int s = 128; s; s >>= 1) {
        if (t < s) red[t] = fmax(red[t], red[t + s]);
        __syncthreads();
    }
    if (t == 0) gmax[j] = red[0] + 1e-8;
}

__global__ void pe_kernel(const double* __restrict__ gmax, float* __restrict__ pe) {
    int idx = blockIdx.x * blockDim.x + threadIdx.x;
    if (idx >= Ln * 32) return;
    int i = idx / 32, j = idx % 32;
    int dist = i - (Tn - 1);
    double pos = fabs((double)dist);
    double mr = log2((double)Tn);
    double hl = exp2(3.0 + (double)j * (mr - 3.0) / 31.0);
    double fe = exp2(-pos / hl);
    double width = exp2((double)(j + 1)) - 1.0;
    double fc = (width > pos) ? 1.0 : 0.0;
    double conc  = 4.0 * (j + 1) * (j + 1);
    double rate  = (double)(j + 1) / 12.0;
    double lnorm = lgamma(conc) - conc * log(rate);
    double pr = exp((conc - 1.0) * log(pos) - rate * pos - lnorm) + 1e-8;
    double fg = pr / gmax[j];
    float sgn = (dist > 0) ? 1.f : ((dist < 0) ? -1.f : 0.f);
    float* row = pe + (size_t)i * 192;
    row[j]       = (float)fe;
    row[32 + j]  = (float)fc;
    row[64 + j]  = (float)fg;
    row[96 + j]  = sgn * (float)fe;
    row[128 + j] = sgn * (float)fc;
    row[160 + j] = sgn * (float)fg;
}

// ---------------- small fp32 sgemm (rK only) ----------------
__global__ void sgemm_kernel(const float* __restrict__ A, int lda,
                             const float* __restrict__ B, int ldb,
                             float* __restrict__ C, int ldc,
                             int M, int N, int K) {
    __shared__ float As[16][68];
    __shared__ float Bs[16][68];
    int t  = threadIdx.x;
    int tx = t & 15, ty = t >> 4;
    int m0 = blockIdx.y * 64, n0 = blockIdx.x * 64;
    int ar = t >> 2, ac = (t & 3) * 4;
    int br = t >> 4, bc = (t & 15) * 4;
    float s[4][4] = {};
    for (int k0 = 0; k0 < K; k0 += 16) {
        float4 av = make_float4(0.f, 0.f, 0.f, 0.f);
        if (m0 + ar < M)
            av = *(const float4*)(A + (size_t)(m0 + ar) * lda + k0 + ac);
        float4 bv = *(const float4*)(B + (size_t)(k0 + br) * ldb + n0 + bc);
        __syncthreads();
        As[ac + 0][ar] = av.x; As[ac + 1][ar] = av.y;
        As[ac + 2][ar] = av.z; As[ac + 3][ar] = av.w;
        *(float4*)&Bs[br][bc] = bv;
        __syncthreads();
#pragma unroll
        for (int kk = 0; kk < 16; kk++) {
            float4 a = *(const float4*)&As[kk][ty * 4];
            float4 b = *(const float4*)&Bs[kk][tx * 4];
            s[0][0] += a.x * b.x; s[0][1] += a.x * b.y; s[0][2] += a.x * b.z; s[0][3] += a.x * b.w;
            s[1][0] += a.y * b.x; s[1][1] += a.y * b.y; s[1][2] += a.y * b.z; s[1][3] += a.y * b.w;
            s[2][0] += a.z * b.x; s[2][1] += a.z * b.y; s[2][2] += a.z * b.z; s[2][3] += a.z * b.w;
            s[3][0] += a.w * b.x; s[3][1] += a.w * b.y; s[3][2] += a.w * b.z; s[3][3] += a.w * b.w;
        }
    }
#pragma unroll
    for (int i = 0; i < 4; i++) {
        int m = m0 + ty * 4 + i;
        if (m < M) {
            float* cp = C + (size_t)m * ldc + n0 + tx * 4;
#pragma unroll
            for (int j = 0; j < 4; j++) cp[j] = s[i][j];
        }
    }
}

// ---------------- hi/lo split helpers ----------------
__device__ __forceinline__ void split_store(float v, bf16* hi, bf16* lo, long o) {
    bf16 h = __float2bfloat16(v);
    hi[o] = h;
    lo[o] = __float2bfloat16(v - __bfloat162float(h));
}

__global__ void split_kernel(const float* __restrict__ src, bf16* __restrict__ hi,
                             bf16* __restrict__ lo, int n) {
    int i = blockIdx.x * 256 + threadIdx.x;
    if (i < n) split_store(src[i], hi, lo, i);
}

// transpose+split: src [K][N] fp32 -> dst hi/lo [N][K] bf16
__global__ void tsplit_kernel(const float* __restrict__ src, int K, int N,
                              bf16* __restrict__ hi, bf16* __restrict__ lo) {
    __shared__ float tile[32][33];
    int n0 = blockIdx.x * 32, k0 = blockIdx.y * 32;
    int tx = threadIdx.x & 31, ty = threadIdx.x >> 5;
#pragma unroll
    for (int i = 0; i < 32; i += 8)
        tile[ty + i][tx] = src[(long)(k0 + ty + i) * N + n0 + tx];
    __syncthreads();
#pragma unroll
    for (int i = 0; i < 32; i += 8) {
        float v = tile[tx][ty + i];   // = src[k0+tx][n0+ty+i]
        long o = (long)(n0 + ty + i) * K + k0 + tx;
        split_store(v, hi, lo, o);
    }
}

// Qf/Kf [b*t][h*64] -> per-(b,h) [z][t][64] hi/lo, r_w/r_r folded into Q
__global__ void qkhead_kernel(const float* __restrict__ Qf, const float* __restrict__ Kf,
                              const float* __restrict__ rwb, const float* __restrict__ rrb,
                              bf16* qwh, bf16* qwl, bf16* qrh, bf16* qrl, bf16* kh, bf16* kl) {
    long i = (long)blockIdx.x * 256 + threadIdx.x;
    if (i >= (long)NBH * Tn * DKn) return;
    int d = (int)(i & 63);
    int q = (int)((i >> 6) % Tn);
    int z = (int)(i / ((long)Tn * DKn));
    int h = z & 7, b = z >> 3;
    long src = ((long)(b * Tn + q)) * HDK + h * DKn + d;
    float qv = Qf[src], kv = Kf[src];
    split_store(qv + rwb[h * DKn + d], qwh, qwl, i);
    split_store(qv + rrb[h * DKn + d], qrh, qrl, i);
    split_store(kv, kh, kl, i);
}

// rK [3071][512] -> rKt [z][3072][64] hi/lo (replicated over b, zero pad row 3071)
__global__ void rkt_kernel(const float* __restrict__ rK, bf16* rkth, bf16* rktl) {
    long i = (long)blockIdx.x * 256 + threadIdx.x;
    if (i >= (long)NBH * Lp * DKn) return;
    int d = (int)(i & 63);
    int l = (int)((i >> 6) % Lp);
    int z = (int)(i / ((long)Lp * DKn));
    float v = (l < Ln) ? rK[(long)l * HDK + (z & 7) * DKn + d] : 0.f;
    split_store(v, rkth, rktl, i);
}

// Vf [b*t][h*192+d] -> Vt [z][d][t] hi/lo (d padded to VPAD rows)
__global__ void vt_kernel(const float* __restrict__ Vf, bf16* vth, bf16* vtl) {
    __shared__ float tile[32][33];
    int z = blockIdx.z, h = z & 7, b = z >> 3;
    int t0 = blockIdx.x * 32, d0 = blockIdx.y * 32;
    int tx = threadIdx.x & 31, ty = threadIdx.x >> 5;
#pragma unroll
    for (int i = 0; i < 32; i += 8)
        tile[ty + i][tx] = Vf[((long)(b * Tn + t0 + ty + i)) * HDV + h * DVn + d0 + tx];
    __syncthreads();
#pragma unroll
    for (int i = 0; i < 32; i += 8) {
        float v = tile[tx][ty + i];    // = Vf[t0+tx][d0+ty+i]
        long o = ((long)z * VPAD + d0 + ty + i) * Tn + t0 + tx;
        split_store(v, vth, vtl, o);
    }
}

// ============================================================
// mma.sync bf16 GEMM: C[M,N] = scale*((Ah+Al)·(Bh+Bl)^T) (+bias)
// A: [m][K] K-major, B: [n][K] K-major, C fp32 [m][ldc].
// Block 128x128, 8 warps (2x4), warp tile 64x32, K stage 32, cp.async 2-stage.
// ============================================================
__global__ void __launch_bounds__(256) gemm_mma(
    const bf16* __restrict__ Ah, const bf16* __restrict__ Al, int lda, long sA8, long sA1,
    const bf16* __restrict__ Bh, const bf16* __restrict__ Bl, int ldb, long sB8, long sB1,
    float* __restrict__ C, int ldc, long sC8, long sC1,
    int Kdim, int Ncols, float scale, const float* __restrict__ bias)
{
    extern __shared__ char smem[];
    const int TILE  = 128 * 80;       // one 128x32 bf16 tile, 80B row stride
    const int STAGE = 4 * TILE;       // Ah, Al, Bh, Bl
    uint32_t sb = smem_u32(smem);
    int tid = threadIdx.x, lane = tid & 31, wid = tid >> 5;
    int wm = wid >> 2, wn = wid & 3;
    int z = blockIdx.z;
    int m0 = blockIdx.y * 128, n0 = blockIdx.x * 128;

    long zo_a = (long)(z >> 3) * sA8 + (long)(z & 7) * sA1;
    long zo_b = (long)(z >> 3) * sB8 + (long)(z & 7) * sB1;
    long zo_c = (long)(z >> 3) * sC8 + (long)(z & 7) * sC1;
    const bf16* pAh = Ah + zo_a + (long)m0 * lda;
    const bf16* pAl = Al + zo_a + (long)m0 * lda;
    const bf16* pBh = Bh + zo_b + (long)n0 * ldb;
    const bf16* pBl = Bl + zo_b + (long)n0 * ldb;

    float acc[4][4][4] = {};
    const int NC = Kdim >> 5;

    // ---- prefetch stage kc ----
    auto prefetch = [&](int kc) {
        int k0 = kc * 32;
        uint32_t s0 = sb + (kc & 1) * STAGE;
        for (int i = tid; i < 512; i += 256) {
            int r = i >> 2, c = i & 3;
            uint32_t so = (uint32_t)(r * 80 + c * 16);
            long goA = (long)r * lda + k0 + c * 8;
            long goB = (long)r * ldb + k0 + c * 8;
            cp16(s0 + so,            pAh + goA);
            cp16(s0 + TILE + so,     pAl + goA);
            cp16(s0 + 2 * TILE + so, pBh + goB);
            cp16(s0 + 3 * TILE + so, pBl + goB);
        }
        CP_COMMIT();
    };

    prefetch(0);
    for (int kc = 0; kc < NC; kc++) {
        CP_WAIT0();
        __syncthreads();
        if (kc + 1 < NC) prefetch(kc + 1);
        uint32_t s0 = sb + (kc & 1) * STAGE;

#pragma unroll
        for (int kk = 0; kk < 2; kk++) {
            int k16 = kk * 16;
            uint32_t ah[4][4], al[4][4], bh[4][2], bl[4][2];
            // A fragments: x4 covers 16x16 (m-half x k-half ordering)
            uint32_t arow = (uint32_t)(wm * 64 + (lane & 15));
            uint32_t acol = (uint32_t)(k16 + (lane >> 4) * 8);
#pragma unroll
            for (int mi = 0; mi < 4; mi++) {
                uint32_t ao = s0 + (arow + mi * 16) * 80 + acol * 2;
                LDSM4(ah[mi], ao);
                LDSM4(al[mi], ao + TILE);
            }
            // B fragments: x4 covers two n8 tiles
            uint32_t brow = (uint32_t)(wn * 32 + (lane & 7) + ((lane >> 4) & 1) * 8);
            uint32_t bcol = (uint32_t)(k16 + ((lane >> 3) & 1) * 8);
#pragma unroll
            for (int g = 0; g < 2; g++) {
                uint32_t t4[4];
                uint32_t bo = s0 + 2 * TILE + (brow + g * 16) * 80 + bcol * 2;
                LDSM4(t4, bo);
                bh[g * 2][0] = t4[0]; bh[g * 2][1] = t4[1];
                bh[g * 2 + 1][0] = t4[2]; bh[g * 2 + 1][1] = t4[3];
                LDSM4(t4, bo + TILE);
                bl[g * 2][0] = t4[0]; bl[g * 2][1] = t4[1];
                bl[g * 2 + 1][0] = t4[2]; bl[g * 2 + 1][1] = t4[3];
            }
#pragma unroll
            for (int mi = 0; mi < 4; mi++)
#pragma unroll
                for (int ni = 0; ni < 4; ni++) {
                    MMA(acc[mi][ni], ah[mi], bh[ni]);
                    MMA(acc[mi][ni], ah[mi], bl[ni]);
                    MMA(acc[mi][ni], al[mi], bh[ni]);
                }
        }
        __syncthreads();
    }

    // ---- epilogue ----
    int gID = lane >> 2, tig = lane & 3;
#pragma unroll
    for (int mi = 0; mi < 4; mi++) {
#pragma unroll
        for (int ni = 0; ni < 4; ni++) {
            int row0 = m0 + wm * 64 + mi * 16 + gID;
            int col  = n0 + wn * 32 + ni * 8 + tig * 2;
            if (col < Ncols) {
                float b0 = bias ? bias[col] : 0.f;
                float b1 = bias ? bias[col + 1] : 0.f;
                float* p0 = C + zo_c + (long)row0 * ldc + col;
                float* p1 = C + zo_c + (long)(row0 + 8) * ldc + col;
                float2 v0 = make_float2(acc[mi][ni][0] * scale + b0, acc[mi][ni][1] * scale + b1);
                float2 v1 = make_float2(acc[mi][ni][2] * scale + b0, acc[mi][ni][3] * scale + b1);
                *(float2*)p0 = v0;
                *(float2*)p1 = v1;
            }
        }
    }
}

// ---------------- fused shift + add + softmax -> attn hi/lo ----------------
__global__ void softmax_shift_kernel(const float* __restrict__ content, const float* __restrict__ rel,
                                     bf16* __restrict__ ah, bf16* __restrict__ al) {
    __shared__ float red[8];
    size_t row = blockIdx.x;              // z*T + q
    int q = (int)(row % Tn);
    const float* pc = content + row * Tn;
    const float* pr = rel + row * (size_t)Lp + (Tn - 1 - q);
    int t = threadIdx.x;
    float v[6];
    float mx = -1e30f;
#pragma unroll
    for (int k = 0; k < 6; k++) {
        int i = t + k * 256;
        v[k] = pc[i] + pr[i];
        mx = fmaxf(mx, v[k]);
    }
#pragma unroll
    for (int o = 16; o; o >>= 1) mx = fmaxf(mx, __shfl_xor_sync(0xffffffffu, mx, o));
    if ((t & 31) == 0) red[t >> 5] = mx;
    __syncthreads();
    mx = red[0];
#pragma unroll
    for (int i = 1; i < 8; i++) mx = fmaxf(mx, red[i]);
    __syncthreads();
    float sum = 0.f;
#pragma unroll
    for (int k = 0; k < 6; k++) {
        v[k] = expf(v[k] - mx);
        sum += v[k];
    }
#pragma unroll
    for (int o = 16; o; o >>= 1) sum += __shfl_xor_sync(0xffffffffu, sum, o);
    if ((t & 31) == 0) red[t >> 5] = sum;
    __syncthreads();
    float tot = 0.f;
#pragma unroll
    for (int i = 0; i < 8; i++) tot += red[i];
    float inv = 1.0f / tot;
#pragma unroll
    for (int k = 0; k < 6; k++) {
        int i = t + k * 256;
        float a = v[k] * inv;
        bf16 h = __float2bfloat16(a);
        ah[row * Tn + i] = h;
        al[row * Tn + i] = __float2bfloat16(a - __bfloat162float(h));
    }
}

// ---------------- launch ----------------
extern "C" void kernel_launch(void* const* d_in, const int* in_sizes, int n_in,
                              void* d_out, int out_size) {
    const float* x       = (const float*)d_in[0];
    const float* W_q     = (const float*)d_in[1];
    const float* W_k     = (const float*)d_in[2];
    const float* W_v     = (const float*)d_in[3];
    const float* W_rel_k = (const float*)d_in[4];
    const float* W_out   = (const float*)d_in[5];
    const float* b_out   = (const float*)d_in[6];
    const float* rwb     = (const float*)d_in[7];
    const float* rrb     = (const float*)d_in[8];
    float* out = (float*)d_out;

    float *pe, *rK, *Qf, *Kf, *Vf, *content, *rel, *ao;
    double* gmax;
    bf16 *xh, *xl, *wqth, *wqtl, *wkth, *wktl, *wvth, *wvtl, *woth, *wotl;
    bf16 *qwh, *qwl, *qrh, *qrl, *kh, *kl, *rkth, *rktl, *vth, *vtl, *ah, *al, *aoh, *aol;
    cudaGetSymbolAddress((void**)&pe, g_pe);
    cudaGetSymbolAddress((void**)&rK, g_rK);
    cudaGetSymbolAddress((void**)&gmax, g_gmax);
    cudaGetSymbolAddress((void**)&Qf, g_Qf);
    cudaGetSymbolAddress((void**)&Kf, g_Kf);
    cudaGetSymbolAddress((void**)&Vf, g_Vf);
    cudaGetSymbolAddress((void**)&xh, g_xh);   cudaGetSymbolAddress((void**)&xl, g_xl);
    cudaGetSymbolAddress((void**)&wqth, g_wqth); cudaGetSymbolAddress((void**)&wqtl, g_wqtl);
    cudaGetSymbolAddress((void**)&wkth, g_wkth); cudaGetSymbolAddress((void**)&wktl, g_wktl);
    cudaGetSymbolAddress((void**)&wvth, g_wvth); cudaGetSymbolAddress((void**)&wvtl, g_wvtl);
    cudaGetSymbolAddress((void**)&woth, g_woth); cudaGetSymbolAddress((void**)&wotl, g_wotl);
    cudaGetSymbolAddress((void**)&qwh, g_qwh); cudaGetSymbolAddress((void**)&qwl, g_qwl);
    cudaGetSymbolAddress((void**)&qrh, g_qrh); cudaGetSymbolAddress((void**)&qrl, g_qrl);
    cudaGetSymbolAddress((void**)&kh, g_kh);   cudaGetSymbolAddress((void**)&kl, g_kl);
    cudaGetSymbolAddress((void**)&rkth, g_rkth); cudaGetSymbolAddress((void**)&rktl, g_rktl);
    cudaGetSymbolAddress((void**)&vth, g_vth); cudaGetSymbolAddress((void**)&vtl, g_vtl);
    cudaGetSymbolAddress((void**)&content, g_content);
    cudaGetSymbolAddress((void**)&rel, g_rel);
    cudaGetSymbolAddress((void**)&ah, g_ah);   cudaGetSymbolAddress((void**)&al, g_al);
    cudaGetSymbolAddress((void**)&ao, g_ao);
    cudaGetSymbolAddress((void**)&aoh, g_aoh); cudaGetSymbolAddress((void**)&aol, g_aol);

    const int GSMEM = 2 * 4 * 128 * 80;   // 81920 bytes
    cudaFuncSetAttribute(gemm_mma, cudaFuncAttributeMaxDynamicSharedMemorySize, GSMEM);

    // 1) positional basis + rK (fp32)
    gamma_max_kernel<<<32, 256>>>(gmax);
    pe_kernel<<<(Ln * 32 + 255) / 256, 256>>>(gmax, pe);
    sgemm_kernel<<<dim3(HDK / 64, (Ln + 63) / 64), 256>>>(pe, 192, W_rel_k, HDK, rK, HDK, Ln, HDK, 192);

    // 2) operand prep
    split_kernel<<<(BT * Cin + 255) / 256, 256>>>(x, xh, xl, BT * Cin);
    tsplit_kernel<<<dim3(HDK / 32, Cin / 32), 256>>>(W_q, Cin, HDK, wqth, wqtl);
    tsplit_kernel<<<dim3(HDK / 32, Cin / 32), 256>>>(W_k, Cin, HDK, wkth, wktl);
    tsplit_kernel<<<dim3(HDV / 32, Cin / 32), 256>>>(W_v, Cin, HDV, wvth, wvtl);
    tsplit_kernel<<<dim3(HDV / 32, HDV / 32), 256>>>(W_out, HDV, HDV, woth, wotl);

    // 3) Q/K/V projections (tensor cores), Q pre-scaled by DK^-1/2
    gemm_mma<<<dim3(HDK / 128, BT / 128, 1), 256, GSMEM>>>(
        xh, xl, Cin, 0, 0, wqth, wqtl, Cin, 0, 0, Qf, HDK, 0, 0, Cin, HDK, 0.125f, nullptr);
    gemm_mma<<<dim3(HDK / 128, BT / 128, 1), 256, GSMEM>>>(
        xh, xl, Cin, 0, 0, wkth, wktl, Cin, 0, 0, Kf, HDK, 0, 0, Cin, HDK, 1.0f, nullptr);
    gemm_mma<<<dim3(HDV / 128, BT / 128, 1), 256, GSMEM>>>(
        xh, xl, Cin, 0, 0, wvth, wvtl, Cin, 0, 0, Vf, HDV, 0, 0, Cin, HDV, 1.0f, nullptr);

    // 4) head reshapes + bias folds + splits
    qkhead_kernel<<<(int)(((long)NBH * Tn * DKn + 255) / 256), 256>>>(
        Qf, Kf, rwb, rrb, qwh, qwl, qrh, qrl, kh, kl);
    rkt_kernel<<<(int)(((long)NBH * Lp * DKn + 255) / 256), 256>>>(rK, rkth, rktl);
    vt_kernel<<<dim3(Tn / 32, DVn / 32, NBH), 256>>>(Vf, vth, vtl);

    // 5) content = (Q+r_w)·K^T  per (b,h): M=1536,N=1536,K=64
    long sQ = (long)Tn * DKn;
    gemm_mma<<<dim3(Tn / 128, Tn / 128, NBH), 256, GSMEM>>>(
        qwh, qwl, DKn, 8 * sQ, sQ, kh, kl, DKn, 8 * sQ, sQ,
        content, Tn, 8L * Tn * Tn, (long)Tn * Tn, DKn, Tn, 1.0f, nullptr);

    // 6) rel = (Q+r_r)·rK^T  per (b,h): M=1536,N=3072,K=64
    long sR = (long)Lp * DKn;
    gemm_mma<<<dim3(Lp / 128, Tn / 128, NBH), 256, GSMEM>>>(
        qrh, qrl, DKn, 8 * sQ, sQ, rkth, rktl, DKn, 8 * sR, sR,
        rel, Lp, 8L * Tn * Lp, (long)Tn * Lp, DKn, Lp, 1.0f, nullptr);

    // 7) shift + add + softmax -> attn hi/lo
    softmax_shift_kernel<<<NBH * Tn, 256>>>(content, rel, ah, al);

    // 8) out_att = attn·V  per (b,h): M=1536,N=192(pad 256),K=1536
    gemm_mma<<<dim3(2, Tn / 128, NBH), 256, GSMEM>>>(
        ah, al, Tn, 8L * Tn * Tn, (long)Tn * Tn,
        vth, vtl, Tn, 8L * VPAD * Tn, (long)VPAD * Tn,
        ao, HDV, (long)Tn * HDV, DVn, Tn, DVn, 1.0f, nullptr);

    // 9) final projection
    split_kernel<<<(BT * HDV + 255) / 256, 256>>>(ao, aoh, aol, BT * HDV);
    gemm_mma<<<dim3(HDV / 128, BT / 128, 1), 256, GSMEM>>>(
        aoh, aol, HDV, 0, 0, woth, wotl, HDV, 0, 0, out, HDV, 0, 0, HDV, HDV, 1.0f, b_out);
}

// round 5
// speedup vs baseline: 4.3702x; 1.0039x over previous
#include <cuda_runtime.h>
#include <cuda_bf16.h>
#include <math.h>
#include <stdint.h>

// Problem constants
#define Tn   1536
#define Bn   4
#define Hn   8
#define DKn  64
#define DVn  192
#define Ln   3071          // 2T-1
#define Lp   3072          // padded
#define HDK  512           // H*DK
#define HDV  1536          // H*DV
#define BT   6144          // B*T
#define NBH  32            // B*H
#define Cin  1536

typedef __nv_bfloat16 bf16;

// ---------------- device scratch ----------------
__device__ float  g_pe[Ln * 192];
__device__ float  g_rK[Ln * HDK];
__device__ double g_gmax[32];

__device__ float  g_Qf[BT * HDK];
__device__ float  g_Kf[BT * HDK];
__device__ float  g_Vf[BT * HDV];

__device__ bf16   g_xh[BT * Cin], g_xl[BT * Cin];
__device__ bf16   g_wqth[HDK * Cin], g_wqtl[HDK * Cin];
__device__ bf16   g_wkth[HDK * Cin], g_wktl[HDK * Cin];
__device__ bf16   g_wvth[HDV * Cin], g_wvtl[HDV * Cin];
__device__ bf16   g_woth[HDV * HDV], g_wotl[HDV * HDV];

__device__ bf16   g_qwh[NBH * Tn * DKn], g_qwl[NBH * Tn * DKn];
__device__ bf16   g_qrh[NBH * Tn * DKn], g_qrl[NBH * Tn * DKn];
__device__ bf16   g_kh [NBH * Tn * DKn], g_kl [NBH * Tn * DKn];
__device__ bf16   g_rkth[Hn * Lp * DKn], g_rktl[Hn * Lp * DKn];   // per-head only
__device__ bf16   g_vth[NBH * DVn * Tn], g_vtl[NBH * DVn * Tn];

__device__ float  g_logits[75497472];             // 32*1536*1536
__device__ bf16   g_ah[75497472], g_al[75497472]; // attn hi/lo
__device__ float  g_ao[BT * HDV];
__device__ bf16   g_aoh[BT * HDV], g_aol[BT * HDV];

// ============================================================
// helpers
// ============================================================
__device__ __forceinline__ uint32_t smem_u32(const void* p) {
    uint32_t a;
    asm("{ .reg .u64 t; cvta.to.shared.u64 t, %1; cvt.u32.u64 %0, t; }" : "=r"(a) : "l"(p));
    return a;
}
__device__ __forceinline__ void cp16(uint32_t s, const void* g) {
    asm volatile("cp.async.ca.shared.global [%0], [%1], 16;" :: "r"(s), "l"(g));
}
#define CP_COMMIT() asm volatile("cp.async.commit_group;" ::: "memory")
#define CP_WAIT0()  asm volatile("cp.async.wait_group 0;" ::: "memory")

#define LDSM4(r, addr) \
    asm volatile("ldmatrix.sync.aligned.m8n8.x4.shared.b16 {%0,%1,%2,%3}, [%4];" \
        : "=r"((r)[0]), "=r"((r)[1]), "=r"((r)[2]), "=r"((r)[3]) : "r"(addr))

#define MMA(acc, a, b) \
    asm volatile("mma.sync.aligned.m16n8k16.row.col.f32.bf16.bf16.f32 " \
        "{%0,%1,%2,%3},{%4,%5,%6,%7},{%8,%9},{%0,%1,%2,%3};" \
        : "+f"((acc)[0]), "+f"((acc)[1]), "+f"((acc)[2]), "+f"((acc)[3]) \
        : "r"((a)[0]), "r"((a)[1]), "r"((a)[2]), "r"((a)[3]), "r"((b)[0]), "r"((b)[1]))

// ---------------- positional basis (validated) ----------------
__global__ void gamma_max_kernel(double* gmax) {
    __shared__ double red[256];
    int j = blockIdx.x, t = threadIdx.x;
    double conc  = 4.0 * (j + 1) * (j + 1);
    double rate  = (double)(j + 1) / 12.0;
    double lnorm = lgamma(conc) - conc * log(rate);
    double best = 0.0;
    for (int i = t; i < Ln; i += 256) {
        double pos = fabs((double)(i - (Tn - 1)));
        double lu = (conc - 1.0) * log(pos) - rate * pos;
        double pr = exp(lu - lnorm);
        if (pr > best) best = pr;
    }
    red[t] = best;
    __syncthreads();
    for (int s = 128; s; s >>= 1) {
        if (t < s) red[t] = fmax(red[t], red[t + s]);
        __syncthreads();
    }
    if (t == 0) gmax[j] = red[0] + 1e-8;
}

__global__ void pe_kernel(const double* __restrict__ gmax, float* __restrict__ pe) {
    int idx = blockIdx.x * blockDim.x + threadIdx.x;
    if (idx >= Ln * 32) return;
    int i = idx / 32, j = idx % 32;
    int dist = i - (Tn - 1);
    double pos = fabs((double)dist);
    double mr = log2((double)Tn);
    double hl = exp2(3.0 + (double)j * (mr - 3.0) / 31.0);
    double fe = exp2(-pos / hl);
    double width = exp2((double)(j + 1)) - 1.0;
    double fc = (width > pos) ? 1.0 : 0.0;
    double conc  = 4.0 * (j + 1) * (j + 1);
    double rate  = (double)(j + 1) / 12.0;
    double lnorm = lgamma(conc) - conc * log(rate);
    double pr = exp((conc - 1.0) * log(pos) - rate * pos - lnorm) + 1e-8;
    double fg = pr / gmax[j];
    float sgn = (dist > 0) ? 1.f : ((dist < 0) ? -1.f : 0.f);
    float* row = pe + (size_t)i * 192;
    row[j]       = (float)fe;
    row[32 + j]  = (float)fc;
    row[64 + j]  = (float)fg;
    row[96 + j]  = sgn * (float)fe;
    row[128 + j] = sgn * (float)fc;
    row[160 + j] = sgn * (float)fg;
}

// ---------------- small fp32 sgemm (rK only) ----------------
__global__ void sgemm_kernel(const float* __restrict__ A, int lda,
                             const float* __restrict__ B, int ldb,
                             float* __restrict__ C, int ldc,
                             int M, int N, int K) {
    __shared__ float As[16][68];
    __shared__ float Bs[16][68];
    int t  = threadIdx.x;
    int tx = t & 15, ty = t >> 4;
    int m0 = blockIdx.y * 64, n0 = blockIdx.x * 64;
    int ar = t >> 2, ac = (t & 3) * 4;
    int br = t >> 4, bc = (t & 15) * 4;
    float s[4][4] = {};
    for (int k0 = 0; k0 < K; k0 += 16) {
        float4 av = make_float4(0.f, 0.f, 0.f, 0.f);
        if (m0 + ar < M)
            av = *(const float4*)(A + (size_t)(m0 + ar) * lda + k0 + ac);
        float4 bv = *(const float4*)(B + (size_t)(k0 + br) * ldb + n0 + bc);
        __syncthreads();
        As[ac + 0][ar] = av.x; As[ac + 1][ar] = av.y;
        As[ac + 2][ar] = av.z; As[ac + 3][ar] = av.w;
        *(float4*)&Bs[br][bc] = bv;
        __syncthreads();
#pragma unroll
        for (int kk = 0; kk < 16; kk++) {
            float4 a = *(const float4*)&As[kk][ty * 4];
            float4 b = *(const float4*)&Bs[kk][tx * 4];
            s[0][0] += a.x * b.x; s[0][1] += a.x * b.y; s[0][2] += a.x * b.z; s[0][3] += a.x * b.w;
            s[1][0] += a.y * b.x; s[1][1] += a.y * b.y; s[1][2] += a.y * b.z; s[1][3] += a.y * b.w;
            s[2][0] += a.z * b.x; s[2][1] += a.z * b.y; s[2][2] += a.z * b.z; s[2][3] += a.z * b.w;
            s[3][0] += a.w * b.x; s[3][1] += a.w * b.y; s[3][2] += a.w * b.z; s[3][3] += a.w * b.w;
        }
    }
#pragma unroll
    for (int i = 0; i < 4; i++) {
        int m = m0 + ty * 4 + i;
        if (m < M) {
            float* cp = C + (size_t)m * ldc + n0 + tx * 4;
#pragma unroll
            for (int j = 0; j < 4; j++) cp[j] = s[i][j];
        }
    }
}

// ---------------- hi/lo split helpers ----------------
__device__ __forceinline__ void split_store(float v, bf16* hi, bf16* lo, long o) {
    bf16 h = __float2bfloat16(v);
    hi[o] = h;
    lo[o] = __float2bfloat16(v - __bfloat162float(h));
}

__global__ void split_kernel(const float* __restrict__ src, bf16* __restrict__ hi,
                             bf16* __restrict__ lo, int n) {
    int i = blockIdx.x * 256 + threadIdx.x;
    if (i < n) split_store(src[i], hi, lo, i);
}

// transpose+split: src [K][N] fp32 -> dst hi/lo [N][K] bf16
__global__ void tsplit_kernel(const float* __restrict__ src, int K, int N,
                              bf16* __restrict__ hi, bf16* __restrict__ lo) {
    __shared__ float tile[32][33];
    int n0 = blockIdx.x * 32, k0 = blockIdx.y * 32;
    int tx = threadIdx.x & 31, ty = threadIdx.x >> 5;
#pragma unroll
    for (int i = 0; i < 32; i += 8)
        tile[ty + i][tx] = src[(long)(k0 + ty + i) * N + n0 + tx];
    __syncthreads();
#pragma unroll
    for (int i = 0; i < 32; i += 8) {
        float v = tile[tx][ty + i];   // = src[k0+tx][n0+ty+i]
        long o = (long)(n0 + ty + i) * K + k0 + tx;
        split_store(v, hi, lo, o);
    }
}

// Qf/Kf [b*t][h*64] -> per-(b,h) [z][t][64] hi/lo, r_w/r_r folded into Q
__global__ void qkhead_kernel(const float* __restrict__ Qf, const float* __restrict__ Kf,
                              const float* __restrict__ rwb, const float* __restrict__ rrb,
                              bf16* qwh, bf16* qwl, bf16* qrh, bf16* qrl, bf16* kh, bf16* kl) {
    long i = (long)blockIdx.x * 256 + threadIdx.x;
    if (i >= (long)NBH * Tn * DKn) return;
    int d = (int)(i & 63);
    int q = (int)((i >> 6) % Tn);
    int z = (int)(i / ((long)Tn * DKn));
    int h = z & 7, b = z >> 3;
    long src = ((long)(b * Tn + q)) * HDK + h * DKn + d;
    float qv = Qf[src], kv = Kf[src];
    split_store(qv + rwb[h * DKn + d], qwh, qwl, i);
    split_store(qv + rrb[h * DKn + d], qrh, qrl, i);
    split_store(kv, kh, kl, i);
}

// rK [3071][512] -> rKt [h][3072][64] hi/lo (zero pad row 3071)
__global__ void rkt_kernel(const float* __restrict__ rK, bf16* rkth, bf16* rktl) {
    long i = (long)blockIdx.x * 256 + threadIdx.x;
    if (i >= (long)Hn * Lp * DKn) return;
    int d = (int)(i & 63);
    int l = (int)((i >> 6) % Lp);
    int h = (int)(i / ((long)Lp * DKn));
    float v = (l < Ln) ? rK[(long)l * HDK + h * DKn + d] : 0.f;
    split_store(v, rkth, rktl, i);
}

// Vf [b*t][h*192+d] -> Vt [z][d][t] hi/lo
__global__ void vt_kernel(const float* __restrict__ Vf, bf16* vth, bf16* vtl) {
    __shared__ float tile[32][33];
    int z = blockIdx.z, h = z & 7, b = z >> 3;
    int t0 = blockIdx.x * 32, d0 = blockIdx.y * 32;
    int tx = threadIdx.x & 31, ty = threadIdx.x >> 5;
#pragma unroll
    for (int i = 0; i < 32; i += 8)
        tile[ty + i][tx] = Vf[((long)(b * Tn + t0 + ty + i)) * HDV + h * DVn + d0 + tx];
    __syncthreads();
#pragma unroll
    for (int i = 0; i < 32; i += 8) {
        float v = tile[tx][ty + i];    // = Vf[t0+tx][d0+ty+i]
        long o = ((long)z * DVn + d0 + ty + i) * Tn + t0 + tx;
        split_store(v, vth, vtl, o);
    }
}

// ============================================================
// mma.sync bf16 GEMM, templated:
//   BN   : 128 (2x4 warps, 64x32 warp tiles) or 64 (4x2 warps, 32x32)
//   MODE : 0 = C = scale*acc + bias
//          1 = C += acc
//          2 = shifted store: C[row][l+row-(Tn-1)] = acc   (rel -> logits)
// A: [m][K] K-major, B: [n][K] K-major bf16 hi/lo, 3-pass compensation.
// ============================================================
template <int BN, int MODE>
__global__ void __launch_bounds__(256) gemm_mma(
    const bf16* __restrict__ Ah, const bf16* __restrict__ Al, int lda, long sA8, long sA1,
    const bf16* __restrict__ Bh, const bf16* __restrict__ Bl, int ldb, long sB8, long sB1,
    float* __restrict__ C, int ldc, long sC8, long sC1,
    int Kdim, int Ncols, float scale, const float* __restrict__ bias)
{
    constexpr int WN = (BN == 128) ? 4 : 2;    // warps along n
    constexpr int AM = (BN == 128) ? 64 : 32;  // warp m-tile
    constexpr int MI = AM / 16;
    constexpr int TILEA = 128 * 80;
    constexpr int TILEB = BN * 80;
    constexpr int STAGE = 2 * TILEA + 2 * TILEB;

    extern __shared__ char smem[];
    uint32_t sb = smem_u32(smem);
    int tid = threadIdx.x, lane = tid & 31, wid = tid >> 5;
    int wm = wid / WN, wn = wid % WN;
    int z = blockIdx.z;
    int m0 = blockIdx.y * 128, n0 = blockIdx.x * BN;

    long zo_a = (long)(z >> 3) * sA8 + (long)(z & 7) * sA1;
    long zo_b = (long)(z >> 3) * sB8 + (long)(z & 7) * sB1;
    long zo_c = (long)(z >> 3) * sC8 + (long)(z & 7) * sC1;
    const bf16* pAh = Ah + zo_a + (long)m0 * lda;
    const bf16* pAl = Al + zo_a + (long)m0 * lda;
    const bf16* pBh = Bh + zo_b + (long)n0 * ldb;
    const bf16* pBl = Bl + zo_b + (long)n0 * ldb;

    float acc[MI][4][4] = {};
    const int NC = Kdim >> 5;

    auto prefetch = [&](int kc) {
        int k0 = kc * 32;
        uint32_t s0 = sb + (kc & 1) * STAGE;
        for (int i = tid; i < 512; i += 256) {
            int r = i >> 2, c = i & 3;
            uint32_t so = (uint32_t)(r * 80 + c * 16);
            long goA = (long)r * lda + k0 + c * 8;
            cp16(s0 + so,        pAh + goA);
            cp16(s0 + TILEA + so, pAl + goA);
            if (r < BN) {
                long goB = (long)r * ldb + k0 + c * 8;
                cp16(s0 + 2 * TILEA + so,         pBh + goB);
                cp16(s0 + 2 * TILEA + TILEB + so, pBl + goB);
            }
        }
        CP_COMMIT();
    };

    prefetch(0);
    for (int kc = 0; kc < NC; kc++) {
        CP_WAIT0();
        __syncthreads();
        if (kc + 1 < NC) prefetch(kc + 1);
        uint32_t s0 = sb + (kc & 1) * STAGE;

#pragma unroll
        for (int kk = 0; kk < 2; kk++) {
            int k16 = kk * 16;
            uint32_t ah[MI][4], al[MI][4], bh[4][2], bl[4][2];
            uint32_t arow = (uint32_t)(wm * AM + (lane & 15));
            uint32_t acol = (uint32_t)(k16 + (lane >> 4) * 8);
#pragma unroll
            for (int mi = 0; mi < MI; mi++) {
                uint32_t ao = s0 + (arow + mi * 16) * 80 + acol * 2;
                LDSM4(ah[mi], ao);
                LDSM4(al[mi], ao + TILEA);
            }
            uint32_t brow = (uint32_t)(wn * 32 + (lane & 7) + ((lane >> 4) & 1) * 8);
            uint32_t bcol = (uint32_t)(k16 + ((lane >> 3) & 1) * 8);
#pragma unroll
            for (int g = 0; g < 2; g++) {
                uint32_t t4[4];
                uint32_t bo = s0 + 2 * TILEA + (brow + g * 16) * 80 + bcol * 2;
                LDSM4(t4, bo);
                bh[g * 2][0] = t4[0]; bh[g * 2][1] = t4[1];
                bh[g * 2 + 1][0] = t4[2]; bh[g * 2 + 1][1] = t4[3];
                LDSM4(t4, bo + TILEB);
                bl[g * 2][0] = t4[0]; bl[g * 2][1] = t4[1];
                bl[g * 2 + 1][0] = t4[2]; bl[g * 2 + 1][1] = t4[3];
            }
#pragma unroll
            for (int mi = 0; mi < MI; mi++)
#pragma unroll
                for (int ni = 0; ni < 4; ni++) {
                    MMA(acc[mi][ni], ah[mi], bh[ni]);
                    MMA(acc[mi][ni], ah[mi], bl[ni]);
                    MMA(acc[mi][ni], al[mi], bh[ni]);
                }
        }
        __syncthreads();
    }

    // ---- epilogue ----
    int gID = lane >> 2, tig = lane & 3;
#pragma unroll
    for (int mi = 0; mi < MI; mi++) {
#pragma unroll
        for (int ni = 0; ni < 4; ni++) {
            int row0 = m0 + wm * AM + mi * 16 + gID;
            int col  = n0 + wn * 32 + ni * 8 + tig * 2;
            if (MODE == 0) {
                if (col < Ncols) {
                    float b0 = bias ? bias[col] : 0.f;
                    float b1 = bias ? bias[col + 1] : 0.f;
                    float* p0 = C + zo_c + (long)row0 * ldc + col;
                    float* p1 = C + zo_c + (long)(row0 + 8) * ldc + col;
                    *(float2*)p0 = make_float2(acc[mi][ni][0] * scale + b0, acc[mi][ni][1] * scale + b1);
                    *(float2*)p1 = make_float2(acc[mi][ni][2] * scale + b0, acc[mi][ni][3] * scale + b1);
                }
            } else if (MODE == 1) {
                float* p0 = C + zo_c + (long)row0 * ldc + col;
                float* p1 = C + zo_c + (long)(row0 + 8) * ldc + col;
                float2 o0 = *(float2*)p0, o1 = *(float2*)p1;
                o0.x += acc[mi][ni][0]; o0.y += acc[mi][ni][1];
                o1.x += acc[mi][ni][2]; o1.y += acc[mi][ni][3];
                *(float2*)p0 = o0;
                *(float2*)p1 = o1;
            } else {
                // shifted store: k = col + row - (Tn-1), row-local within z
                int k0a = col + row0 - (Tn - 1);          // row0
                int k0b = k0a + 8;                        // row0+8
                float* r0p = C + zo_c + (long)row0 * ldc;
                float* r1p = C + zo_c + (long)(row0 + 8) * ldc;
                if (k0a >= 0     && k0a < Tn)     r0p[k0a]     = acc[mi][ni][0];
                if (k0a + 1 >= 0 && k0a + 1 < Tn) r0p[k0a + 1] = acc[mi][ni][1];
                if (k0b >= 0     && k0b < Tn)     r1p[k0b]     = acc[mi][ni][2];
                if (k0b + 1 >= 0 && k0b + 1 < Tn) r1p[k0b + 1] = acc[mi][ni][3];
            }
        }
    }
}

// ---------------- softmax over logits rows -> attn hi/lo ----------------
__global__ void softmax_kernel(const float* __restrict__ logits,
                               bf16* __restrict__ ah, bf16* __restrict__ al) {
    __shared__ float red[8];
    size_t row = blockIdx.x;              // z*T + q
    const float* p = logits + row * Tn;
    int t = threadIdx.x;
    float v[6];
    float mx = -1e30f;
#pragma unroll
    for (int k = 0; k < 6; k++) {
        v[k] = p[t + k * 256];
        mx = fmaxf(mx, v[k]);
    }
#pragma unroll
    for (int o = 16; o; o >>= 1) mx = fmaxf(mx, __shfl_xor_sync(0xffffffffu, mx, o));
    if ((t & 31) == 0) red[t >> 5] = mx;
    __syncthreads();
    mx = red[0];
#pragma unroll
    for (int i = 1; i < 8; i++) mx = fmaxf(mx, red[i]);
    __syncthreads();
    float sum = 0.f;
#pragma unroll
    for (int k = 0; k < 6; k++) {
        v[k] = expf(v[k] - mx);
        sum += v[k];
    }
#pragma unroll
    for (int o = 16; o; o >>= 1) sum += __shfl_xor_sync(0xffffffffu, sum, o);
    if ((t & 31) == 0) red[t >> 5] = sum;
    __syncthreads();
    float tot = 0.f;
#pragma unroll
    for (int i = 0; i < 8; i++) tot += red[i];
    float inv = 1.0f / tot;
#pragma unroll
    for (int k = 0; k < 6; k++) {
        int i = t + k * 256;
        float a = v[k] * inv;
        bf16 h = __float2bfloat16(a);
        ah[row * Tn + i] = h;
        al[row * Tn + i] = __float2bfloat16(a - __bfloat162float(h));
    }
}

// ---------------- launch ----------------
extern "C" void kernel_launch(void* const* d_in, const int* in_sizes, int n_in,
                              void* d_out, int out_size) {
    const float* x       = (const float*)d_in[0];
    const float* W_q     = (const float*)d_in[1];
    const float* W_k     = (const float*)d_in[2];
    const float* W_v     = (const float*)d_in[3];
    const float* W_rel_k = (const float*)d_in[4];
    const float* W_out   = (const float*)d_in[5];
    const float* b_out   = (const float*)d_in[6];
    const float* rwb     = (const float*)d_in[7];
    const float* rrb     = (const float*)d_in[8];
    float* out = (float*)d_out;

    float *pe, *rK, *Qf, *Kf, *Vf, *logits, *ao;
    double* gmax;
    bf16 *xh, *xl, *wqth, *wqtl, *wkth, *wktl, *wvth, *wvtl, *woth, *wotl;
    bf16 *qwh, *qwl, *qrh, *qrl, *kh, *kl, *rkth, *rktl, *vth, *vtl, *ah, *al, *aoh, *aol;
    cudaGetSymbolAddress((void**)&pe, g_pe);
    cudaGetSymbolAddress((void**)&rK, g_rK);
    cudaGetSymbolAddress((void**)&gmax, g_gmax);
    cudaGetSymbolAddress((void**)&Qf, g_Qf);
    cudaGetSymbolAddress((void**)&Kf, g_Kf);
    cudaGetSymbolAddress((void**)&Vf, g_Vf);
    cudaGetSymbolAddress((void**)&xh, g_xh);   cudaGetSymbolAddress((void**)&xl, g_xl);
    cudaGetSymbolAddress((void**)&wqth, g_wqth); cudaGetSymbolAddress((void**)&wqtl, g_wqtl);
    cudaGetSymbolAddress((void**)&wkth, g_wkth); cudaGetSymbolAddress((void**)&wktl, g_wktl);
    cudaGetSymbolAddress((void**)&wvth, g_wvth); cudaGetSymbolAddress((void**)&wvtl, g_wvtl);
    cudaGetSymbolAddress((void**)&woth, g_woth); cudaGetSymbolAddress((void**)&wotl, g_wotl);
    cudaGetSymbolAddress((void**)&qwh, g_qwh); cudaGetSymbolAddress((void**)&qwl, g_qwl);
    cudaGetSymbolAddress((void**)&qrh, g_qrh); cudaGetSymbolAddress((void**)&qrl, g_qrl);
    cudaGetSymbolAddress((void**)&kh, g_kh);   cudaGetSymbolAddress((void**)&kl, g_kl);
    cudaGetSymbolAddress((void**)&rkth, g_rkth); cudaGetSymbolAddress((void**)&rktl, g_rktl);
    cudaGetSymbolAddress((void**)&vth, g_vth); cudaGetSymbolAddress((void**)&vtl, g_vtl);
    cudaGetSymbolAddress((void**)&logits, g_logits);
    cudaGetSymbolAddress((void**)&ah, g_ah);   cudaGetSymbolAddress((void**)&al, g_al);
    cudaGetSymbolAddress((void**)&ao, g_ao);
    cudaGetSymbolAddress((void**)&aoh, g_aoh); cudaGetSymbolAddress((void**)&aol, g_aol);

    const int SM128 = 2 * (2 * 128 * 80 + 2 * 128 * 80);  // 81920
    const int SM64  = 2 * (2 * 128 * 80 + 2 * 64 * 80);   // 61440
    cudaFuncSetAttribute(gemm_mma<128, 0>, cudaFuncAttributeMaxDynamicSharedMemorySize, SM128);
    cudaFuncSetAttribute(gemm_mma<128, 1>, cudaFuncAttributeMaxDynamicSharedMemorySize, SM128);
    cudaFuncSetAttribute(gemm_mma<128, 2>, cudaFuncAttributeMaxDynamicSharedMemorySize, SM128);
    cudaFuncSetAttribute(gemm_mma<64, 0>,  cudaFuncAttributeMaxDynamicSharedMemorySize, SM64);

    // 1) positional basis + rK (fp32)
    gamma_max_kernel<<<32, 256>>>(gmax);
    pe_kernel<<<(Ln * 32 + 255) / 256, 256>>>(gmax, pe);
    sgemm_kernel<<<dim3(HDK / 64, (Ln + 63) / 64), 256>>>(pe, 192, W_rel_k, HDK, rK, HDK, Ln, HDK, 192);

    // 2) operand prep
    split_kernel<<<(BT * Cin + 255) / 256, 256>>>(x, xh, xl, BT * Cin);
    tsplit_kernel<<<dim3(HDK / 32, Cin / 32), 256>>>(W_q, Cin, HDK, wqth, wqtl);
    tsplit_kernel<<<dim3(HDK / 32, Cin / 32), 256>>>(W_k, Cin, HDK, wkth, wktl);
    tsplit_kernel<<<dim3(HDV / 32, Cin / 32), 256>>>(W_v, Cin, HDV, wvth, wvtl);
    tsplit_kernel<<<dim3(HDV / 32, HDV / 32), 256>>>(W_out, HDV, HDV, woth, wotl);

    // 3) Q/K/V projections, Q pre-scaled by DK^-1/2
    gemm_mma<128, 0><<<dim3(HDK / 128, BT / 128, 1), 256, SM128>>>(
        xh, xl, Cin, 0, 0, wqth, wqtl, Cin, 0, 0, Qf, HDK, 0, 0, Cin, HDK, 0.125f, nullptr);
    gemm_mma<128, 0><<<dim3(HDK / 128, BT / 128, 1), 256, SM128>>>(
        xh, xl, Cin, 0, 0, wkth, wktl, Cin, 0, 0, Kf, HDK, 0, 0, Cin, HDK, 1.0f, nullptr);
    gemm_mma<128, 0><<<dim3(HDV / 128, BT / 128, 1), 256, SM128>>>(
        xh, xl, Cin, 0, 0, wvth, wvtl, Cin, 0, 0, Vf, HDV, 0, 0, Cin, HDV, 1.0f, nullptr);

    // 4) head reshapes + bias folds + splits
    qkhead_kernel<<<(int)(((long)NBH * Tn * DKn + 255) / 256), 256>>>(
        Qf, Kf, rwb, rrb, qwh, qwl, qrh, qrl, kh, kl);
    rkt_kernel<<<(int)(((long)Hn * Lp * DKn + 255) / 256), 256>>>(rK, rkth, rktl);
    vt_kernel<<<dim3(Tn / 32, DVn / 32, NBH), 256>>>(Vf, vth, vtl);

    // 5) rel = (Q+r_r)·rK^T, shifted-written directly into logits  (MODE 2)
    long sQ = (long)Tn * DKn;
    long sR = (long)Lp * DKn;
    gemm_mma<128, 2><<<dim3(Lp / 128, Tn / 128, NBH), 256, SM128>>>(
        qrh, qrl, DKn, 8 * sQ, sQ, rkth, rktl, DKn, 0, sR,
        logits, Tn, 8L * Tn * Tn, (long)Tn * Tn, DKn, Tn, 1.0f, nullptr);

    // 6) logits += (Q+r_w)·K^T  (MODE 1)
    gemm_mma<128, 1><<<dim3(Tn / 128, Tn / 128, NBH), 256, SM128>>>(
        qwh, qwl, DKn, 8 * sQ, sQ, kh, kl, DKn, 8 * sQ, sQ,
        logits, Tn, 8L * Tn * Tn, (long)Tn * Tn, DKn, Tn, 1.0f, nullptr);

    // 7) softmax -> attn hi/lo
    softmax_kernel<<<NBH * Tn, 256>>>(logits, ah, al);

    // 8) out_att = attn·V  per (b,h): M=1536, N=192 (BN=64, exact), K=1536
    gemm_mma<64, 0><<<dim3(DVn / 64, Tn / 128, NBH), 256, SM64>>>(
        ah, al, Tn, 8L * Tn * Tn, (long)Tn * Tn,
        vth, vtl, Tn, 8L * DVn * Tn, (long)DVn * Tn,
        ao, HDV, (long)Tn * HDV, DVn, Tn, DVn, 1.0f, nullptr);

    // 9) final projection
    split_kernel<<<(BT * HDV + 255) / 256, 256>>>(ao, aoh, aol, BT * HDV);
    gemm_mma<128, 0><<<dim3(HDV / 128, BT / 128, 1), 256, SM128>>>(
        aoh, aol, HDV, 0, 0, woth, wotl, HDV, 0, 0, out, HDV, 0, 0, HDV, HDV, 1.0f, b_out);
}

// round 6
// speedup vs baseline: 5.4110x; 1.2381x over previous
#include <cuda_runtime.h>
#include <cuda_fp16.h>
#include <math.h>
#include <stdint.h>

// Problem constants
#define Tn   1536
#define Bn   4
#define Hn   8
#define DKn  64
#define DVn  192
#define Ln   3071          // 2T-1
#define Lp   3072          // padded
#define HDK  512           // H*DK
#define HDV  1536          // H*DV
#define BT   6144          // B*T
#define NBH  32            // B*H
#define Cin  1536

// ---------------- device scratch ----------------
__device__ float  g_pe[Ln * 192];
__device__ float  g_rK[Ln * HDK];
__device__ double g_gmax[32];

__device__ float  g_Qf[BT * HDK];
__device__ float  g_Kf[BT * HDK];
__device__ float  g_Vf[BT * HDV];

__device__ half   g_xh[BT * Cin], g_xl[BT * Cin];
__device__ half   g_wqth[HDK * Cin], g_wqtl[HDK * Cin];
__device__ half   g_wkth[HDK * Cin], g_wktl[HDK * Cin];
__device__ half   g_wvth[HDV * Cin], g_wvtl[HDV * Cin];
__device__ half   g_woth[HDV * HDV], g_wotl[HDV * HDV];

__device__ half   g_qwh[NBH * Tn * DKn], g_qwl[NBH * Tn * DKn];
__device__ half   g_qrh[NBH * Tn * DKn], g_qrl[NBH * Tn * DKn];
__device__ half   g_kh [NBH * Tn * DKn], g_kl [NBH * Tn * DKn];
__device__ half   g_rkth[Hn * Lp * DKn], g_rktl[Hn * Lp * DKn];
__device__ half   g_vth[NBH * DVn * Tn], g_vtl[NBH * DVn * Tn];

__device__ float  g_logits[75497472];     // 32*1536*1536
__device__ half   g_attn[75497472];       // attn (single fp16)
__device__ half   g_aoh[BT * HDV];        // attn@V result fp16

// ============================================================
// helpers
// ============================================================
__device__ __forceinline__ uint32_t smem_u32(const void* p) {
    uint32_t a;
    asm("{ .reg .u64 t; cvta.to.shared.u64 t, %1; cvt.u32.u64 %0, t; }" : "=r"(a) : "l"(p));
    return a;
}
__device__ __forceinline__ void cp16(uint32_t s, const void* g) {
    asm volatile("cp.async.ca.shared.global [%0], [%1], 16;" :: "r"(s), "l"(g));
}
#define CP_COMMIT() asm volatile("cp.async.commit_group;" ::: "memory")
#define CP_WAIT0()  asm volatile("cp.async.wait_group 0;" ::: "memory")

#define LDSM4(r, addr) \
    asm volatile("ldmatrix.sync.aligned.m8n8.x4.shared.b16 {%0,%1,%2,%3}, [%4];" \
        : "=r"((r)[0]), "=r"((r)[1]), "=r"((r)[2]), "=r"((r)[3]) : "r"(addr))

#define MMA(acc, a, b) \
    asm volatile("mma.sync.aligned.m16n8k16.row.col.f32.f16.f16.f32 " \
        "{%0,%1,%2,%3},{%4,%5,%6,%7},{%8,%9},{%0,%1,%2,%3};" \
        : "+f"((acc)[0]), "+f"((acc)[1]), "+f"((acc)[2]), "+f"((acc)[3]) \
        : "r"((a)[0]), "r"((a)[1]), "r"((a)[2]), "r"((a)[3]), "r"((b)[0]), "r"((b)[1]))

// ---------------- positional basis (validated) ----------------
__global__ void gamma_max_kernel(double* gmax) {
    __shared__ double red[256];
    int j = blockIdx.x, t = threadIdx.x;
    double conc  = 4.0 * (j + 1) * (j + 1);
    double rate  = (double)(j + 1) / 12.0;
    double lnorm = lgamma(conc) - conc * log(rate);
    double best = 0.0;
    for (int i = t; i < Ln; i += 256) {
        double pos = fabs((double)(i - (Tn - 1)));
        double lu = (conc - 1.0) * log(pos) - rate * pos;
        double pr = exp(lu - lnorm);
        if (pr > best) best = pr;
    }
    red[t] = best;
    __syncthreads();
    for (int s = 128; s; s >>= 1) {
        if (t < s) red[t] = fmax(red[t], red[t + s]);
        __syncthreads();
    }
    if (t == 0) gmax[j] = red[0] + 1e-8;
}

__global__ void pe_kernel(const double* __restrict__ gmax, float* __restrict__ pe) {
    int idx = blockIdx.x * blockDim.x + threadIdx.x;
    if (idx >= Ln * 32) return;
    int i = idx / 32, j = idx % 32;
    int dist = i - (Tn - 1);
    double pos = fabs((double)dist);
    double mr = log2((double)Tn);
    double hl = exp2(3.0 + (double)j * (mr - 3.0) / 31.0);
    double fe = exp2(-pos / hl);
    double width = exp2((double)(j + 1)) - 1.0;
    double fc = (width > pos) ? 1.0 : 0.0;
    double conc  = 4.0 * (j + 1) * (j + 1);
    double rate  = (double)(j + 1) / 12.0;
    double lnorm = lgamma(conc) - conc * log(rate);
    double pr = exp((conc - 1.0) * log(pos) - rate * pos - lnorm) + 1e-8;
    double fg = pr / gmax[j];
    float sgn = (dist > 0) ? 1.f : ((dist < 0) ? -1.f : 0.f);
    float* row = pe + (size_t)i * 192;
    row[j]       = (float)fe;
    row[32 + j]  = (float)fc;
    row[64 + j]  = (float)fg;
    row[96 + j]  = sgn * (float)fe;
    row[128 + j] = sgn * (float)fc;
    row[160 + j] = sgn * (float)fg;
}

// ---------------- small fp32 sgemm (rK only) ----------------
__global__ void sgemm_kernel(const float* __restrict__ A, int lda,
                             const float* __restrict__ B, int ldb,
                             float* __restrict__ C, int ldc,
                             int M, int N, int K) {
    __shared__ float As[16][68];
    __shared__ float Bs[16][68];
    int t  = threadIdx.x;
    int tx = t & 15, ty = t >> 4;
    int m0 = blockIdx.y * 64, n0 = blockIdx.x * 64;
    int ar = t >> 2, ac = (t & 3) * 4;
    int br = t >> 4, bc = (t & 15) * 4;
    float s[4][4] = {};
    for (int k0 = 0; k0 < K; k0 += 16) {
        float4 av = make_float4(0.f, 0.f, 0.f, 0.f);
        if (m0 + ar < M)
            av = *(const float4*)(A + (size_t)(m0 + ar) * lda + k0 + ac);
        float4 bv = *(const float4*)(B + (size_t)(k0 + br) * ldb + n0 + bc);
        __syncthreads();
        As[ac + 0][ar] = av.x; As[ac + 1][ar] = av.y;
        As[ac + 2][ar] = av.z; As[ac + 3][ar] = av.w;
        *(float4*)&Bs[br][bc] = bv;
        __syncthreads();
#pragma unroll
        for (int kk = 0; kk < 16; kk++) {
            float4 a = *(const float4*)&As[kk][ty * 4];
            float4 b = *(const float4*)&Bs[kk][tx * 4];
            s[0][0] += a.x * b.x; s[0][1] += a.x * b.y; s[0][2] += a.x * b.z; s[0][3] += a.x * b.w;
            s[1][0] += a.y * b.x; s[1][1] += a.y * b.y; s[1][2] += a.y * b.z; s[1][3] += a.y * b.w;
            s[2][0] += a.z * b.x; s[2][1] += a.z * b.y; s[2][2] += a.z * b.z; s[2][3] += a.z * b.w;
            s[3][0] += a.w * b.x; s[3][1] += a.w * b.y; s[3][2] += a.w * b.z; s[3][3] += a.w * b.w;
        }
    }
#pragma unroll
    for (int i = 0; i < 4; i++) {
        int m = m0 + ty * 4 + i;
        if (m < M) {
            float* cp = C + (size_t)m * ldc + n0 + tx * 4;
#pragma unroll
            for (int j = 0; j < 4; j++) cp[j] = s[i][j];
        }
    }
}

// ---------------- hi/lo split helpers (fp16) ----------------
__device__ __forceinline__ void split_h(float v, half* hi, half* lo, long o) {
    half h = __float2half_rn(v);
    hi[o] = h;
    lo[o] = __float2half_rn(v - __half2float(h));
}

__global__ void split_kernel(const float* __restrict__ src, half* __restrict__ hi,
                             half* __restrict__ lo, int n) {
    int i = blockIdx.x * 256 + threadIdx.x;
    if (i < n) split_h(src[i], hi, lo, i);
}

// transpose+split: src [K][N] fp32 -> dst hi/lo [N][K] fp16
__global__ void tsplit_kernel(const float* __restrict__ src, int K, int N,
                              half* __restrict__ hi, half* __restrict__ lo) {
    __shared__ float tile[32][33];
    int n0 = blockIdx.x * 32, k0 = blockIdx.y * 32;
    int tx = threadIdx.x & 31, ty = threadIdx.x >> 5;
#pragma unroll
    for (int i = 0; i < 32; i += 8)
        tile[ty + i][tx] = src[(long)(k0 + ty + i) * N + n0 + tx];
    __syncthreads();
#pragma unroll
    for (int i = 0; i < 32; i += 8) {
        float v = tile[tx][ty + i];
        long o = (long)(n0 + ty + i) * K + k0 + tx;
        split_h(v, hi, lo, o);
    }
}

// Qf/Kf [b*t][h*64] -> per-(b,h) [z][t][64] hi/lo, r_w/r_r folded into Q
__global__ void qkhead_kernel(const float* __restrict__ Qf, const float* __restrict__ Kf,
                              const float* __restrict__ rwb, const float* __restrict__ rrb,
                              half* qwh, half* qwl, half* qrh, half* qrl, half* kh, half* kl) {
    long i = (long)blockIdx.x * 256 + threadIdx.x;
    if (i >= (long)NBH * Tn * DKn) return;
    int d = (int)(i & 63);
    int q = (int)((i >> 6) % Tn);
    int z = (int)(i / ((long)Tn * DKn));
    int h = z & 7, b = z >> 3;
    long src = ((long)(b * Tn + q)) * HDK + h * DKn + d;
    float qv = Qf[src], kv = Kf[src];
    split_h(qv + rwb[h * DKn + d], qwh, qwl, i);
    split_h(qv + rrb[h * DKn + d], qrh, qrl, i);
    split_h(kv, kh, kl, i);
}

// rK [3071][512] -> rKt [h][3072][64] hi/lo (zero pad row 3071)
__global__ void rkt_kernel(const float* __restrict__ rK, half* rkth, half* rktl) {
    long i = (long)blockIdx.x * 256 + threadIdx.x;
    if (i >= (long)Hn * Lp * DKn) return;
    int d = (int)(i & 63);
    int l = (int)((i >> 6) % Lp);
    int h = (int)(i / ((long)Lp * DKn));
    float v = (l < Ln) ? rK[(long)l * HDK + h * DKn + d] : 0.f;
    split_h(v, rkth, rktl, i);
}

// Vf [b*t][h*192+d] -> Vt [z][d][t] hi/lo
__global__ void vt_kernel(const float* __restrict__ Vf, half* vth, half* vtl) {
    __shared__ float tile[32][33];
    int z = blockIdx.z, h = z & 7, b = z >> 3;
    int t0 = blockIdx.x * 32, d0 = blockIdx.y * 32;
    int tx = threadIdx.x & 31, ty = threadIdx.x >> 5;
#pragma unroll
    for (int i = 0; i < 32; i += 8)
        tile[ty + i][tx] = Vf[((long)(b * Tn + t0 + ty + i)) * HDV + h * DVn + d0 + tx];
    __syncthreads();
#pragma unroll
    for (int i = 0; i < 32; i += 8) {
        float v = tile[tx][ty + i];
        long o = ((long)z * DVn + d0 + ty + i) * Tn + t0 + tx;
        split_h(v, vth, vtl, o);
    }
}

// ============================================================
// mma.sync fp16 GEMM, templated:
//   BN    : 128 (2x4 warps, 64x32 warp tiles) or 64 (4x2 warps, 32x32)
//   NPASS : 3 = (ah.bh + ah.bl + al.bh)  |  2 = (ah.bh + ah.bl), A hi only
//   MODE  : 0 = fp32 C = scale*acc + bias
//           1 = fp32 C += acc
//           2 = banded shifted store into logits (rel)
//           3 = fp16 C = acc
// A: [m][K] K-major, B: [n][K] K-major, fp16 hi/lo.
// ============================================================
template <int BN, int NPASS, int MODE>
__global__ void __launch_bounds__(256) gemm_mma(
    const half* __restrict__ Ah, const half* __restrict__ Al, int lda, long sA8, long sA1,
    const half* __restrict__ Bh, const half* __restrict__ Bl, int ldb, long sB8, long sB1,
    void* __restrict__ Cv, int ldc, long sC8, long sC1,
    int Kdim, int Ncols, float scale, const float* __restrict__ bias)
{
    constexpr int WN = (BN == 128) ? 4 : 2;
    constexpr int AM = (BN == 128) ? 64 : 32;
    constexpr int MI = AM / 16;
    constexpr int NA = (NPASS == 3) ? 2 : 1;
    constexpr int TILEA = 128 * 80;
    constexpr int TILEB = BN * 80;
    constexpr int STAGE = NA * TILEA + 2 * TILEB;

    extern __shared__ char smem[];
    uint32_t sb = smem_u32(smem);
    int tid = threadIdx.x, lane = tid & 31, wid = tid >> 5;
    int wm = wid / WN, wn = wid % WN;
    int z = blockIdx.z;
    int m0 = blockIdx.y * 128, n0 = blockIdx.x * BN;

    long zo_a = (long)(z >> 3) * sA8 + (long)(z & 7) * sA1;
    long zo_b = (long)(z >> 3) * sB8 + (long)(z & 7) * sB1;
    long zo_c = (long)(z >> 3) * sC8 + (long)(z & 7) * sC1;
    const half* pAh = Ah + zo_a + (long)m0 * lda;
    const half* pAl = Al + zo_a + (long)m0 * lda;
    long boff = (MODE == 2) ? (long)(Tn - 128 - m0 + n0) : (long)n0;
    const half* pBh = Bh + zo_b + boff * ldb;
    const half* pBl = Bl + zo_b + boff * ldb;

    float acc[MI][4][4] = {};
    const int NC = Kdim >> 5;

    auto prefetch = [&](int kc) {
        int k0 = kc * 32;
        uint32_t s0 = sb + (kc & 1) * STAGE;
        for (int i = tid; i < 512; i += 256) {
            int r = i >> 2, c = i & 3;
            uint32_t so = (uint32_t)(r * 80 + c * 16);
            long go = (long)r * lda + k0 + c * 8;
            cp16(s0 + so, pAh + go);
            if (NPASS == 3) cp16(s0 + TILEA + so, pAl + go);
        }
        for (int i = tid; i < BN * 4; i += 256) {
            int r = i >> 2, c = i & 3;
            uint32_t so = (uint32_t)(r * 80 + c * 16);
            long go = (long)r * ldb + k0 + c * 8;
            cp16(s0 + NA * TILEA + so,         pBh + go);
            cp16(s0 + NA * TILEA + TILEB + so, pBl + go);
        }
        CP_COMMIT();
    };

    prefetch(0);
    for (int kc = 0; kc < NC; kc++) {
        CP_WAIT0();
        __syncthreads();
        if (kc + 1 < NC) prefetch(kc + 1);
        uint32_t s0 = sb + (kc & 1) * STAGE;

#pragma unroll
        for (int kk = 0; kk < 2; kk++) {
            int k16 = kk * 16;
            uint32_t ah[MI][4], al[MI][4], bh[4][2], bl[4][2];
            uint32_t arow = (uint32_t)(wm * AM + (lane & 15));
            uint32_t acol = (uint32_t)(k16 + (lane >> 4) * 8);
#pragma unroll
            for (int mi = 0; mi < MI; mi++) {
                uint32_t ao = s0 + (arow + mi * 16) * 80 + acol * 2;
                LDSM4(ah[mi], ao);
                if (NPASS == 3) LDSM4(al[mi], ao + TILEA);
            }
            uint32_t brow = (uint32_t)(wn * 32 + (lane & 7) + ((lane >> 4) & 1) * 8);
            uint32_t bcol = (uint32_t)(k16 + ((lane >> 3) & 1) * 8);
#pragma unroll
            for (int g = 0; g < 2; g++) {
                uint32_t t4[4];
                uint32_t bo = s0 + NA * TILEA + (brow + g * 16) * 80 + bcol * 2;
                LDSM4(t4, bo);
                bh[g * 2][0] = t4[0]; bh[g * 2][1] = t4[1];
                bh[g * 2 + 1][0] = t4[2]; bh[g * 2 + 1][1] = t4[3];
                LDSM4(t4, bo + TILEB);
                bl[g * 2][0] = t4[0]; bl[g * 2][1] = t4[1];
                bl[g * 2 + 1][0] = t4[2]; bl[g * 2 + 1][1] = t4[3];
            }
#pragma unroll
            for (int mi = 0; mi < MI; mi++)
#pragma unroll
                for (int ni = 0; ni < 4; ni++) {
                    MMA(acc[mi][ni], ah[mi], bh[ni]);
                    MMA(acc[mi][ni], ah[mi], bl[ni]);
                    if (NPASS == 3) MMA(acc[mi][ni], al[mi], bh[ni]);
                }
        }
        __syncthreads();
    }

    // ---- epilogue ----
    int gID = lane >> 2, tig = lane & 3;
#pragma unroll
    for (int mi = 0; mi < MI; mi++) {
#pragma unroll
        for (int ni = 0; ni < 4; ni++) {
            int rloc = wm * AM + mi * 16 + gID;
            int coll = wn * 32 + ni * 8 + tig * 2;
            int row0 = m0 + rloc;
            int col  = n0 + coll;
            if (MODE == 0) {
                float* Cf = (float*)Cv;
                if (col < Ncols) {
                    float b0 = bias ? bias[col] : 0.f;
                    float b1 = bias ? bias[col + 1] : 0.f;
                    float* p0 = Cf + zo_c + (long)row0 * ldc + col;
                    float* p1 = Cf + zo_c + (long)(row0 + 8) * ldc + col;
                    *(float2*)p0 = make_float2(acc[mi][ni][0] * scale + b0, acc[mi][ni][1] * scale + b1);
                    *(float2*)p1 = make_float2(acc[mi][ni][2] * scale + b0, acc[mi][ni][3] * scale + b1);
                }
            } else if (MODE == 1) {
                float* Cf = (float*)Cv;
                float* p0 = Cf + zo_c + (long)row0 * ldc + col;
                float* p1 = Cf + zo_c + (long)(row0 + 8) * ldc + col;
                float2 o0 = *(float2*)p0, o1 = *(float2*)p1;
                o0.x += acc[mi][ni][0]; o0.y += acc[mi][ni][1];
                o1.x += acc[mi][ni][2]; o1.y += acc[mi][ni][3];
                *(float2*)p0 = o0;
                *(float2*)p1 = o1;
            } else if (MODE == 2) {
                // banded shifted store: k = n0 + coll + rloc - 127
                float* Cf = (float*)Cv;
                int k0a = n0 + coll + rloc - 127;
                int k0b = k0a + 8;
                float* r0p = Cf + zo_c + (long)row0 * ldc;
                float* r1p = r0p + 8L * ldc;
                if (k0a >= 0     && k0a < Tn)     r0p[k0a]     = acc[mi][ni][0];
                if (k0a + 1 >= 0 && k0a + 1 < Tn) r0p[k0a + 1] = acc[mi][ni][1];
                if (k0b >= 0     && k0b < Tn)     r1p[k0b]     = acc[mi][ni][2];
                if (k0b + 1 >= 0 && k0b + 1 < Tn) r1p[k0b + 1] = acc[mi][ni][3];
            } else {
                half* Ch = (half*)Cv;
                if (col < Ncols) {
                    half2* p0 = (half2*)(Ch + zo_c + (long)row0 * ldc + col);
                    half2* p1 = (half2*)(Ch + zo_c + (long)(row0 + 8) * ldc + col);
                    *p0 = __floats2half2_rn(acc[mi][ni][0], acc[mi][ni][1]);
                    *p1 = __floats2half2_rn(acc[mi][ni][2], acc[mi][ni][3]);
                }
            }
        }
    }
}

// ---------------- softmax over logits rows -> attn fp16 ----------------
__global__ void softmax_kernel(const float* __restrict__ logits, half* __restrict__ attn) {
    __shared__ float red[8];
    size_t row = blockIdx.x;
    const float* p = logits + row * Tn;
    int t = threadIdx.x;
    float v[6];
    float mx = -1e30f;
#pragma unroll
    for (int k = 0; k < 6; k++) {
        v[k] = p[t + k * 256];
        mx = fmaxf(mx, v[k]);
    }
#pragma unroll
    for (int o = 16; o; o >>= 1) mx = fmaxf(mx, __shfl_xor_sync(0xffffffffu, mx, o));
    if ((t & 31) == 0) red[t >> 5] = mx;
    __syncthreads();
    mx = red[0];
#pragma unroll
    for (int i = 1; i < 8; i++) mx = fmaxf(mx, red[i]);
    __syncthreads();
    float sum = 0.f;
#pragma unroll
    for (int k = 0; k < 6; k++) {
        v[k] = expf(v[k] - mx);
        sum += v[k];
    }
#pragma unroll
    for (int o = 16; o; o >>= 1) sum += __shfl_xor_sync(0xffffffffu, sum, o);
    if ((t & 31) == 0) red[t >> 5] = sum;
    __syncthreads();
    float tot = 0.f;
#pragma unroll
    for (int i = 0; i < 8; i++) tot += red[i];
    float inv = 1.0f / tot;
#pragma unroll
    for (int k = 0; k < 6; k++) {
        int i = t + k * 256;
        attn[row * Tn + i] = __float2half_rn(v[k] * inv);
    }
}

// ---------------- launch ----------------
extern "C" void kernel_launch(void* const* d_in, const int* in_sizes, int n_in,
                              void* d_out, int out_size) {
    const float* x       = (const float*)d_in[0];
    const float* W_q     = (const float*)d_in[1];
    const float* W_k     = (const float*)d_in[2];
    const float* W_v     = (const float*)d_in[3];
    const float* W_rel_k = (const float*)d_in[4];
    const float* W_out   = (const float*)d_in[5];
    const float* b_out   = (const float*)d_in[6];
    const float* rwb     = (const float*)d_in[7];
    const float* rrb     = (const float*)d_in[8];
    float* out = (float*)d_out;

    float *pe, *rK, *Qf, *Kf, *Vf, *logits;
    double* gmax;
    half *xh, *xl, *wqth, *wqtl, *wkth, *wktl, *wvth, *wvtl, *woth, *wotl;
    half *qwh, *qwl, *qrh, *qrl, *kh, *kl, *rkth, *rktl, *vth, *vtl, *attn, *aoh;
    cudaGetSymbolAddress((void**)&pe, g_pe);
    cudaGetSymbolAddress((void**)&rK, g_rK);
    cudaGetSymbolAddress((void**)&gmax, g_gmax);
    cudaGetSymbolAddress((void**)&Qf, g_Qf);
    cudaGetSymbolAddress((void**)&Kf, g_Kf);
    cudaGetSymbolAddress((void**)&Vf, g_Vf);
    cudaGetSymbolAddress((void**)&xh, g_xh);   cudaGetSymbolAddress((void**)&xl, g_xl);
    cudaGetSymbolAddress((void**)&wqth, g_wqth); cudaGetSymbolAddress((void**)&wqtl, g_wqtl);
    cudaGetSymbolAddress((void**)&wkth, g_wkth); cudaGetSymbolAddress((void**)&wktl, g_wktl);
    cudaGetSymbolAddress((void**)&wvth, g_wvth); cudaGetSymbolAddress((void**)&wvtl, g_wvtl);
    cudaGetSymbolAddress((void**)&woth, g_woth); cudaGetSymbolAddress((void**)&wotl, g_wotl);
    cudaGetSymbolAddress((void**)&qwh, g_qwh); cudaGetSymbolAddress((void**)&qwl, g_qwl);
    cudaGetSymbolAddress((void**)&qrh, g_qrh); cudaGetSymbolAddress((void**)&qrl, g_qrl);
    cudaGetSymbolAddress((void**)&kh, g_kh);   cudaGetSymbolAddress((void**)&kl, g_kl);
    cudaGetSymbolAddress((void**)&rkth, g_rkth); cudaGetSymbolAddress((void**)&rktl, g_rktl);
    cudaGetSymbolAddress((void**)&vth, g_vth); cudaGetSymbolAddress((void**)&vtl, g_vtl);
    cudaGetSymbolAddress((void**)&logits, g_logits);
    cudaGetSymbolAddress((void**)&attn, g_attn);
    cudaGetSymbolAddress((void**)&aoh, g_aoh);

    const int SM_3_128 = 2 * (2 * 128 * 80 + 2 * 128 * 80);  // 81920
    const int SM_2_128 = 2 * (1 * 128 * 80 + 2 * 128 * 80);  // 61440
    const int SM_2_64  = 2 * (1 * 128 * 80 + 2 * 64 * 80);   // 40960
    cudaFuncSetAttribute(gemm_mma<128, 3, 0>, cudaFuncAttributeMaxDynamicSharedMemorySize, SM_3_128);
    cudaFuncSetAttribute(gemm_mma<128, 3, 1>, cudaFuncAttributeMaxDynamicSharedMemorySize, SM_3_128);
    cudaFuncSetAttribute(gemm_mma<128, 3, 2>, cudaFuncAttributeMaxDynamicSharedMemorySize, SM_3_128);
    cudaFuncSetAttribute(gemm_mma<128, 2, 0>, cudaFuncAttributeMaxDynamicSharedMemorySize, SM_2_128);
    cudaFuncSetAttribute(gemm_mma<64, 2, 3>,  cudaFuncAttributeMaxDynamicSharedMemorySize, SM_2_64);

    // 1) positional basis + rK (fp32)
    gamma_max_kernel<<<32, 256>>>(gmax);
    pe_kernel<<<(Ln * 32 + 255) / 256, 256>>>(gmax, pe);
    sgemm_kernel<<<dim3(HDK / 64, (Ln + 63) / 64), 256>>>(pe, 192, W_rel_k, HDK, rK, HDK, Ln, HDK, 192);

    // 2) operand prep
    split_kernel<<<(BT * Cin + 255) / 256, 256>>>(x, xh, xl, BT * Cin);
    tsplit_kernel<<<dim3(HDK / 32, Cin / 32), 256>>>(W_q, Cin, HDK, wqth, wqtl);
    tsplit_kernel<<<dim3(HDK / 32, Cin / 32), 256>>>(W_k, Cin, HDK, wkth, wktl);
    tsplit_kernel<<<dim3(HDV / 32, Cin / 32), 256>>>(W_v, Cin, HDV, wvth, wvtl);
    tsplit_kernel<<<dim3(HDV / 32, HDV / 32), 256>>>(W_out, HDV, HDV, woth, wotl);

    // 3) projections: Q,K 3-pass (logit path), V 2-pass
    gemm_mma<128, 3, 0><<<dim3(HDK / 128, BT / 128, 1), 256, SM_3_128>>>(
        xh, xl, Cin, 0, 0, wqth, wqtl, Cin, 0, 0, Qf, HDK, 0, 0, Cin, HDK, 0.125f, nullptr);
    gemm_mma<128, 3, 0><<<dim3(HDK / 128, BT / 128, 1), 256, SM_3_128>>>(
        xh, xl, Cin, 0, 0, wkth, wktl, Cin, 0, 0, Kf, HDK, 0, 0, Cin, HDK, 1.0f, nullptr);
    gemm_mma<128, 2, 0><<<dim3(HDV / 128, BT / 128, 1), 256, SM_2_128>>>(
        xh, xh, Cin, 0, 0, wvth, wvtl, Cin, 0, 0, Vf, HDV, 0, 0, Cin, HDV, 1.0f, nullptr);

    // 4) head reshapes + bias folds + splits
    qkhead_kernel<<<(int)(((long)NBH * Tn * DKn + 255) / 256), 256>>>(
        Qf, Kf, rwb, rrb, qwh, qwl, qrh, qrl, kh, kl);
    rkt_kernel<<<(int)(((long)Hn * Lp * DKn + 255) / 256), 256>>>(rK, rkth, rktl);
    vt_kernel<<<dim3(Tn / 32, DVn / 32, NBH), 256>>>(Vf, vth, vtl);

    // 5) rel = (Q+r_r)·rK^T, banded (13 l-tiles), shifted store into logits
    long sQ = (long)Tn * DKn;
    long sR = (long)Lp * DKn;
    gemm_mma<128, 3, 2><<<dim3(13, Tn / 128, NBH), 256, SM_3_128>>>(
        qrh, qrl, DKn, 8 * sQ, sQ, rkth, rktl, DKn, 0, sR,
        logits, Tn, 8L * Tn * Tn, (long)Tn * Tn, DKn, Tn, 1.0f, nullptr);

    // 6) logits += (Q+r_w)·K^T
    gemm_mma<128, 3, 1><<<dim3(Tn / 128, Tn / 128, NBH), 256, SM_3_128>>>(
        qwh, qwl, DKn, 8 * sQ, sQ, kh, kl, DKn, 8 * sQ, sQ,
        logits, Tn, 8L * Tn * Tn, (long)Tn * Tn, DKn, Tn, 1.0f, nullptr);

    // 7) softmax -> attn fp16 (single)
    softmax_kernel<<<NBH * Tn, 256>>>(logits, attn);

    // 8) out_att = attn·V  (2-pass, A single), fp16 out
    gemm_mma<64, 2, 3><<<dim3(DVn / 64, Tn / 128, NBH), 256, SM_2_64>>>(
        attn, attn, Tn, 8L * Tn * Tn, (long)Tn * Tn,
        vth, vtl, Tn, 8L * DVn * Tn, (long)DVn * Tn,
        aoh, HDV, (long)Tn * HDV, DVn, Tn, DVn, 1.0f, nullptr);

    // 9) final projection (2-pass, A single)
    gemm_mma<128, 2, 0><<<dim3(HDV / 128, BT / 128, 1), 256, SM_2_128>>>(
        aoh, aoh, HDV, 0, 0, woth, wotl, HDV, 0, 0, out, HDV, 0, 0, HDV, HDV, 1.0f, b_out);
}

// round 7
// speedup vs baseline: 5.7608x; 1.0647x over previous
#include <cuda_runtime.h>
#include <cuda_fp16.h>
#include <math.h>
#include <stdint.h>

// Problem constants
#define Tn   1536
#define Bn   4
#define Hn   8
#define DKn  64
#define DVn  192
#define Ln   3071          // 2T-1
#define Lp   3072          // padded
#define HDK  512           // H*DK
#define HDV  1536          // H*DV
#define BT   6144          // B*T
#define NBH  32            // B*H
#define Cin  1536

// ---------------- device scratch ----------------
__device__ float  g_pe[Ln * 192];
__device__ float  g_rK[Ln * HDK];
__device__ double g_gmax[32];

__device__ float  g_Qf[BT * HDK];
__device__ float  g_Kf[BT * HDK];
__device__ float  g_Vf[BT * HDV];

__device__ half   g_xh[BT * Cin], g_xl[BT * Cin];
__device__ half   g_wqth[HDK * Cin], g_wqtl[HDK * Cin];
__device__ half   g_wkth[HDK * Cin], g_wktl[HDK * Cin];
__device__ half   g_wvth[HDV * Cin], g_wvtl[HDV * Cin];
__device__ half   g_woth[HDV * HDV], g_wotl[HDV * HDV];

__device__ half   g_qwh[NBH * Tn * DKn], g_qwl[NBH * Tn * DKn];
__device__ half   g_qrh[NBH * Tn * DKn], g_qrl[NBH * Tn * DKn];
__device__ half   g_kh [NBH * Tn * DKn], g_kl [NBH * Tn * DKn];
__device__ half   g_rkth[Hn * Lp * DKn], g_rktl[Hn * Lp * DKn];
__device__ half   g_vth[NBH * DVn * Tn], g_vtl[NBH * DVn * Tn];

__device__ float  g_logits[75497472];     // 32*1536*1536 (holds rel after banded gemm)
__device__ half   g_aoh[BT * HDV];        // flash output fp16

// ============================================================
// helpers
// ============================================================
__device__ __forceinline__ uint32_t smem_u32(const void* p) {
    uint32_t a;
    asm("{ .reg .u64 t; cvta.to.shared.u64 t, %1; cvt.u32.u64 %0, t; }" : "=r"(a) : "l"(p));
    return a;
}
__device__ __forceinline__ void cp16(uint32_t s, const void* g) {
    asm volatile("cp.async.ca.shared.global [%0], [%1], 16;" :: "r"(s), "l"(g));
}
#define CP_COMMIT() asm volatile("cp.async.commit_group;" ::: "memory")
#define CP_WAIT(n)  asm volatile("cp.async.wait_group %0;" :: "n"(n) : "memory")

#define LDSM4(r, addr) \
    asm volatile("ldmatrix.sync.aligned.m8n8.x4.shared.b16 {%0,%1,%2,%3}, [%4];" \
        : "=r"((r)[0]), "=r"((r)[1]), "=r"((r)[2]), "=r"((r)[3]) : "r"(addr))

#define MMA(acc, a, b) \
    asm volatile("mma.sync.aligned.m16n8k16.row.col.f32.f16.f16.f32 " \
        "{%0,%1,%2,%3},{%4,%5,%6,%7},{%8,%9},{%0,%1,%2,%3};" \
        : "+f"((acc)[0]), "+f"((acc)[1]), "+f"((acc)[2]), "+f"((acc)[3]) \
        : "r"((a)[0]), "r"((a)[1]), "r"((a)[2]), "r"((a)[3]), "r"((b)[0]), "r"((b)[1]))

#define STS32(addr, v) \
    asm volatile("st.shared.b32 [%0], %1;" :: "r"(addr), "r"(v))

// ---------------- positional basis (validated) ----------------
__global__ void gamma_max_kernel(double* gmax) {
    __shared__ double red[256];
    int j = blockIdx.x, t = threadIdx.x;
    double conc  = 4.0 * (j + 1) * (j + 1);
    double rate  = (double)(j + 1) / 12.0;
    double lnorm = lgamma(conc) - conc * log(rate);
    double best = 0.0;
    for (int i = t; i < Ln; i += 256) {
        double pos = fabs((double)(i - (Tn - 1)));
        double lu = (conc - 1.0) * log(pos) - rate * pos;
        double pr = exp(lu - lnorm);
        if (pr > best) best = pr;
    }
    red[t] = best;
    __syncthreads();
    for (int s = 128; s; s >>= 1) {
        if (t < s) red[t] = fmax(red[t], red[t + s]);
        __syncthreads();
    }
    if (t == 0) gmax[j] = red[0] + 1e-8;
}

__global__ void pe_kernel(const double* __restrict__ gmax, float* __restrict__ pe) {
    int idx = blockIdx.x * blockDim.x + threadIdx.x;
    if (idx >= Ln * 32) return;
    int i = idx / 32, j = idx % 32;
    int dist = i - (Tn - 1);
    double pos = fabs((double)dist);
    double mr = log2((double)Tn);
    double hl = exp2(3.0 + (double)j * (mr - 3.0) / 31.0);
    double fe = exp2(-pos / hl);
    double width = exp2((double)(j + 1)) - 1.0;
    double fc = (width > pos) ? 1.0 : 0.0;
    double conc  = 4.0 * (j + 1) * (j + 1);
    double rate  = (double)(j + 1) / 12.0;
    double lnorm = lgamma(conc) - conc * log(rate);
    double pr = exp((conc - 1.0) * log(pos) - rate * pos - lnorm) + 1e-8;
    double fg = pr / gmax[j];
    float sgn = (dist > 0) ? 1.f : ((dist < 0) ? -1.f : 0.f);
    float* row = pe + (size_t)i * 192;
    row[j]       = (float)fe;
    row[32 + j]  = (float)fc;
    row[64 + j]  = (float)fg;
    row[96 + j]  = sgn * (float)fe;
    row[128 + j] = sgn * (float)fc;
    row[160 + j] = sgn * (float)fg;
}

// ---------------- small fp32 sgemm (rK only) ----------------
__global__ void sgemm_kernel(const float* __restrict__ A, int lda,
                             const float* __restrict__ B, int ldb,
                             float* __restrict__ C, int ldc,
                             int M, int N, int K) {
    __shared__ float As[16][68];
    __shared__ float Bs[16][68];
    int t  = threadIdx.x;
    int tx = t & 15, ty = t >> 4;
    int m0 = blockIdx.y * 64, n0 = blockIdx.x * 64;
    int ar = t >> 2, ac = (t & 3) * 4;
    int br = t >> 4, bc = (t & 15) * 4;
    float s[4][4] = {};
    for (int k0 = 0; k0 < K; k0 += 16) {
        float4 av = make_float4(0.f, 0.f, 0.f, 0.f);
        if (m0 + ar < M)
            av = *(const float4*)(A + (size_t)(m0 + ar) * lda + k0 + ac);
        float4 bv = *(const float4*)(B + (size_t)(k0 + br) * ldb + n0 + bc);
        __syncthreads();
        As[ac + 0][ar] = av.x; As[ac + 1][ar] = av.y;
        As[ac + 2][ar] = av.z; As[ac + 3][ar] = av.w;
        *(float4*)&Bs[br][bc] = bv;
        __syncthreads();
#pragma unroll
        for (int kk = 0; kk < 16; kk++) {
            float4 a = *(const float4*)&As[kk][ty * 4];
            float4 b = *(const float4*)&Bs[kk][tx * 4];
            s[0][0] += a.x * b.x; s[0][1] += a.x * b.y; s[0][2] += a.x * b.z; s[0][3] += a.x * b.w;
            s[1][0] += a.y * b.x; s[1][1] += a.y * b.y; s[1][2] += a.y * b.z; s[1][3] += a.y * b.w;
            s[2][0] += a.z * b.x; s[2][1] += a.z * b.y; s[2][2] += a.z * b.z; s[2][3] += a.z * b.w;
            s[3][0] += a.w * b.x; s[3][1] += a.w * b.y; s[3][2] += a.w * b.z; s[3][3] += a.w * b.w;
        }
    }
#pragma unroll
    for (int i = 0; i < 4; i++) {
        int m = m0 + ty * 4 + i;
        if (m < M) {
            float* cp = C + (size_t)m * ldc + n0 + tx * 4;
#pragma unroll
            for (int j = 0; j < 4; j++) cp[j] = s[i][j];
        }
    }
}

// ---------------- hi/lo split helpers (fp16) ----------------
__device__ __forceinline__ void split_h(float v, half* hi, half* lo, long o) {
    half h = __float2half_rn(v);
    hi[o] = h;
    lo[o] = __float2half_rn(v - __half2float(h));
}

__global__ void split_kernel(const float* __restrict__ src, half* __restrict__ hi,
                             half* __restrict__ lo, int n) {
    int i = blockIdx.x * 256 + threadIdx.x;
    if (i < n) split_h(src[i], hi, lo, i);
}

__global__ void tsplit_kernel(const float* __restrict__ src, int K, int N,
                              half* __restrict__ hi, half* __restrict__ lo) {
    __shared__ float tile[32][33];
    int n0 = blockIdx.x * 32, k0 = blockIdx.y * 32;
    int tx = threadIdx.x & 31, ty = threadIdx.x >> 5;
#pragma unroll
    for (int i = 0; i < 32; i += 8)
        tile[ty + i][tx] = src[(long)(k0 + ty + i) * N + n0 + tx];
    __syncthreads();
#pragma unroll
    for (int i = 0; i < 32; i += 8) {
        float v = tile[tx][ty + i];
        long o = (long)(n0 + ty + i) * K + k0 + tx;
        split_h(v, hi, lo, o);
    }
}

__global__ void qkhead_kernel(const float* __restrict__ Qf, const float* __restrict__ Kf,
                              const float* __restrict__ rwb, const float* __restrict__ rrb,
                              half* qwh, half* qwl, half* qrh, half* qrl, half* kh, half* kl) {
    long i = (long)blockIdx.x * 256 + threadIdx.x;
    if (i >= (long)NBH * Tn * DKn) return;
    int d = (int)(i & 63);
    int q = (int)((i >> 6) % Tn);
    int z = (int)(i / ((long)Tn * DKn));
    int h = z & 7, b = z >> 3;
    long src = ((long)(b * Tn + q)) * HDK + h * DKn + d;
    float qv = Qf[src], kv = Kf[src];
    split_h(qv + rwb[h * DKn + d], qwh, qwl, i);
    split_h(qv + rrb[h * DKn + d], qrh, qrl, i);
    split_h(kv, kh, kl, i);
}

__global__ void rkt_kernel(const float* __restrict__ rK, half* rkth, half* rktl) {
    long i = (long)blockIdx.x * 256 + threadIdx.x;
    if (i >= (long)Hn * Lp * DKn) return;
    int d = (int)(i & 63);
    int l = (int)((i >> 6) % Lp);
    int h = (int)(i / ((long)Lp * DKn));
    float v = (l < Ln) ? rK[(long)l * HDK + h * DKn + d] : 0.f;
    split_h(v, rkth, rktl, i);
}

__global__ void vt_kernel(const float* __restrict__ Vf, half* vth, half* vtl) {
    __shared__ float tile[32][33];
    int z = blockIdx.z, h = z & 7, b = z >> 3;
    int t0 = blockIdx.x * 32, d0 = blockIdx.y * 32;
    int tx = threadIdx.x & 31, ty = threadIdx.x >> 5;
#pragma unroll
    for (int i = 0; i < 32; i += 8)
        tile[ty + i][tx] = Vf[((long)(b * Tn + t0 + ty + i)) * HDV + h * DVn + d0 + tx];
    __syncthreads();
#pragma unroll
    for (int i = 0; i < 32; i += 8) {
        float v = tile[tx][ty + i];
        long o = ((long)z * DVn + d0 + ty + i) * Tn + t0 + tx;
        split_h(v, vth, vtl, o);
    }
}

// ============================================================
// mma.sync fp16 GEMM (projections / out-proj / banded rel)
//   NPASS 3: ah.bh+ah.bl+al.bh   NPASS 2: ah.bh+ah.bl (A hi only)
//   MODE 0: fp32 C = scale*acc + bias    MODE 2: banded shifted store (rel)
// ============================================================
template <int NPASS, int MODE>
__global__ void __launch_bounds__(256) gemm_mma(
    const half* __restrict__ Ah, const half* __restrict__ Al, int lda, long sA8, long sA1,
    const half* __restrict__ Bh, const half* __restrict__ Bl, int ldb, long sB8, long sB1,
    void* __restrict__ Cv, int ldc, long sC8, long sC1,
    int Kdim, int Ncols, float scale, const float* __restrict__ bias)
{
    constexpr int NA = (NPASS == 3) ? 2 : 1;
    constexpr int TILEA = 128 * 80;
    constexpr int TILEB = 128 * 80;
    constexpr int STAGE = NA * TILEA + 2 * TILEB;

    extern __shared__ char smem[];
    uint32_t sb = smem_u32(smem);
    int tid = threadIdx.x, lane = tid & 31, wid = tid >> 5;
    int wm = wid >> 2, wn = wid & 3;
    int z = blockIdx.z;
    int m0 = blockIdx.y * 128, n0 = blockIdx.x * 128;

    long zo_a = (long)(z >> 3) * sA8 + (long)(z & 7) * sA1;
    long zo_b = (long)(z >> 3) * sB8 + (long)(z & 7) * sB1;
    long zo_c = (long)(z >> 3) * sC8 + (long)(z & 7) * sC1;
    const half* pAh = Ah + zo_a + (long)m0 * lda;
    const half* pAl = Al + zo_a + (long)m0 * lda;
    long boff = (MODE == 2) ? (long)(Tn - 128 - m0 + n0) : (long)n0;
    const half* pBh = Bh + zo_b + boff * ldb;
    const half* pBl = Bl + zo_b + boff * ldb;

    float acc[4][4][4] = {};
    const int NC = Kdim >> 5;

    auto prefetch = [&](int kc) {
        int k0 = kc * 32;
        uint32_t s0 = sb + (kc & 1) * STAGE;
        for (int i = tid; i < 512; i += 256) {
            int r = i >> 2, c = i & 3;
            uint32_t so = (uint32_t)(r * 80 + c * 16);
            long go = (long)r * lda + k0 + c * 8;
            cp16(s0 + so, pAh + go);
            if (NPASS == 3) cp16(s0 + TILEA + so, pAl + go);
            long gb = (long)r * ldb + k0 + c * 8;
            cp16(s0 + NA * TILEA + so,         pBh + gb);
            cp16(s0 + NA * TILEA + TILEB + so, pBl + gb);
        }
        CP_COMMIT();
    };

    prefetch(0);
    for (int kc = 0; kc < NC; kc++) {
        CP_WAIT(0);
        __syncthreads();
        if (kc + 1 < NC) prefetch(kc + 1);
        uint32_t s0 = sb + (kc & 1) * STAGE;

#pragma unroll
        for (int kk = 0; kk < 2; kk++) {
            int k16 = kk * 16;
            uint32_t ah[4][4], al4[4][4], bh[4][2], bl4[4][2];
            uint32_t arow = (uint32_t)(wm * 64 + (lane & 15));
            uint32_t acol = (uint32_t)(k16 + (lane >> 4) * 8);
#pragma unroll
            for (int mi = 0; mi < 4; mi++) {
                uint32_t ao = s0 + (arow + mi * 16) * 80 + acol * 2;
                LDSM4(ah[mi], ao);
                if (NPASS == 3) LDSM4(al4[mi], ao + TILEA);
            }
            uint32_t brow = (uint32_t)(wn * 32 + (lane & 7) + ((lane >> 4) & 1) * 8);
            uint32_t bcol = (uint32_t)(k16 + ((lane >> 3) & 1) * 8);
#pragma unroll
            for (int g = 0; g < 2; g++) {
                uint32_t t4[4];
                uint32_t bo = s0 + NA * TILEA + (brow + g * 16) * 80 + bcol * 2;
                LDSM4(t4, bo);
                bh[g * 2][0] = t4[0]; bh[g * 2][1] = t4[1];
                bh[g * 2 + 1][0] = t4[2]; bh[g * 2 + 1][1] = t4[3];
                LDSM4(t4, bo + TILEB);
                bl4[g * 2][0] = t4[0]; bl4[g * 2][1] = t4[1];
                bl4[g * 2 + 1][0] = t4[2]; bl4[g * 2 + 1][1] = t4[3];
            }
#pragma unroll
            for (int mi = 0; mi < 4; mi++)
#pragma unroll
                for (int ni = 0; ni < 4; ni++) {
                    MMA(acc[mi][ni], ah[mi], bh[ni]);
                    MMA(acc[mi][ni], ah[mi], bl4[ni]);
                    if (NPASS == 3) MMA(acc[mi][ni], al4[mi], bh[ni]);
                }
        }
        __syncthreads();
    }

    int gID = lane >> 2, tig = lane & 3;
#pragma unroll
    for (int mi = 0; mi < 4; mi++) {
#pragma unroll
        for (int ni = 0; ni < 4; ni++) {
            int rloc = wm * 64 + mi * 16 + gID;
            int coll = wn * 32 + ni * 8 + tig * 2;
            int row0 = m0 + rloc;
            int col  = n0 + coll;
            if (MODE == 0) {
                float* Cf = (float*)Cv;
                if (col < Ncols) {
                    float b0 = bias ? bias[col] : 0.f;
                    float b1 = bias ? bias[col + 1] : 0.f;
                    float* p0 = Cf + zo_c + (long)row0 * ldc + col;
                    float* p1 = Cf + zo_c + (long)(row0 + 8) * ldc + col;
                    *(float2*)p0 = make_float2(acc[mi][ni][0] * scale + b0, acc[mi][ni][1] * scale + b1);
                    *(float2*)p1 = make_float2(acc[mi][ni][2] * scale + b0, acc[mi][ni][3] * scale + b1);
                }
            } else {
                float* Cf = (float*)Cv;
                int k0a = n0 + coll + rloc - 127;
                int k0b = k0a + 8;
                float* r0p = Cf + zo_c + (long)row0 * ldc;
                float* r1p = r0p + 8L * ldc;
                if (k0a >= 0     && k0a < Tn)     r0p[k0a]     = acc[mi][ni][0];
                if (k0a + 1 >= 0 && k0a + 1 < Tn) r0p[k0a + 1] = acc[mi][ni][1];
                if (k0b >= 0     && k0b < Tn)     r1p[k0b]     = acc[mi][ni][2];
                if (k0b + 1 >= 0 && k0b + 1 < Tn) r1p[k0b + 1] = acc[mi][ni][3];
            }
        }
    }
}

// ============================================================
// flash kernel: per (z, 128-q block): S = Qw.K^T (3-pass) + logits(rel),
// online softmax, O += P.V^T (2-pass), O/l -> aoh fp16.
// smem: Q 40960 | K 40960 | P 40960 | V 2x30720 | stats 3584  = 187904
// ============================================================
__global__ void __launch_bounds__(256) flash_kernel(
    const half* __restrict__ qwh_, const half* __restrict__ qwl_,
    const half* __restrict__ kh_,  const half* __restrict__ kl_,
    const half* __restrict__ vth_, const half* __restrict__ vtl_,
    const float* __restrict__ logits, half* __restrict__ aoh)
{
    extern __shared__ char smem[];
    uint32_t sb = smem_u32(smem);
    const uint32_t QB = sb, KB = sb + 40960, PB = sb + 81920, VB = sb + 122880;
    float* mArr = (float*)(smem + 184320);
    float* lArr = mArr + 128;
    float* aArr = lArr + 128;
    float* red  = aArr + 128;   // [128][4]

    int tid = threadIdx.x, lane = tid & 31, wid = tid >> 5;
    int wm = wid >> 2, wn = wid & 3;      // S phase: 2x4 warps
    int wm2 = wid >> 1, wn2 = wid & 1;    // PV phase: 4x2 warps
    int gID = lane >> 2, tig = lane & 3;
    int z = blockIdx.z;
    int q0 = blockIdx.y * 128;
    int h = z & 7, b = z >> 3;

    long zq = (long)z * Tn * DKn;
    const half* pQh = qwh_ + zq + (long)q0 * DKn;
    const half* pQl = qwl_ + zq + (long)q0 * DKn;
    const half* pKh = kh_ + zq;
    const half* pKl = kl_ + zq;
    long zv = (long)z * DVn * Tn;
    const float* pL = logits + (long)z * Tn * Tn + (long)q0 * Tn;

    for (int r = tid; r < 128; r += 256) { mArr[r] = -1e30f; lArr[r] = 0.f; }

    // prologue: Q (hi+lo, 2 chunks) + K tile 0
    for (int i = tid; i < 1024; i += 256) {
        int r = i >> 3, c = i & 7;
        uint32_t off = (uint32_t)((c >> 2) * 10240 + r * 80 + (c & 3) * 16);
        cp16(QB + off,         pQh + (long)r * DKn + c * 8);
        cp16(QB + 20480 + off, pQl + (long)r * DKn + c * 8);
        cp16(KB + off,         pKh + (long)r * DKn + c * 8);
        cp16(KB + 20480 + off, pKl + (long)r * DKn + c * 8);
    }
    CP_COMMIT();

    float O[2][12][4] = {};

    auto loadK = [&](int kn) {
        const half* gh = pKh + (long)kn * 128 * DKn;
        const half* gl = pKl + (long)kn * 128 * DKn;
        for (int i = tid; i < 1024; i += 256) {
            int r = i >> 3, c = i & 7;
            uint32_t off = (uint32_t)((c >> 2) * 10240 + r * 80 + (c & 3) * 16);
            cp16(KB + off,         gh + (long)r * DKn + c * 8);
            cp16(KB + 20480 + off, gl + (long)r * DKn + c * 8);
        }
        CP_COMMIT();
    };

    for (int kt = 0; kt < 12; kt++) {
        CP_WAIT(0);
        __syncthreads();

        // ---- S = Qw . K^T (3-pass) ----
        float S[4][4][4] = {};
#pragma unroll
        for (int chunk = 0; chunk < 2; chunk++) {
            uint32_t qbase = QB + chunk * 10240;
            uint32_t kbase = KB + chunk * 10240;
#pragma unroll
            for (int kk = 0; kk < 2; kk++) {
                int k16 = kk * 16;
                uint32_t ah[4][4], al4[4][4], bh[4][2], bl4[4][2];
                uint32_t arow = (uint32_t)(wm * 64 + (lane & 15));
                uint32_t acol = (uint32_t)(k16 + (lane >> 4) * 8);
#pragma unroll
                for (int mi = 0; mi < 4; mi++) {
                    uint32_t ao = qbase + (arow + mi * 16) * 80 + acol * 2;
                    LDSM4(ah[mi], ao);
                    LDSM4(al4[mi], ao + 20480);
                }
                uint32_t brow = (uint32_t)(wn * 32 + (lane & 7) + ((lane >> 4) & 1) * 8);
                uint32_t bcol = (uint32_t)(k16 + ((lane >> 3) & 1) * 8);
#pragma unroll
                for (int g = 0; g < 2; g++) {
                    uint32_t t4[4];
                    uint32_t bo = kbase + (brow + g * 16) * 80 + bcol * 2;
                    LDSM4(t4, bo);
                    bh[g * 2][0] = t4[0]; bh[g * 2][1] = t4[1];
                    bh[g * 2 + 1][0] = t4[2]; bh[g * 2 + 1][1] = t4[3];
                    LDSM4(t4, bo + 20480);
                    bl4[g * 2][0] = t4[0]; bl4[g * 2][1] = t4[1];
                    bl4[g * 2 + 1][0] = t4[2]; bl4[g * 2 + 1][1] = t4[3];
                }
#pragma unroll
                for (int mi = 0; mi < 4; mi++)
#pragma unroll
                    for (int ni = 0; ni < 4; ni++) {
                        MMA(S[mi][ni], ah[mi], bh[ni]);
                        MMA(S[mi][ni], ah[mi], bl4[ni]);
                        MMA(S[mi][ni], al4[mi], bh[ni]);
                    }
            }
        }

        // ---- add rel bias from logits ----
#pragma unroll
        for (int mi = 0; mi < 4; mi++) {
            int r0 = wm * 64 + mi * 16 + gID;
#pragma unroll
            for (int ni = 0; ni < 4; ni++) {
                long coff = (long)kt * 128 + wn * 32 + ni * 8 + tig * 2;
                float2 v0 = *(const float2*)(pL + (long)r0 * Tn + coff);
                float2 v1 = *(const float2*)(pL + (long)(r0 + 8) * Tn + coff);
                S[mi][ni][0] += v0.x; S[mi][ni][1] += v0.y;
                S[mi][ni][2] += v1.x; S[mi][ni][3] += v1.y;
            }
        }

        // ---- stats a: per-warp row maxes -> red ----
#pragma unroll
        for (int mi = 0; mi < 4; mi++) {
            float m0v = -1e30f, m1v = -1e30f;
#pragma unroll
            for (int ni = 0; ni < 4; ni++) {
                m0v = fmaxf(m0v, fmaxf(S[mi][ni][0], S[mi][ni][1]));
                m1v = fmaxf(m1v, fmaxf(S[mi][ni][2], S[mi][ni][3]));
            }
            m0v = fmaxf(m0v, __shfl_xor_sync(0xffffffffu, m0v, 1));
            m0v = fmaxf(m0v, __shfl_xor_sync(0xffffffffu, m0v, 2));
            m1v = fmaxf(m1v, __shfl_xor_sync(0xffffffffu, m1v, 1));
            m1v = fmaxf(m1v, __shfl_xor_sync(0xffffffffu, m1v, 2));
            if (tig == 0) {
                int r0 = wm * 64 + mi * 16 + gID;
                red[r0 * 4 + wn] = m0v;
                red[(r0 + 8) * 4 + wn] = m1v;
            }
        }
        __syncthreads();

        // ---- stats b: m_new, exp in place, partial sums ----
        float mns0[4], mns1[4], alp0[4], alp1[4], sum0[4], sum1[4];
#pragma unroll
        for (int mi = 0; mi < 4; mi++) {
            int r0 = wm * 64 + mi * 16 + gID, r1 = r0 + 8;
            float mo0 = mArr[r0], mo1 = mArr[r1];
            float mn0 = mo0, mn1 = mo1;
#pragma unroll
            for (int w = 0; w < 4; w++) {
                mn0 = fmaxf(mn0, red[r0 * 4 + w]);
                mn1 = fmaxf(mn1, red[r1 * 4 + w]);
            }
            float s0 = 0.f, s1 = 0.f;
#pragma unroll
            for (int ni = 0; ni < 4; ni++) {
                S[mi][ni][0] = __expf(S[mi][ni][0] - mn0);
                S[mi][ni][1] = __expf(S[mi][ni][1] - mn0);
                S[mi][ni][2] = __expf(S[mi][ni][2] - mn1);
                S[mi][ni][3] = __expf(S[mi][ni][3] - mn1);
                s0 += S[mi][ni][0] + S[mi][ni][1];
                s1 += S[mi][ni][2] + S[mi][ni][3];
            }
            s0 += __shfl_xor_sync(0xffffffffu, s0, 1);
            s0 += __shfl_xor_sync(0xffffffffu, s0, 2);
            s1 += __shfl_xor_sync(0xffffffffu, s1, 1);
            s1 += __shfl_xor_sync(0xffffffffu, s1, 2);
            mns0[mi] = mn0; mns1[mi] = mn1;
            alp0[mi] = __expf(mo0 - mn0); alp1[mi] = __expf(mo1 - mn1);
            sum0[mi] = s0; sum1[mi] = s1;
        }
        __syncthreads();

        // ---- stats c: write sums + alpha; store P ----
#pragma unroll
        for (int mi = 0; mi < 4; mi++) {
            int r0 = wm * 64 + mi * 16 + gID, r1 = r0 + 8;
            if (tig == 0) {
                red[r0 * 4 + wn] = sum0[mi];
                red[r1 * 4 + wn] = sum1[mi];
                if (wn == 0) { aArr[r0] = alp0[mi]; aArr[r1] = alp1[mi]; }
            }
#pragma unroll
            for (int ni = 0; ni < 4; ni++) {
                int colin = ni * 8 + tig * 2;
                half2 h0 = __floats2half2_rn(S[mi][ni][0], S[mi][ni][1]);
                half2 h1 = __floats2half2_rn(S[mi][ni][2], S[mi][ni][3]);
                uint32_t p0 = PB + wn * 10240 + r0 * 80 + colin * 2;
                uint32_t p1 = PB + wn * 10240 + r1 * 80 + colin * 2;
                STS32(p0, *(uint32_t*)&h0);
                STS32(p1, *(uint32_t*)&h1);
            }
        }
        __syncthreads();

        // ---- stats d: owner updates l, m ----
        if (wn == 0 && tig == 0) {
#pragma unroll
            for (int mi = 0; mi < 4; mi++) {
                int r0 = wm * 64 + mi * 16 + gID, r1 = r0 + 8;
                lArr[r0] = lArr[r0] * alp0[mi] + red[r0 * 4 + 0] + red[r0 * 4 + 1] + red[r0 * 4 + 2] + red[r0 * 4 + 3];
                lArr[r1] = lArr[r1] * alp1[mi] + red[r1 * 4 + 0] + red[r1 * 4 + 1] + red[r1 * 4 + 2] + red[r1 * 4 + 3];
                mArr[r0] = mns0[mi];
                mArr[r1] = mns1[mi];
            }
        }

        // ---- prefetch V0, V1, K(next) ----
        {
            const half* gh = vth_ + zv + (long)kt * 128;
            const half* gl = vtl_ + zv + (long)kt * 128;
            for (int cc2 = 0; cc2 < 2; cc2++) {
                uint32_t vb = VB + cc2 * 30720;
                for (int i = tid; i < 768; i += 256) {
                    int r = i >> 2, c4 = i & 3;
                    uint32_t off = (uint32_t)(r * 80 + c4 * 16);
                    cp16(vb + off,         gh + (long)r * Tn + cc2 * 32 + c4 * 8);
                    cp16(vb + 15360 + off, gl + (long)r * Tn + cc2 * 32 + c4 * 8);
                }
                CP_COMMIT();
            }
            loadK((kt + 1 < 12) ? kt + 1 : 11);
        }

        // ---- O rescale ----
#pragma unroll
        for (int mi = 0; mi < 2; mi++) {
            float a0 = aArr[wm2 * 32 + mi * 16 + gID];
            float a1 = aArr[wm2 * 32 + mi * 16 + gID + 8];
#pragma unroll
            for (int ni = 0; ni < 12; ni++) {
                O[mi][ni][0] *= a0; O[mi][ni][1] *= a0;
                O[mi][ni][2] *= a1; O[mi][ni][3] *= a1;
            }
        }

        // ---- PV chunks ----
        auto pvChunk = [&](int c) {
            uint32_t pb = PB + c * 10240;
            uint32_t vb = VB + (c & 1) * 30720;
#pragma unroll
            for (int kk = 0; kk < 2; kk++) {
                int k16 = kk * 16;
                uint32_t pa[2][4], vh[12][2], vl[12][2];
                uint32_t arow = (uint32_t)(wm2 * 32 + (lane & 15));
                uint32_t acol = (uint32_t)(k16 + (lane >> 4) * 8);
#pragma unroll
                for (int mi = 0; mi < 2; mi++)
                    LDSM4(pa[mi], pb + (arow + mi * 16) * 80 + acol * 2);
                uint32_t brow = (uint32_t)(wn2 * 96 + (lane & 7) + ((lane >> 4) & 1) * 8);
                uint32_t bcol = (uint32_t)(k16 + ((lane >> 3) & 1) * 8);
#pragma unroll
                for (int g = 0; g < 6; g++) {
                    uint32_t t4[4];
                    uint32_t bo = vb + (brow + g * 16) * 80 + bcol * 2;
                    LDSM4(t4, bo);
                    vh[g * 2][0] = t4[0]; vh[g * 2][1] = t4[1];
                    vh[g * 2 + 1][0] = t4[2]; vh[g * 2 + 1][1] = t4[3];
                    LDSM4(t4, bo + 15360);
                    vl[g * 2][0] = t4[0]; vl[g * 2][1] = t4[1];
                    vl[g * 2 + 1][0] = t4[2]; vl[g * 2 + 1][1] = t4[3];
                }
#pragma unroll
                for (int mi = 0; mi < 2; mi++)
#pragma unroll
                    for (int ni = 0; ni < 12; ni++) {
                        MMA(O[mi][ni], pa[mi], vh[ni]);
                        MMA(O[mi][ni], pa[mi], vl[ni]);
                    }
            }
        };
        auto loadV = [&](int c) {
            uint32_t vb = VB + (c & 1) * 30720;
            const half* gh = vth_ + zv + (long)kt * 128 + c * 32;
            const half* gl = vtl_ + zv + (long)kt * 128 + c * 32;
            for (int i = tid; i < 768; i += 256) {
                int r = i >> 2, c4 = i & 3;
                uint32_t off = (uint32_t)(r * 80 + c4 * 16);
                cp16(vb + off,         gh + (long)r * Tn + c4 * 8);
                cp16(vb + 15360 + off, gl + (long)r * Tn + c4 * 8);
            }
            CP_COMMIT();
        };

        CP_WAIT(2); __syncthreads();
        pvChunk(0);
        __syncthreads(); loadV(2);
        CP_WAIT(2); __syncthreads();
        pvChunk(1);
        __syncthreads(); loadV(3);
        CP_WAIT(1); __syncthreads();
        pvChunk(2);
        CP_WAIT(0); __syncthreads();
        pvChunk(3);
    }

    // ---- epilogue: O / l -> aoh ----
    __syncthreads();
#pragma unroll
    for (int mi = 0; mi < 2; mi++) {
        int rl0 = wm2 * 32 + mi * 16 + gID, rl1 = rl0 + 8;
        float i0 = 1.f / lArr[rl0], i1 = 1.f / lArr[rl1];
        long base0 = ((long)(b * Tn + q0 + rl0)) * HDV + h * 192;
        long base1 = ((long)(b * Tn + q0 + rl1)) * HDV + h * 192;
#pragma unroll
        for (int ni = 0; ni < 12; ni++) {
            int col = wn2 * 96 + ni * 8 + tig * 2;
            *(half2*)(aoh + base0 + col) = __floats2half2_rn(O[mi][ni][0] * i0, O[mi][ni][1] * i0);
            *(half2*)(aoh + base1 + col) = __floats2half2_rn(O[mi][ni][2] * i1, O[mi][ni][3] * i1);
        }
    }
}

// ---------------- launch ----------------
extern "C" void kernel_launch(void* const* d_in, const int* in_sizes, int n_in,
                              void* d_out, int out_size) {
    const float* x       = (const float*)d_in[0];
    const float* W_q     = (const float*)d_in[1];
    const float* W_k     = (const float*)d_in[2];
    const float* W_v     = (const float*)d_in[3];
    const float* W_rel_k = (const float*)d_in[4];
    const float* W_out   = (const float*)d_in[5];
    const float* b_out   = (const float*)d_in[6];
    const float* rwb     = (const float*)d_in[7];
    const float* rrb     = (const float*)d_in[8];
    float* out = (float*)d_out;

    float *pe, *rK, *Qf, *Kf, *Vf, *logits;
    double* gmax;
    half *xh, *xl, *wqth, *wqtl, *wkth, *wktl, *wvth, *wvtl, *woth, *wotl;
    half *qwh, *qwl, *qrh, *qrl, *kh, *kl, *rkth, *rktl, *vth, *vtl, *aoh;
    cudaGetSymbolAddress((void**)&pe, g_pe);
    cudaGetSymbolAddress((void**)&rK, g_rK);
    cudaGetSymbolAddress((void**)&gmax, g_gmax);
    cudaGetSymbolAddress((void**)&Qf, g_Qf);
    cudaGetSymbolAddress((void**)&Kf, g_Kf);
    cudaGetSymbolAddress((void**)&Vf, g_Vf);
    cudaGetSymbolAddress((void**)&xh, g_xh);   cudaGetSymbolAddress((void**)&xl, g_xl);
    cudaGetSymbolAddress((void**)&wqth, g_wqth); cudaGetSymbolAddress((void**)&wqtl, g_wqtl);
    cudaGetSymbolAddress((void**)&wkth, g_wkth); cudaGetSymbolAddress((void**)&wktl, g_wktl);
    cudaGetSymbolAddress((void**)&wvth, g_wvth); cudaGetSymbolAddress((void**)&wvtl, g_wvtl);
    cudaGetSymbolAddress((void**)&woth, g_woth); cudaGetSymbolAddress((void**)&wotl, g_wotl);
    cudaGetSymbolAddress((void**)&qwh, g_qwh); cudaGetSymbolAddress((void**)&qwl, g_qwl);
    cudaGetSymbolAddress((void**)&qrh, g_qrh); cudaGetSymbolAddress((void**)&qrl, g_qrl);
    cudaGetSymbolAddress((void**)&kh, g_kh);   cudaGetSymbolAddress((void**)&kl, g_kl);
    cudaGetSymbolAddress((void**)&rkth, g_rkth); cudaGetSymbolAddress((void**)&rktl, g_rktl);
    cudaGetSymbolAddress((void**)&vth, g_vth); cudaGetSymbolAddress((void**)&vtl, g_vtl);
    cudaGetSymbolAddress((void**)&logits, g_logits);
    cudaGetSymbolAddress((void**)&aoh, g_aoh);

    const int SM_3 = 2 * (2 * 128 * 80 + 2 * 128 * 80);  // 81920
    const int SM_2 = 2 * (1 * 128 * 80 + 2 * 128 * 80);  // 61440
    const int SM_F = 187904;
    cudaFuncSetAttribute(gemm_mma<3, 0>, cudaFuncAttributeMaxDynamicSharedMemorySize, SM_3);
    cudaFuncSetAttribute(gemm_mma<3, 2>, cudaFuncAttributeMaxDynamicSharedMemorySize, SM_3);
    cudaFuncSetAttribute(gemm_mma<2, 0>, cudaFuncAttributeMaxDynamicSharedMemorySize, SM_2);
    cudaFuncSetAttribute(flash_kernel, cudaFuncAttributeMaxDynamicSharedMemorySize, SM_F);

    // 1) positional basis + rK (fp32)
    gamma_max_kernel<<<32, 256>>>(gmax);
    pe_kernel<<<(Ln * 32 + 255) / 256, 256>>>(gmax, pe);
    sgemm_kernel<<<dim3(HDK / 64, (Ln + 63) / 64), 256>>>(pe, 192, W_rel_k, HDK, rK, HDK, Ln, HDK, 192);

    // 2) operand prep
    split_kernel<<<(BT * Cin + 255) / 256, 256>>>(x, xh, xl, BT * Cin);
    tsplit_kernel<<<dim3(HDK / 32, Cin / 32), 256>>>(W_q, Cin, HDK, wqth, wqtl);
    tsplit_kernel<<<dim3(HDK / 32, Cin / 32), 256>>>(W_k, Cin, HDK, wkth, wktl);
    tsplit_kernel<<<dim3(HDV / 32, Cin / 32), 256>>>(W_v, Cin, HDV, wvth, wvtl);
    tsplit_kernel<<<dim3(HDV / 32, HDV / 32), 256>>>(W_out, HDV, HDV, woth, wotl);

    // 3) projections: Q,K 3-pass; V 2-pass
    gemm_mma<3, 0><<<dim3(HDK / 128, BT / 128, 1), 256, SM_3>>>(
        xh, xl, Cin, 0, 0, wqth, wqtl, Cin, 0, 0, Qf, HDK, 0, 0, Cin, HDK, 0.125f, nullptr);
    gemm_mma<3, 0><<<dim3(HDK / 128, BT / 128, 1), 256, SM_3>>>(
        xh, xl, Cin, 0, 0, wkth, wktl, Cin, 0, 0, Kf, HDK, 0, 0, Cin, HDK, 1.0f, nullptr);
    gemm_mma<2, 0><<<dim3(HDV / 128, BT / 128, 1), 256, SM_2>>>(
        xh, xh, Cin, 0, 0, wvth, wvtl, Cin, 0, 0, Vf, HDV, 0, 0, Cin, HDV, 1.0f, nullptr);

    // 4) head reshapes + bias folds + splits
    qkhead_kernel<<<(int)(((long)NBH * Tn * DKn + 255) / 256), 256>>>(
        Qf, Kf, rwb, rrb, qwh, qwl, qrh, qrl, kh, kl);
    rkt_kernel<<<(int)(((long)Hn * Lp * DKn + 255) / 256), 256>>>(rK, rkth, rktl);
    vt_kernel<<<dim3(Tn / 32, DVn / 32, NBH), 256>>>(Vf, vth, vtl);

    // 5) rel = (Q+r_r).rK^T, banded (13 l-tiles), shifted store into logits
    long sQ = (long)Tn * DKn;
    long sR = (long)Lp * DKn;
    gemm_mma<3, 2><<<dim3(13, Tn / 128, NBH), 256, SM_3>>>(
        qrh, qrl, DKn, 8 * sQ, sQ, rkth, rktl, DKn, 0, sR,
        logits, Tn, 8L * Tn * Tn, (long)Tn * Tn, DKn, Tn, 1.0f, nullptr);

    // 6) flash: content + softmax + attn.V fused
    flash_kernel<<<dim3(1, Tn / 128, NBH), 256, SM_F>>>(
        qwh, qwl, kh, kl, vth, vtl, logits, aoh);

    // 7) final projection (2-pass)
    gemm_mma<2, 0><<<dim3(HDV / 128, BT / 128, 1), 256, SM_2>>>(
        aoh, aoh, HDV, 0, 0, woth, wotl, HDV, 0, 0, out, HDV, 0, 0, HDV, HDV, 1.0f, b_out);
}

// round 8
// speedup vs baseline: 6.1127x; 1.0611x over previous
#include <cuda_runtime.h>
#include <cuda_fp16.h>
#include <math.h>
#include <stdint.h>

// Problem constants
#define Tn   1536
#define Bn   4
#define Hn   8
#define DKn  64
#define DVn  192
#define Ln   3071          // 2T-1
#define Lp   3072          // padded
#define HDK  512           // H*DK
#define HDV  1536          // H*DV
#define BT   6144          // B*T
#define NBH  32            // B*H
#define Cin  1536

// ---------------- device scratch ----------------
__device__ float  g_pe[Ln * 192];
__device__ float  g_rK[Ln * HDK];
__device__ double g_gmax[32];

__device__ float  g_Vf[BT * HDV];

__device__ half   g_xh[BT * Cin], g_xl[BT * Cin];
__device__ half   g_wqkh[1024 * Cin], g_wqkl[1024 * Cin];   // W_q^T | W_k^T concat
__device__ half   g_wvth[HDV * Cin], g_wvtl[HDV * Cin];
__device__ half   g_woth[HDV * HDV], g_wotl[HDV * HDV];

__device__ half   g_qwh[NBH * Tn * DKn], g_qwl[NBH * Tn * DKn];
__device__ half   g_qrh[NBH * Tn * DKn], g_qrl[NBH * Tn * DKn];
__device__ half   g_kh [NBH * Tn * DKn], g_kl [NBH * Tn * DKn];
__device__ half   g_rkth[Hn * Lp * DKn], g_rktl[Hn * Lp * DKn];
__device__ half   g_vth[NBH * DVn * Tn], g_vtl[NBH * DVn * Tn];

__device__ float  g_logits[75497472];     // 32*1536*1536 (holds rel after banded gemm)
__device__ half   g_aoh[BT * HDV];        // flash output fp16

// ============================================================
// helpers
// ============================================================
__device__ __forceinline__ uint32_t smem_u32(const void* p) {
    uint32_t a;
    asm("{ .reg .u64 t; cvta.to.shared.u64 t, %1; cvt.u32.u64 %0, t; }" : "=r"(a) : "l"(p));
    return a;
}
__device__ __forceinline__ void cp16(uint32_t s, const void* g) {
    asm volatile("cp.async.ca.shared.global [%0], [%1], 16;" :: "r"(s), "l"(g));
}
#define CP_COMMIT() asm volatile("cp.async.commit_group;" ::: "memory")
#define CP_WAIT(n)  asm volatile("cp.async.wait_group %0;" :: "n"(n) : "memory")

#define LDSM4(r, addr) \
    asm volatile("ldmatrix.sync.aligned.m8n8.x4.shared.b16 {%0,%1,%2,%3}, [%4];" \
        : "=r"((r)[0]), "=r"((r)[1]), "=r"((r)[2]), "=r"((r)[3]) : "r"(addr))

#define MMA(acc, a, b) \
    asm volatile("mma.sync.aligned.m16n8k16.row.col.f32.f16.f16.f32 " \
        "{%0,%1,%2,%3},{%4,%5,%6,%7},{%8,%9},{%0,%1,%2,%3};" \
        : "+f"((acc)[0]), "+f"((acc)[1]), "+f"((acc)[2]), "+f"((acc)[3]) \
        : "r"((a)[0]), "r"((a)[1]), "r"((a)[2]), "r"((a)[3]), "r"((b)[0]), "r"((b)[1]))

#define STS32(addr, v) \
    asm volatile("st.shared.b32 [%0], %1;" :: "r"(addr), "r"(v))

// ---------------- positional basis (validated) ----------------
__global__ void gamma_max_kernel(double* gmax) {
    __shared__ double red[256];
    int j = blockIdx.x, t = threadIdx.x;
    double conc  = 4.0 * (j + 1) * (j + 1);
    double rate  = (double)(j + 1) / 12.0;
    double lnorm = lgamma(conc) - conc * log(rate);
    double best = 0.0;
    for (int i = t; i < Ln; i += 256) {
        double pos = fabs((double)(i - (Tn - 1)));
        double lu = (conc - 1.0) * log(pos) - rate * pos;
        double pr = exp(lu - lnorm);
        if (pr > best) best = pr;
    }
    red[t] = best;
    __syncthreads();
    for (int s = 128; s; s >>= 1) {
        if (t < s) red[t] = fmax(red[t], red[t + s]);
        __syncthreads();
    }
    if (t == 0) gmax[j] = red[0] + 1e-8;
}

__global__ void pe_kernel(const double* __restrict__ gmax, float* __restrict__ pe) {
    int idx = blockIdx.x * blockDim.x + threadIdx.x;
    if (idx >= Ln * 32) return;
    int i = idx / 32, j = idx % 32;
    int dist = i - (Tn - 1);
    double pos = fabs((double)dist);
    double mr = log2((double)Tn);
    double hl = exp2(3.0 + (double)j * (mr - 3.0) / 31.0);
    double fe = exp2(-pos / hl);
    double width = exp2((double)(j + 1)) - 1.0;
    double fc = (width > pos) ? 1.0 : 0.0;
    double conc  = 4.0 * (j + 1) * (j + 1);
    double rate  = (double)(j + 1) / 12.0;
    double lnorm = lgamma(conc) - conc * log(rate);
    double pr = exp((conc - 1.0) * log(pos) - rate * pos - lnorm) + 1e-8;
    double fg = pr / gmax[j];
    float sgn = (dist > 0) ? 1.f : ((dist < 0) ? -1.f : 0.f);
    float* row = pe + (size_t)i * 192;
    row[j]       = (float)fe;
    row[32 + j]  = (float)fc;
    row[64 + j]  = (float)fg;
    row[96 + j]  = sgn * (float)fe;
    row[128 + j] = sgn * (float)fc;
    row[160 + j] = sgn * (float)fg;
}

// ---------------- small fp32 sgemm (rK only) ----------------
__global__ void sgemm_kernel(const float* __restrict__ A, int lda,
                             const float* __restrict__ B, int ldb,
                             float* __restrict__ C, int ldc,
                             int M, int N, int K) {
    __shared__ float As[16][68];
    __shared__ float Bs[16][68];
    int t  = threadIdx.x;
    int tx = t & 15, ty = t >> 4;
    int m0 = blockIdx.y * 64, n0 = blockIdx.x * 64;
    int ar = t >> 2, ac = (t & 3) * 4;
    int br = t >> 4, bc = (t & 15) * 4;
    float s[4][4] = {};
    for (int k0 = 0; k0 < K; k0 += 16) {
        float4 av = make_float4(0.f, 0.f, 0.f, 0.f);
        if (m0 + ar < M)
            av = *(const float4*)(A + (size_t)(m0 + ar) * lda + k0 + ac);
        float4 bv = *(const float4*)(B + (size_t)(k0 + br) * ldb + n0 + bc);
        __syncthreads();
        As[ac + 0][ar] = av.x; As[ac + 1][ar] = av.y;
        As[ac + 2][ar] = av.z; As[ac + 3][ar] = av.w;
        *(float4*)&Bs[br][bc] = bv;
        __syncthreads();
#pragma unroll
        for (int kk = 0; kk < 16; kk++) {
            float4 a = *(const float4*)&As[kk][ty * 4];
            float4 b = *(const float4*)&Bs[kk][tx * 4];
            s[0][0] += a.x * b.x; s[0][1] += a.x * b.y; s[0][2] += a.x * b.z; s[0][3] += a.x * b.w;
            s[1][0] += a.y * b.x; s[1][1] += a.y * b.y; s[1][2] += a.y * b.z; s[1][3] += a.y * b.w;
            s[2][0] += a.z * b.x; s[2][1] += a.z * b.y; s[2][2] += a.z * b.z; s[2][3] += a.z * b.w;
            s[3][0] += a.w * b.x; s[3][1] += a.w * b.y; s[3][2] += a.w * b.z; s[3][3] += a.w * b.w;
        }
    }
#pragma unroll
    for (int i = 0; i < 4; i++) {
        int m = m0 + ty * 4 + i;
        if (m < M) {
            float* cp = C + (size_t)m * ldc + n0 + tx * 4;
#pragma unroll
            for (int j = 0; j < 4; j++) cp[j] = s[i][j];
        }
    }
}

// ---------------- hi/lo split helpers (fp16) ----------------
__device__ __forceinline__ void split_h(float v, half* hi, half* lo, long o) {
    half h = __float2half_rn(v);
    hi[o] = h;
    lo[o] = __float2half_rn(v - __half2float(h));
}

// vectorized split: 4 floats per thread
__global__ void split_kernel(const float4* __restrict__ src, uint2* __restrict__ hi,
                             uint2* __restrict__ lo, int n4) {
    int i = blockIdx.x * 256 + threadIdx.x;
    if (i >= n4) return;
    float4 v = src[i];
    half h0 = __float2half_rn(v.x), h1 = __float2half_rn(v.y);
    half h2 = __float2half_rn(v.z), h3 = __float2half_rn(v.w);
    half2 hA = __halves2half2(h0, h1), hB = __halves2half2(h2, h3);
    half2 lA = __floats2half2_rn(v.x - __half2float(h0), v.y - __half2float(h1));
    half2 lB = __floats2half2_rn(v.z - __half2float(h2), v.w - __half2float(h3));
    uint2 ho, lw;
    ho.x = *(uint32_t*)&hA; ho.y = *(uint32_t*)&hB;
    lw.x = *(uint32_t*)&lA; lw.y = *(uint32_t*)&lB;
    hi[i] = ho;
    lo[i] = lw;
}

__global__ void tsplit_kernel(const float* __restrict__ src, int K, int N,
                              half* __restrict__ hi, half* __restrict__ lo) {
    __shared__ float tile[32][33];
    int n0 = blockIdx.x * 32, k0 = blockIdx.y * 32;
    int tx = threadIdx.x & 31, ty = threadIdx.x >> 5;
#pragma unroll
    for (int i = 0; i < 32; i += 8)
        tile[ty + i][tx] = src[(long)(k0 + ty + i) * N + n0 + tx];
    __syncthreads();
#pragma unroll
    for (int i = 0; i < 32; i += 8) {
        float v = tile[tx][ty + i];
        long o = (long)(n0 + ty + i) * K + k0 + tx;
        split_h(v, hi, lo, o);
    }
}

__global__ void rkt_kernel(const float* __restrict__ rK, half* rkth, half* rktl) {
    long i = (long)blockIdx.x * 256 + threadIdx.x;
    if (i >= (long)Hn * Lp * DKn) return;
    int d = (int)(i & 63);
    int l = (int)((i >> 6) % Lp);
    int h = (int)(i / ((long)Lp * DKn));
    float v = (l < Ln) ? rK[(long)l * HDK + h * DKn + d] : 0.f;
    split_h(v, rkth, rktl, i);
}

__global__ void vt_kernel(const float* __restrict__ Vf, half* vth, half* vtl) {
    __shared__ float tile[32][33];
    int z = blockIdx.z, h = z & 7, b = z >> 3;
    int t0 = blockIdx.x * 32, d0 = blockIdx.y * 32;
    int tx = threadIdx.x & 31, ty = threadIdx.x >> 5;
#pragma unroll
    for (int i = 0; i < 32; i += 8)
        tile[ty + i][tx] = Vf[((long)(b * Tn + t0 + ty + i)) * HDV + h * DVn + d0 + tx];
    __syncthreads();
#pragma unroll
    for (int i = 0; i < 32; i += 8) {
        float v = tile[tx][ty + i];
        long o = ((long)z * DVn + d0 + ty + i) * Tn + t0 + tx;
        split_h(v, vth, vtl, o);
    }
}

// ============================================================
// mma.sync fp16 GEMM (general):
//   NPASS 3: ah.bh+ah.bl+al.bh   NPASS 2: ah.bh+ah.bl (A hi only)
//   MODE 0: fp32 C = scale*acc + bias    MODE 2: banded shifted store (rel)
// ============================================================
template <int NPASS, int MODE>
__global__ void __launch_bounds__(256) gemm_mma(
    const half* __restrict__ Ah, const half* __restrict__ Al, int lda, long sA8, long sA1,
    const half* __restrict__ Bh, const half* __restrict__ Bl, int ldb, long sB8, long sB1,
    void* __restrict__ Cv, int ldc, long sC8, long sC1,
    int Kdim, int Ncols, float scale, const float* __restrict__ bias)
{
    constexpr int NA = (NPASS == 3) ? 2 : 1;
    constexpr int TILEA = 128 * 80;
    constexpr int TILEB = 128 * 80;
    constexpr int STAGE = NA * TILEA + 2 * TILEB;

    extern __shared__ char smem[];
    uint32_t sb = smem_u32(smem);
    int tid = threadIdx.x, lane = tid & 31, wid = tid >> 5;
    int wm = wid >> 2, wn = wid & 3;
    int z = blockIdx.z;
    int m0 = blockIdx.y * 128, n0 = blockIdx.x * 128;

    long zo_a = (long)(z >> 3) * sA8 + (long)(z & 7) * sA1;
    long zo_b = (long)(z >> 3) * sB8 + (long)(z & 7) * sB1;
    long zo_c = (long)(z >> 3) * sC8 + (long)(z & 7) * sC1;
    const half* pAh = Ah + zo_a + (long)m0 * lda;
    const half* pAl = Al + zo_a + (long)m0 * lda;
    long boff = (MODE == 2) ? (long)(Tn - 128 - m0 + n0) : (long)n0;
    const half* pBh = Bh + zo_b + boff * ldb;
    const half* pBl = Bl + zo_b + boff * ldb;

    float acc[4][4][4] = {};
    const int NC = Kdim >> 5;

    auto prefetch = [&](int kc) {
        int k0 = kc * 32;
        uint32_t s0 = sb + (kc & 1) * STAGE;
        for (int i = tid; i < 512; i += 256) {
            int r = i >> 2, c = i & 3;
            uint32_t so = (uint32_t)(r * 80 + c * 16);
            long go = (long)r * lda + k0 + c * 8;
            cp16(s0 + so, pAh + go);
            if (NPASS == 3) cp16(s0 + TILEA + so, pAl + go);
            long gb = (long)r * ldb + k0 + c * 8;
            cp16(s0 + NA * TILEA + so,         pBh + gb);
            cp16(s0 + NA * TILEA + TILEB + so, pBl + gb);
        }
        CP_COMMIT();
    };

    prefetch(0);
    for (int kc = 0; kc < NC; kc++) {
        CP_WAIT(0);
        __syncthreads();
        if (kc + 1 < NC) prefetch(kc + 1);
        uint32_t s0 = sb + (kc & 1) * STAGE;

#pragma unroll
        for (int kk = 0; kk < 2; kk++) {
            int k16 = kk * 16;
            uint32_t ah[4][4], al4[4][4], bh[4][2], bl4[4][2];
            uint32_t arow = (uint32_t)(wm * 64 + (lane & 15));
            uint32_t acol = (uint32_t)(k16 + (lane >> 4) * 8);
#pragma unroll
            for (int mi = 0; mi < 4; mi++) {
                uint32_t ao = s0 + (arow + mi * 16) * 80 + acol * 2;
                LDSM4(ah[mi], ao);
                if (NPASS == 3) LDSM4(al4[mi], ao + TILEA);
            }
            uint32_t brow = (uint32_t)(wn * 32 + (lane & 7) + ((lane >> 4) & 1) * 8);
            uint32_t bcol = (uint32_t)(k16 + ((lane >> 3) & 1) * 8);
#pragma unroll
            for (int g = 0; g < 2; g++) {
                uint32_t t4[4];
                uint32_t bo = s0 + NA * TILEA + (brow + g * 16) * 80 + bcol * 2;
                LDSM4(t4, bo);
                bh[g * 2][0] = t4[0]; bh[g * 2][1] = t4[1];
                bh[g * 2 + 1][0] = t4[2]; bh[g * 2 + 1][1] = t4[3];
                LDSM4(t4, bo + TILEB);
                bl4[g * 2][0] = t4[0]; bl4[g * 2][1] = t4[1];
                bl4[g * 2 + 1][0] = t4[2]; bl4[g * 2 + 1][1] = t4[3];
            }
#pragma unroll
            for (int mi = 0; mi < 4; mi++)
#pragma unroll
                for (int ni = 0; ni < 4; ni++) {
                    MMA(acc[mi][ni], ah[mi], bh[ni]);
                    MMA(acc[mi][ni], ah[mi], bl4[ni]);
                    if (NPASS == 3) MMA(acc[mi][ni], al4[mi], bh[ni]);
                }
        }
        __syncthreads();
    }

    int gID = lane >> 2, tig = lane & 3;
#pragma unroll
    for (int mi = 0; mi < 4; mi++) {
#pragma unroll
        for (int ni = 0; ni < 4; ni++) {
            int rloc = wm * 64 + mi * 16 + gID;
            int coll = wn * 32 + ni * 8 + tig * 2;
            int row0 = m0 + rloc;
            int col  = n0 + coll;
            if (MODE == 0) {
                float* Cf = (float*)Cv;
                if (col < Ncols) {
                    float b0 = bias ? bias[col] : 0.f;
                    float b1 = bias ? bias[col + 1] : 0.f;
                    float* p0 = Cf + zo_c + (long)row0 * ldc + col;
                    float* p1 = Cf + zo_c + (long)(row0 + 8) * ldc + col;
                    *(float2*)p0 = make_float2(acc[mi][ni][0] * scale + b0, acc[mi][ni][1] * scale + b1);
                    *(float2*)p1 = make_float2(acc[mi][ni][2] * scale + b0, acc[mi][ni][3] * scale + b1);
                }
            } else {
                float* Cf = (float*)Cv;
                int k0a = n0 + coll + rloc - 127;
                int k0b = k0a + 8;
                float* r0p = Cf + zo_c + (long)row0 * ldc;
                float* r1p = r0p + 8L * ldc;
                if (k0a >= 0     && k0a < Tn)     r0p[k0a]     = acc[mi][ni][0];
                if (k0a + 1 >= 0 && k0a + 1 < Tn) r0p[k0a + 1] = acc[mi][ni][1];
                if (k0b >= 0     && k0b < Tn)     r1p[k0b]     = acc[mi][ni][2];
                if (k0b + 1 >= 0 && k0b + 1 < Tn) r1p[k0b + 1] = acc[mi][ni][3];
            }
        }
    }
}

// ============================================================
// fused Q+K projection: C = x @ [W_q | W_k] (N=1024), 3-pass;
// epilogue: Q cols scaled 0.125, +r_w / +r_r folds, hi/lo split,
// head-split layout [z][t][64] direct to qwh/qwl/qrh/qrl/kh/kl.
// ============================================================
__global__ void __launch_bounds__(256) qkproj_kernel(
    const half* __restrict__ Ah, const half* __restrict__ Al,
    const half* __restrict__ Bh, const half* __restrict__ Bl,
    const float* __restrict__ rwb, const float* __restrict__ rrb,
    half* __restrict__ qwh, half* __restrict__ qwl,
    half* __restrict__ qrh, half* __restrict__ qrl,
    half* __restrict__ kh,  half* __restrict__ kl)
{
    constexpr int TILEA = 128 * 80;
    constexpr int TILEB = 128 * 80;
    constexpr int STAGE = 2 * TILEA + 2 * TILEB;

    extern __shared__ char smem[];
    uint32_t sb = smem_u32(smem);
    int tid = threadIdx.x, lane = tid & 31, wid = tid >> 5;
    int wm = wid >> 2, wn = wid & 3;
    int m0 = blockIdx.y * 128, n0 = blockIdx.x * 128;
    int bIdx = m0 / Tn, t0 = m0 % Tn;

    const half* pAh = Ah + (long)m0 * Cin;
    const half* pAl = Al + (long)m0 * Cin;
    const half* pBh = Bh + (long)n0 * Cin;
    const half* pBl = Bl + (long)n0 * Cin;

    float acc[4][4][4] = {};
    const int NC = Cin >> 5;

    auto prefetch = [&](int kc) {
        int k0 = kc * 32;
        uint32_t s0 = sb + (kc & 1) * STAGE;
        for (int i = tid; i < 512; i += 256) {
            int r = i >> 2, c = i & 3;
            uint32_t so = (uint32_t)(r * 80 + c * 16);
            long go = (long)r * Cin + k0 + c * 8;
            cp16(s0 + so,         pAh + go);
            cp16(s0 + TILEA + so, pAl + go);
            cp16(s0 + 2 * TILEA + so,         pBh + go);
            cp16(s0 + 2 * TILEA + TILEB + so, pBl + go);
        }
        CP_COMMIT();
    };

    prefetch(0);
    for (int kc = 0; kc < NC; kc++) {
        CP_WAIT(0);
        __syncthreads();
        if (kc + 1 < NC) prefetch(kc + 1);
        uint32_t s0 = sb + (kc & 1) * STAGE;

#pragma unroll
        for (int kk = 0; kk < 2; kk++) {
            int k16 = kk * 16;
            uint32_t ah[4][4], al4[4][4], bh[4][2], bl4[4][2];
            uint32_t arow = (uint32_t)(wm * 64 + (lane & 15));
            uint32_t acol = (uint32_t)(k16 + (lane >> 4) * 8);
#pragma unroll
            for (int mi = 0; mi < 4; mi++) {
                uint32_t ao = s0 + (arow + mi * 16) * 80 + acol * 2;
                LDSM4(ah[mi], ao);
                LDSM4(al4[mi], ao + TILEA);
            }
            uint32_t brow = (uint32_t)(wn * 32 + (lane & 7) + ((lane >> 4) & 1) * 8);
            uint32_t bcol = (uint32_t)(k16 + ((lane >> 3) & 1) * 8);
#pragma unroll
            for (int g = 0; g < 2; g++) {
                uint32_t t4[4];
                uint32_t bo = s0 + 2 * TILEA + (brow + g * 16) * 80 + bcol * 2;
                LDSM4(t4, bo);
                bh[g * 2][0] = t4[0]; bh[g * 2][1] = t4[1];
                bh[g * 2 + 1][0] = t4[2]; bh[g * 2 + 1][1] = t4[3];
                LDSM4(t4, bo + TILEB);
                bl4[g * 2][0] = t4[0]; bl4[g * 2][1] = t4[1];
                bl4[g * 2 + 1][0] = t4[2]; bl4[g * 2 + 1][1] = t4[3];
            }
#pragma unroll
            for (int mi = 0; mi < 4; mi++)
#pragma unroll
                for (int ni = 0; ni < 4; ni++) {
                    MMA(acc[mi][ni], ah[mi], bh[ni]);
                    MMA(acc[mi][ni], ah[mi], bl4[ni]);
                    MMA(acc[mi][ni], al4[mi], bh[ni]);
                }
        }
        __syncthreads();
    }

    // ---- epilogue: head-split + bias fold + hi/lo split ----
    int gID = lane >> 2, tig = lane & 3;
#pragma unroll
    for (int mi = 0; mi < 4; mi++) {
#pragma unroll
        for (int ni = 0; ni < 4; ni++) {
            int rloc = wm * 64 + mi * 16 + gID;
            int coll = wn * 32 + ni * 8 + tig * 2;
            int col  = n0 + coll;
#pragma unroll
            for (int half_i = 0; half_i < 2; half_i++) {
                int t = t0 + rloc + half_i * 8;
                float v0 = acc[mi][ni][half_i * 2 + 0];
                float v1 = acc[mi][ni][half_i * 2 + 1];
                if (col < 512) {
                    int h = col >> 6, d = col & 63;
                    long o = ((long)(bIdx * 8 + h) * Tn + t) * 64 + d;
                    float q0 = v0 * 0.125f, q1 = v1 * 0.125f;
                    float w0 = q0 + rwb[col], w1 = q1 + rwb[col + 1];
                    float r0 = q0 + rrb[col], r1 = q1 + rrb[col + 1];
                    half wh0 = __float2half_rn(w0), wh1 = __float2half_rn(w1);
                    half rh0 = __float2half_rn(r0), rh1 = __float2half_rn(r1);
                    *(half2*)(qwh + o) = __halves2half2(wh0, wh1);
                    *(half2*)(qwl + o) = __floats2half2_rn(w0 - __half2float(wh0), w1 - __half2float(wh1));
                    *(half2*)(qrh + o) = __halves2half2(rh0, rh1);
                    *(half2*)(qrl + o) = __floats2half2_rn(r0 - __half2float(rh0), r1 - __half2float(rh1));
                } else {
                    int ck = col - 512;
                    int h = ck >> 6, d = ck & 63;
                    long o = ((long)(bIdx * 8 + h) * Tn + t) * 64 + d;
                    half kh0 = __float2half_rn(v0), kh1 = __float2half_rn(v1);
                    *(half2*)(kh + o) = __halves2half2(kh0, kh1);
                    *(half2*)(kl + o) = __floats2half2_rn(v0 - __half2float(kh0), v1 - __half2float(kh1));
                }
            }
        }
    }
}

// ============================================================
// flash kernel (unchanged from R6 winner)
// ============================================================
__global__ void __launch_bounds__(256) flash_kernel(
    const half* __restrict__ qwh_, const half* __restrict__ qwl_,
    const half* __restrict__ kh_,  const half* __restrict__ kl_,
    const half* __restrict__ vth_, const half* __restrict__ vtl_,
    const float* __restrict__ logits, half* __restrict__ aoh)
{
    extern __shared__ char smem[];
    uint32_t sb = smem_u32(smem);
    const uint32_t QB = sb, KB = sb + 40960, PB = sb + 81920, VB = sb + 122880;
    float* mArr = (float*)(smem + 184320);
    float* lArr = mArr + 128;
    float* aArr = lArr + 128;
    float* red  = aArr + 128;   // [128][4]

    int tid = threadIdx.x, lane = tid & 31, wid = tid >> 5;
    int wm = wid >> 2, wn = wid & 3;
    int wm2 = wid >> 1, wn2 = wid & 1;
    int gID = lane >> 2, tig = lane & 3;
    int z = blockIdx.z;
    int q0 = blockIdx.y * 128;
    int h = z & 7, b = z >> 3;

    long zq = (long)z * Tn * DKn;
    const half* pQh = qwh_ + zq + (long)q0 * DKn;
    const half* pQl = qwl_ + zq + (long)q0 * DKn;
    const half* pKh = kh_ + zq;
    const half* pKl = kl_ + zq;
    long zv = (long)z * DVn * Tn;
    const float* pL = logits + (long)z * Tn * Tn + (long)q0 * Tn;

    for (int r = tid; r < 128; r += 256) { mArr[r] = -1e30f; lArr[r] = 0.f; }

    for (int i = tid; i < 1024; i += 256) {
        int r = i >> 3, c = i & 7;
        uint32_t off = (uint32_t)((c >> 2) * 10240 + r * 80 + (c & 3) * 16);
        cp16(QB + off,         pQh + (long)r * DKn + c * 8);
        cp16(QB + 20480 + off, pQl + (long)r * DKn + c * 8);
        cp16(KB + off,         pKh + (long)r * DKn + c * 8);
        cp16(KB + 20480 + off, pKl + (long)r * DKn + c * 8);
    }
    CP_COMMIT();

    float O[2][12][4] = {};

    auto loadK = [&](int kn) {
        const half* gh = pKh + (long)kn * 128 * DKn;
        const half* gl = pKl + (long)kn * 128 * DKn;
        for (int i = tid; i < 1024; i += 256) {
            int r = i >> 3, c = i & 7;
            uint32_t off = (uint32_t)((c >> 2) * 10240 + r * 80 + (c & 3) * 16);
            cp16(KB + off,         gh + (long)r * DKn + c * 8);
            cp16(KB + 20480 + off, gl + (long)r * DKn + c * 8);
        }
        CP_COMMIT();
    };

    for (int kt = 0; kt < 12; kt++) {
        CP_WAIT(0);
        __syncthreads();

        float S[4][4][4] = {};
#pragma unroll
        for (int chunk = 0; chunk < 2; chunk++) {
            uint32_t qbase = QB + chunk * 10240;
            uint32_t kbase = KB + chunk * 10240;
#pragma unroll
            for (int kk = 0; kk < 2; kk++) {
                int k16 = kk * 16;
                uint32_t ah[4][4], al4[4][4], bh[4][2], bl4[4][2];
                uint32_t arow = (uint32_t)(wm * 64 + (lane & 15));
                uint32_t acol = (uint32_t)(k16 + (lane >> 4) * 8);
#pragma unroll
                for (int mi = 0; mi < 4; mi++) {
                    uint32_t ao = qbase + (arow + mi * 16) * 80 + acol * 2;
                    LDSM4(ah[mi], ao);
                    LDSM4(al4[mi], ao + 20480);
                }
                uint32_t brow = (uint32_t)(wn * 32 + (lane & 7) + ((lane >> 4) & 1) * 8);
                uint32_t bcol = (uint32_t)(k16 + ((lane >> 3) & 1) * 8);
#pragma unroll
                for (int g = 0; g < 2; g++) {
                    uint32_t t4[4];
                    uint32_t bo = kbase + (brow + g * 16) * 80 + bcol * 2;
                    LDSM4(t4, bo);
                    bh[g * 2][0] = t4[0]; bh[g * 2][1] = t4[1];
                    bh[g * 2 + 1][0] = t4[2]; bh[g * 2 + 1][1] = t4[3];
                    LDSM4(t4, bo + 20480);
                    bl4[g * 2][0] = t4[0]; bl4[g * 2][1] = t4[1];
                    bl4[g * 2 + 1][0] = t4[2]; bl4[g * 2 + 1][1] = t4[3];
                }
#pragma unroll
                for (int mi = 0; mi < 4; mi++)
#pragma unroll
                    for (int ni = 0; ni < 4; ni++) {
                        MMA(S[mi][ni], ah[mi], bh[ni]);
                        MMA(S[mi][ni], ah[mi], bl4[ni]);
                        MMA(S[mi][ni], al4[mi], bh[ni]);
                    }
            }
        }

#pragma unroll
        for (int mi = 0; mi < 4; mi++) {
            int r0 = wm * 64 + mi * 16 + gID;
#pragma unroll
            for (int ni = 0; ni < 4; ni++) {
                long coff = (long)kt * 128 + wn * 32 + ni * 8 + tig * 2;
                float2 v0 = *(const float2*)(pL + (long)r0 * Tn + coff);
                float2 v1 = *(const float2*)(pL + (long)(r0 + 8) * Tn + coff);
                S[mi][ni][0] += v0.x; S[mi][ni][1] += v0.y;
                S[mi][ni][2] += v1.x; S[mi][ni][3] += v1.y;
            }
        }

#pragma unroll
        for (int mi = 0; mi < 4; mi++) {
            float m0v = -1e30f, m1v = -1e30f;
#pragma unroll
            for (int ni = 0; ni < 4; ni++) {
                m0v = fmaxf(m0v, fmaxf(S[mi][ni][0], S[mi][ni][1]));
                m1v = fmaxf(m1v, fmaxf(S[mi][ni][2], S[mi][ni][3]));
            }
            m0v = fmaxf(m0v, __shfl_xor_sync(0xffffffffu, m0v, 1));
            m0v = fmaxf(m0v, __shfl_xor_sync(0xffffffffu, m0v, 2));
            m1v = fmaxf(m1v, __shfl_xor_sync(0xffffffffu, m1v, 1));
            m1v = fmaxf(m1v, __shfl_xor_sync(0xffffffffu, m1v, 2));
            if (tig == 0) {
                int r0 = wm * 64 + mi * 16 + gID;
                red[r0 * 4 + wn] = m0v;
                red[(r0 + 8) * 4 + wn] = m1v;
            }
        }
        __syncthreads();

        float mns0[4], mns1[4], alp0[4], alp1[4], sum0[4], sum1[4];
#pragma unroll
        for (int mi = 0; mi < 4; mi++) {
            int r0 = wm * 64 + mi * 16 + gID, r1 = r0 + 8;
            float mo0 = mArr[r0], mo1 = mArr[r1];
            float mn0 = mo0, mn1 = mo1;
#pragma unroll
            for (int w = 0; w < 4; w++) {
                mn0 = fmaxf(mn0, red[r0 * 4 + w]);
                mn1 = fmaxf(mn1, red[r1 * 4 + w]);
            }
            float s0 = 0.f, s1 = 0.f;
#pragma unroll
            for (int ni = 0; ni < 4; ni++) {
                S[mi][ni][0] = __expf(S[mi][ni][0] - mn0);
                S[mi][ni][1] = __expf(S[mi][ni][1] - mn0);
                S[mi][ni][2] = __expf(S[mi][ni][2] - mn1);
                S[mi][ni][3] = __expf(S[mi][ni][3] - mn1);
                s0 += S[mi][ni][0] + S[mi][ni][1];
                s1 += S[mi][ni][2] + S[mi][ni][3];
            }
            s0 += __shfl_xor_sync(0xffffffffu, s0, 1);
            s0 += __shfl_xor_sync(0xffffffffu, s0, 2);
            s1 += __shfl_xor_sync(0xffffffffu, s1, 1);
            s1 += __shfl_xor_sync(0xffffffffu, s1, 2);
            mns0[mi] = mn0; mns1[mi] = mn1;
            alp0[mi] = __expf(mo0 - mn0); alp1[mi] = __expf(mo1 - mn1);
            sum0[mi] = s0; sum1[mi] = s1;
        }
        __syncthreads();

#pragma unroll
        for (int mi = 0; mi < 4; mi++) {
            int r0 = wm * 64 + mi * 16 + gID, r1 = r0 + 8;
            if (tig == 0) {
                red[r0 * 4 + wn] = sum0[mi];
                red[r1 * 4 + wn] = sum1[mi];
                if (wn == 0) { aArr[r0] = alp0[mi]; aArr[r1] = alp1[mi]; }
            }
#pragma unroll
            for (int ni = 0; ni < 4; ni++) {
                int colin = ni * 8 + tig * 2;
                half2 h0 = __floats2half2_rn(S[mi][ni][0], S[mi][ni][1]);
                half2 h1 = __floats2half2_rn(S[mi][ni][2], S[mi][ni][3]);
                uint32_t p0 = PB + wn * 10240 + r0 * 80 + colin * 2;
                uint32_t p1 = PB + wn * 10240 + r1 * 80 + colin * 2;
                STS32(p0, *(uint32_t*)&h0);
                STS32(p1, *(uint32_t*)&h1);
            }
        }
        __syncthreads();

        if (wn == 0 && tig == 0) {
#pragma unroll
            for (int mi = 0; mi < 4; mi++) {
                int r0 = wm * 64 + mi * 16 + gID, r1 = r0 + 8;
                lArr[r0] = lArr[r0] * alp0[mi] + red[r0 * 4 + 0] + red[r0 * 4 + 1] + red[r0 * 4 + 2] + red[r0 * 4 + 3];
                lArr[r1] = lArr[r1] * alp1[mi] + red[r1 * 4 + 0] + red[r1 * 4 + 1] + red[r1 * 4 + 2] + red[r1 * 4 + 3];
                mArr[r0] = mns0[mi];
                mArr[r1] = mns1[mi];
            }
        }

        {
            const half* gh = vth_ + zv + (long)kt * 128;
            const half* gl = vtl_ + zv + (long)kt * 128;
            for (int cc2 = 0; cc2 < 2; cc2++) {
                uint32_t vb = VB + cc2 * 30720;
                for (int i = tid; i < 768; i += 256) {
                    int r = i >> 2, c4 = i & 3;
                    uint32_t off = (uint32_t)(r * 80 + c4 * 16);
                    cp16(vb + off,         gh + (long)r * Tn + cc2 * 32 + c4 * 8);
                    cp16(vb + 15360 + off, gl + (long)r * Tn + cc2 * 32 + c4 * 8);
                }
                CP_COMMIT();
            }
            loadK((kt + 1 < 12) ? kt + 1 : 11);
        }

#pragma unroll
        for (int mi = 0; mi < 2; mi++) {
            float a0 = aArr[wm2 * 32 + mi * 16 + gID];
            float a1 = aArr[wm2 * 32 + mi * 16 + gID + 8];
#pragma unroll
            for (int ni = 0; ni < 12; ni++) {
                O[mi][ni][0] *= a0; O[mi][ni][1] *= a0;
                O[mi][ni][2] *= a1; O[mi][ni][3] *= a1;
            }
        }

        auto pvChunk = [&](int c) {
            uint32_t pb = PB + c * 10240;
            uint32_t vb = VB + (c & 1) * 30720;
#pragma unroll
            for (int kk = 0; kk < 2; kk++) {
                int k16 = kk * 16;
                uint32_t pa[2][4], vh[12][2], vl[12][2];
                uint32_t arow = (uint32_t)(wm2 * 32 + (lane & 15));
                uint32_t acol = (uint32_t)(k16 + (lane >> 4) * 8);
#pragma unroll
                for (int mi = 0; mi < 2; mi++)
                    LDSM4(pa[mi], pb + (arow + mi * 16) * 80 + acol * 2);
                uint32_t brow = (uint32_t)(wn2 * 96 + (lane & 7) + ((lane >> 4) & 1) * 8);
                uint32_t bcol = (uint32_t)(k16 + ((lane >> 3) & 1) * 8);
#pragma unroll
                for (int g = 0; g < 6; g++) {
                    uint32_t t4[4];
                    uint32_t bo = vb + (brow + g * 16) * 80 + bcol * 2;
                    LDSM4(t4, bo);
                    vh[g * 2][0] = t4[0]; vh[g * 2][1] = t4[1];
                    vh[g * 2 + 1][0] = t4[2]; vh[g * 2 + 1][1] = t4[3];
                    LDSM4(t4, bo + 15360);
                    vl[g * 2][0] = t4[0]; vl[g * 2][1] = t4[1];
                    vl[g * 2 + 1][0] = t4[2]; vl[g * 2 + 1][1] = t4[3];
                }
#pragma unroll
                for (int mi = 0; mi < 2; mi++)
#pragma unroll
                    for (int ni = 0; ni < 12; ni++) {
                        MMA(O[mi][ni], pa[mi], vh[ni]);
                        MMA(O[mi][ni], pa[mi], vl[ni]);
                    }
            }
        };
        auto loadV = [&](int c) {
            uint32_t vb = VB + (c & 1) * 30720;
            const half* gh = vth_ + zv + (long)kt * 128 + c * 32;
            const half* gl = vtl_ + zv + (long)kt * 128 + c * 32;
            for (int i = tid; i < 768; i += 256) {
                int r = i >> 2, c4 = i & 3;
                uint32_t off = (uint32_t)(r * 80 + c4 * 16);
                cp16(vb + off,         gh + (long)r * Tn + c4 * 8);
                cp16(vb + 15360 + off, gl + (long)r * Tn + c4 * 8);
            }
            CP_COMMIT();
        };

        CP_WAIT(2); __syncthreads();
        pvChunk(0);
        __syncthreads(); loadV(2);
        CP_WAIT(2); __syncthreads();
        pvChunk(1);
        __syncthreads(); loadV(3);
        CP_WAIT(1); __syncthreads();
        pvChunk(2);
        CP_WAIT(0); __syncthreads();
        pvChunk(3);
    }

    __syncthreads();
#pragma unroll
    for (int mi = 0; mi < 2; mi++) {
        int rl0 = wm2 * 32 + mi * 16 + gID, rl1 = rl0 + 8;
        float i0 = 1.f / lArr[rl0], i1 = 1.f / lArr[rl1];
        long base0 = ((long)(b * Tn + q0 + rl0)) * HDV + h * 192;
        long base1 = ((long)(b * Tn + q0 + rl1)) * HDV + h * 192;
#pragma unroll
        for (int ni = 0; ni < 12; ni++) {
            int col = wn2 * 96 + ni * 8 + tig * 2;
            *(half2*)(aoh + base0 + col) = __floats2half2_rn(O[mi][ni][0] * i0, O[mi][ni][1] * i0);
            *(half2*)(aoh + base1 + col) = __floats2half2_rn(O[mi][ni][2] * i1, O[mi][ni][3] * i1);
        }
    }
}

// ---------------- launch ----------------
extern "C" void kernel_launch(void* const* d_in, const int* in_sizes, int n_in,
                              void* d_out, int out_size) {
    const float* x       = (const float*)d_in[0];
    const float* W_q     = (const float*)d_in[1];
    const float* W_k     = (const float*)d_in[2];
    const float* W_v     = (const float*)d_in[3];
    const float* W_rel_k = (const float*)d_in[4];
    const float* W_out   = (const float*)d_in[5];
    const float* b_out   = (const float*)d_in[6];
    const float* rwb     = (const float*)d_in[7];
    const float* rrb     = (const float*)d_in[8];
    float* out = (float*)d_out;

    float *pe, *rK, *Vf, *logits;
    double* gmax;
    half *xh, *xl, *wqkh, *wqkl, *wvth, *wvtl, *woth, *wotl;
    half *qwh, *qwl, *qrh, *qrl, *kh, *kl, *rkth, *rktl, *vth, *vtl, *aoh;
    cudaGetSymbolAddress((void**)&pe, g_pe);
    cudaGetSymbolAddress((void**)&rK, g_rK);
    cudaGetSymbolAddress((void**)&gmax, g_gmax);
    cudaGetSymbolAddress((void**)&Vf, g_Vf);
    cudaGetSymbolAddress((void**)&xh, g_xh);   cudaGetSymbolAddress((void**)&xl, g_xl);
    cudaGetSymbolAddress((void**)&wqkh, g_wqkh); cudaGetSymbolAddress((void**)&wqkl, g_wqkl);
    cudaGetSymbolAddress((void**)&wvth, g_wvth); cudaGetSymbolAddress((void**)&wvtl, g_wvtl);
    cudaGetSymbolAddress((void**)&woth, g_woth); cudaGetSymbolAddress((void**)&wotl, g_wotl);
    cudaGetSymbolAddress((void**)&qwh, g_qwh); cudaGetSymbolAddress((void**)&qwl, g_qwl);
    cudaGetSymbolAddress((void**)&qrh, g_qrh); cudaGetSymbolAddress((void**)&qrl, g_qrl);
    cudaGetSymbolAddress((void**)&kh, g_kh);   cudaGetSymbolAddress((void**)&kl, g_kl);
    cudaGetSymbolAddress((void**)&rkth, g_rkth); cudaGetSymbolAddress((void**)&rktl, g_rktl);
    cudaGetSymbolAddress((void**)&vth, g_vth); cudaGetSymbolAddress((void**)&vtl, g_vtl);
    cudaGetSymbolAddress((void**)&logits, g_logits);
    cudaGetSymbolAddress((void**)&aoh, g_aoh);

    const int SM_3 = 2 * (2 * 128 * 80 + 2 * 128 * 80);  // 81920
    const int SM_2 = 2 * (1 * 128 * 80 + 2 * 128 * 80);  // 61440
    const int SM_F = 187904;
    cudaFuncSetAttribute(gemm_mma<3, 2>, cudaFuncAttributeMaxDynamicSharedMemorySize, SM_3);
    cudaFuncSetAttribute(gemm_mma<2, 0>, cudaFuncAttributeMaxDynamicSharedMemorySize, SM_2);
    cudaFuncSetAttribute(qkproj_kernel, cudaFuncAttributeMaxDynamicSharedMemorySize, SM_3);
    cudaFuncSetAttribute(flash_kernel, cudaFuncAttributeMaxDynamicSharedMemorySize, SM_F);

    // 1) positional basis + rK (fp32)
    gamma_max_kernel<<<32, 256>>>(gmax);
    pe_kernel<<<(Ln * 32 + 255) / 256, 256>>>(gmax, pe);
    sgemm_kernel<<<dim3(HDK / 64, (Ln + 63) / 64), 256>>>(pe, 192, W_rel_k, HDK, rK, HDK, Ln, HDK, 192);

    // 2) operand prep
    split_kernel<<<(BT * Cin / 4 + 255) / 256, 256>>>(
        (const float4*)x, (uint2*)xh, (uint2*)xl, BT * Cin / 4);
    tsplit_kernel<<<dim3(HDK / 32, Cin / 32), 256>>>(W_q, Cin, HDK, wqkh, wqkl);
    tsplit_kernel<<<dim3(HDK / 32, Cin / 32), 256>>>(W_k, Cin, HDK,
                                                     wqkh + (long)512 * Cin, wqkl + (long)512 * Cin);
    tsplit_kernel<<<dim3(HDV / 32, Cin / 32), 256>>>(W_v, Cin, HDV, wvth, wvtl);
    tsplit_kernel<<<dim3(HDV / 32, HDV / 32), 256>>>(W_out, HDV, HDV, woth, wotl);
    rkt_kernel<<<(int)(((long)Hn * Lp * DKn + 255) / 256), 256>>>(rK, rkth, rktl);

    // 3) fused Q+K projection with head-split epilogue (3-pass, N=1024)
    qkproj_kernel<<<dim3(1024 / 128, BT / 128, 1), 256, SM_3>>>(
        xh, xl, wqkh, wqkl, rwb, rrb, qwh, qwl, qrh, qrl, kh, kl);

    // 4) V projection (2-pass) + head transpose
    gemm_mma<2, 0><<<dim3(HDV / 128, BT / 128, 1), 256, SM_2>>>(
        xh, xh, Cin, 0, 0, wvth, wvtl, Cin, 0, 0, Vf, HDV, 0, 0, Cin, HDV, 1.0f, nullptr);
    vt_kernel<<<dim3(Tn / 32, DVn / 32, NBH), 256>>>(Vf, vth, vtl);

    // 5) rel = (Q+r_r).rK^T, banded (13 l-tiles), shifted store into logits
    long sQ = (long)Tn * DKn;
    long sR = (long)Lp * DKn;
    gemm_mma<3, 2><<<dim3(13, Tn / 128, NBH), 256, SM_3>>>(
        qrh, qrl, DKn, 8 * sQ, sQ, rkth, rktl, DKn, 0, sR,
        logits, Tn, 8L * Tn * Tn, (long)Tn * Tn, DKn, Tn, 1.0f, nullptr);

    // 6) flash: content + softmax + attn.V fused
    flash_kernel<<<dim3(1, Tn / 128, NBH), 256, SM_F>>>(
        qwh, qwl, kh, kl, vth, vtl, logits, aoh);

    // 7) final projection (2-pass)
    gemm_mma<2, 0><<<dim3(HDV / 128, BT / 128, 1), 256, SM_2>>>(
        aoh, aoh, HDV, 0, 0, woth, wotl, HDV, 0, 0, out, HDV, 0, 0, HDV, HDV, 1.0f, b_out);
}

// round 9
// speedup vs baseline: 7.0589x; 1.1548x over previous
#include <cuda_runtime.h>
#include <cuda_fp16.h>
#include <math.h>
#include <stdint.h>

// Problem constants
#define Tn   1536
#define Bn   4
#define Hn   8
#define DKn  64
#define DVn  192
#define Ln   3071          // 2T-1
#define Lp   3072          // padded
#define HDK  512           // H*DK
#define HDV  1536          // H*DV
#define BT   6144          // B*T
#define NBH  32            // B*H
#define Cin  1536

// ---------------- device scratch ----------------
__device__ float  g_pe[Ln * 192];
__device__ float  g_rK[Ln * HDK];
__device__ double g_gmax[32];

__device__ float  g_Vf[BT * HDV];

__device__ half   g_xh[BT * Cin], g_xl[BT * Cin];
__device__ half   g_wqkh[1024 * Cin], g_wqkl[1024 * Cin];   // W_q^T | W_k^T concat
__device__ half   g_wvth[HDV * Cin], g_wvtl[HDV * Cin];
__device__ half   g_woth[HDV * HDV], g_wotl[HDV * HDV];

__device__ half   g_qwh[NBH * Tn * DKn], g_qwl[NBH * Tn * DKn];
__device__ half   g_qrh[NBH * Tn * DKn], g_qrl[NBH * Tn * DKn];
__device__ half   g_kh [NBH * Tn * DKn], g_kl [NBH * Tn * DKn];
__device__ half   g_rkth[Hn * Lp * DKn], g_rktl[Hn * Lp * DKn];
__device__ half   g_vth[NBH * DVn * Tn], g_vtl[NBH * DVn * Tn];

__device__ float  g_logits[75497472];     // 32*1536*1536 (holds rel after banded gemm)
__device__ half   g_aoh[BT * HDV];        // flash output fp16

// ============================================================
// helpers
// ============================================================
__device__ __forceinline__ uint32_t smem_u32(const void* p) {
    uint32_t a;
    asm("{ .reg .u64 t; cvta.to.shared.u64 t, %1; cvt.u32.u64 %0, t; }" : "=r"(a) : "l"(p));
    return a;
}
__device__ __forceinline__ void cp16(uint32_t s, const void* g) {
    asm volatile("cp.async.ca.shared.global [%0], [%1], 16;" :: "r"(s), "l"(g));
}
#define CP_COMMIT() asm volatile("cp.async.commit_group;" ::: "memory")
#define CP_WAIT(n)  asm volatile("cp.async.wait_group %0;" :: "n"(n) : "memory")

#define LDSM4(r, addr) \
    asm volatile("ldmatrix.sync.aligned.m8n8.x4.shared.b16 {%0,%1,%2,%3}, [%4];" \
        : "=r"((r)[0]), "=r"((r)[1]), "=r"((r)[2]), "=r"((r)[3]) : "r"(addr))

#define MMA(acc, a, b) \
    asm volatile("mma.sync.aligned.m16n8k16.row.col.f32.f16.f16.f32 " \
        "{%0,%1,%2,%3},{%4,%5,%6,%7},{%8,%9},{%0,%1,%2,%3};" \
        : "+f"((acc)[0]), "+f"((acc)[1]), "+f"((acc)[2]), "+f"((acc)[3]) \
        : "r"((a)[0]), "r"((a)[1]), "r"((a)[2]), "r"((a)[3]), "r"((b)[0]), "r"((b)[1]))

#define STS32(addr, v) \
    asm volatile("st.shared.b32 [%0], %1;" :: "r"(addr), "r"(v))

// ---------------- positional basis (validated) ----------------
__global__ void gamma_max_kernel(double* gmax) {
    __shared__ double red[256];
    int j = blockIdx.x, t = threadIdx.x;
    double conc  = 4.0 * (j + 1) * (j + 1);
    double rate  = (double)(j + 1) / 12.0;
    double lnorm = lgamma(conc) - conc * log(rate);
    double best = 0.0;
    for (int i = t; i < Ln; i += 256) {
        double pos = fabs((double)(i - (Tn - 1)));
        double lu = (conc - 1.0) * log(pos) - rate * pos;
        double pr = exp(lu - lnorm);
        if (pr > best) best = pr;
    }
    red[t] = best;
    __syncthreads();
    for (int s = 128; s; s >>= 1) {
        if (t < s) red[t] = fmax(red[t], red[t + s]);
        __syncthreads();
    }
    if (t == 0) gmax[j] = red[0] + 1e-8;
}

__global__ void pe_kernel(const double* __restrict__ gmax, float* __restrict__ pe) {
    int idx = blockIdx.x * blockDim.x + threadIdx.x;
    if (idx >= Ln * 32) return;
    int i = idx / 32, j = idx % 32;
    int dist = i - (Tn - 1);
    double pos = fabs((double)dist);
    double mr = log2((double)Tn);
    double hl = exp2(3.0 + (double)j * (mr - 3.0) / 31.0);
    double fe = exp2(-pos / hl);
    double width = exp2((double)(j + 1)) - 1.0;
    double fc = (width > pos) ? 1.0 : 0.0;
    double conc  = 4.0 * (j + 1) * (j + 1);
    double rate  = (double)(j + 1) / 12.0;
    double lnorm = lgamma(conc) - conc * log(rate);
    double pr = exp((conc - 1.0) * log(pos) - rate * pos - lnorm) + 1e-8;
    double fg = pr / gmax[j];
    float sgn = (dist > 0) ? 1.f : ((dist < 0) ? -1.f : 0.f);
    float* row = pe + (size_t)i * 192;
    row[j]       = (float)fe;
    row[32 + j]  = (float)fc;
    row[64 + j]  = (float)fg;
    row[96 + j]  = sgn * (float)fe;
    row[128 + j] = sgn * (float)fc;
    row[160 + j] = sgn * (float)fg;
}

// ---------------- small fp32 sgemm (rK only) ----------------
__global__ void sgemm_kernel(const float* __restrict__ A, int lda,
                             const float* __restrict__ B, int ldb,
                             float* __restrict__ C, int ldc,
                             int M, int N, int K) {
    __shared__ float As[16][68];
    __shared__ float Bs[16][68];
    int t  = threadIdx.x;
    int tx = t & 15, ty = t >> 4;
    int m0 = blockIdx.y * 64, n0 = blockIdx.x * 64;
    int ar = t >> 2, ac = (t & 3) * 4;
    int br = t >> 4, bc = (t & 15) * 4;
    float s[4][4] = {};
    for (int k0 = 0; k0 < K; k0 += 16) {
        float4 av = make_float4(0.f, 0.f, 0.f, 0.f);
        if (m0 + ar < M)
            av = *(const float4*)(A + (size_t)(m0 + ar) * lda + k0 + ac);
        float4 bv = *(const float4*)(B + (size_t)(k0 + br) * ldb + n0 + bc);
        __syncthreads();
        As[ac + 0][ar] = av.x; As[ac + 1][ar] = av.y;
        As[ac + 2][ar] = av.z; As[ac + 3][ar] = av.w;
        *(float4*)&Bs[br][bc] = bv;
        __syncthreads();
#pragma unroll
        for (int kk = 0; kk < 16; kk++) {
            float4 a = *(const float4*)&As[kk][ty * 4];
            float4 b = *(const float4*)&Bs[kk][tx * 4];
            s[0][0] += a.x * b.x; s[0][1] += a.x * b.y; s[0][2] += a.x * b.z; s[0][3] += a.x * b.w;
            s[1][0] += a.y * b.x; s[1][1] += a.y * b.y; s[1][2] += a.y * b.z; s[1][3] += a.y * b.w;
            s[2][0] += a.z * b.x; s[2][1] += a.z * b.y; s[2][2] += a.z * b.z; s[2][3] += a.z * b.w;
            s[3][0] += a.w * b.x; s[3][1] += a.w * b.y; s[3][2] += a.w * b.z; s[3][3] += a.w * b.w;
        }
    }
#pragma unroll
    for (int i = 0; i < 4; i++) {
        int m = m0 + ty * 4 + i;
        if (m < M) {
            float* cp = C + (size_t)m * ldc + n0 + tx * 4;
#pragma unroll
            for (int j = 0; j < 4; j++) cp[j] = s[i][j];
        }
    }
}

// ---------------- hi/lo split helpers (fp16) ----------------
__device__ __forceinline__ void split_h(float v, half* hi, half* lo, long o) {
    half h = __float2half_rn(v);
    hi[o] = h;
    lo[o] = __float2half_rn(v - __half2float(h));
}

// vectorized split: 4 floats per thread
__global__ void split_kernel(const float4* __restrict__ src, uint2* __restrict__ hi,
                             uint2* __restrict__ lo, int n4) {
    int i = blockIdx.x * 256 + threadIdx.x;
    if (i >= n4) return;
    float4 v = src[i];
    half h0 = __float2half_rn(v.x), h1 = __float2half_rn(v.y);
    half h2 = __float2half_rn(v.z), h3 = __float2half_rn(v.w);
    half2 hA = __halves2half2(h0, h1), hB = __halves2half2(h2, h3);
    half2 lA = __floats2half2_rn(v.x - __half2float(h0), v.y - __half2float(h1));
    half2 lB = __floats2half2_rn(v.z - __half2float(h2), v.w - __half2float(h3));
    uint2 ho, lw;
    ho.x = *(uint32_t*)&hA; ho.y = *(uint32_t*)&hB;
    lw.x = *(uint32_t*)&lA; lw.y = *(uint32_t*)&lB;
    hi[i] = ho;
    lo[i] = lw;
}

__global__ void tsplit_kernel(const float* __restrict__ src, int K, int N,
                              half* __restrict__ hi, half* __restrict__ lo) {
    __shared__ float tile[32][33];
    int n0 = blockIdx.x * 32, k0 = blockIdx.y * 32;
    int tx = threadIdx.x & 31, ty = threadIdx.x >> 5;
#pragma unroll
    for (int i = 0; i < 32; i += 8)
        tile[ty + i][tx] = src[(long)(k0 + ty + i) * N + n0 + tx];
    __syncthreads();
#pragma unroll
    for (int i = 0; i < 32; i += 8) {
        float v = tile[tx][ty + i];
        long o = (long)(n0 + ty + i) * K + k0 + tx;
        split_h(v, hi, lo, o);
    }
}

__global__ void rkt_kernel(const float* __restrict__ rK, half* rkth, half* rktl) {
    long i = (long)blockIdx.x * 256 + threadIdx.x;
    if (i >= (long)Hn * Lp * DKn) return;
    int d = (int)(i & 63);
    int l = (int)((i >> 6) % Lp);
    int h = (int)(i / ((long)Lp * DKn));
    float v = (l < Ln) ? rK[(long)l * HDK + h * DKn + d] : 0.f;
    split_h(v, rkth, rktl, i);
}

__global__ void vt_kernel(const float* __restrict__ Vf, half* vth, half* vtl) {
    __shared__ float tile[32][33];
    int z = blockIdx.z, h = z & 7, b = z >> 3;
    int t0 = blockIdx.x * 32, d0 = blockIdx.y * 32;
    int tx = threadIdx.x & 31, ty = threadIdx.x >> 5;
#pragma unroll
    for (int i = 0; i < 32; i += 8)
        tile[ty + i][tx] = Vf[((long)(b * Tn + t0 + ty + i)) * HDV + h * DVn + d0 + tx];
    __syncthreads();
#pragma unroll
    for (int i = 0; i < 32; i += 8) {
        float v = tile[tx][ty + i];
        long o = ((long)z * DVn + d0 + ty + i) * Tn + t0 + tx;
        split_h(v, vth, vtl, o);
    }
}

// ============================================================
// mma.sync fp16 GEMM (general):
//   NPASS 3: ah.bh+ah.bl+al.bh   NPASS 2: ah.bh+ah.bl (A hi only)
//   MODE 0: fp32 C = scale*acc + bias    MODE 2: banded shifted store (rel)
// ============================================================
template <int NPASS, int MODE>
__global__ void __launch_bounds__(256) gemm_mma(
    const half* __restrict__ Ah, const half* __restrict__ Al, int lda, long sA8, long sA1,
    const half* __restrict__ Bh, const half* __restrict__ Bl, int ldb, long sB8, long sB1,
    void* __restrict__ Cv, int ldc, long sC8, long sC1,
    int Kdim, int Ncols, float scale, const float* __restrict__ bias)
{
    constexpr int NA = (NPASS == 3) ? 2 : 1;
    constexpr int TILEA = 128 * 80;
    constexpr int TILEB = 128 * 80;
    constexpr int STAGE = NA * TILEA + 2 * TILEB;

    extern __shared__ char smem[];
    uint32_t sb = smem_u32(smem);
    int tid = threadIdx.x, lane = tid & 31, wid = tid >> 5;
    int wm = wid >> 2, wn = wid & 3;
    int z = blockIdx.z;
    int m0 = blockIdx.y * 128, n0 = blockIdx.x * 128;

    long zo_a = (long)(z >> 3) * sA8 + (long)(z & 7) * sA1;
    long zo_b = (long)(z >> 3) * sB8 + (long)(z & 7) * sB1;
    long zo_c = (long)(z >> 3) * sC8 + (long)(z & 7) * sC1;
    const half* pAh = Ah + zo_a + (long)m0 * lda;
    const half* pAl = Al + zo_a + (long)m0 * lda;
    long boff = (MODE == 2) ? (long)(Tn - 128 - m0 + n0) : (long)n0;
    const half* pBh = Bh + zo_b + boff * ldb;
    const half* pBl = Bl + zo_b + boff * ldb;

    float acc[4][4][4] = {};
    const int NC = Kdim >> 5;

    auto prefetch = [&](int kc) {
        int k0 = kc * 32;
        uint32_t s0 = sb + (kc & 1) * STAGE;
        for (int i = tid; i < 512; i += 256) {
            int r = i >> 2, c = i & 3;
            uint32_t so = (uint32_t)(r * 80 + c * 16);
            long go = (long)r * lda + k0 + c * 8;
            cp16(s0 + so, pAh + go);
            if (NPASS == 3) cp16(s0 + TILEA + so, pAl + go);
            long gb = (long)r * ldb + k0 + c * 8;
            cp16(s0 + NA * TILEA + so,         pBh + gb);
            cp16(s0 + NA * TILEA + TILEB + so, pBl + gb);
        }
        CP_COMMIT();
    };

    prefetch(0);
    for (int kc = 0; kc < NC; kc++) {
        CP_WAIT(0);
        __syncthreads();
        if (kc + 1 < NC) prefetch(kc + 1);
        uint32_t s0 = sb + (kc & 1) * STAGE;

#pragma unroll
        for (int kk = 0; kk < 2; kk++) {
            int k16 = kk * 16;
            uint32_t ah[4][4], al4[4][4], bh[4][2], bl4[4][2];
            uint32_t arow = (uint32_t)(wm * 64 + (lane & 15));
            uint32_t acol = (uint32_t)(k16 + (lane >> 4) * 8);
#pragma unroll
            for (int mi = 0; mi < 4; mi++) {
                uint32_t ao = s0 + (arow + mi * 16) * 80 + acol * 2;
                LDSM4(ah[mi], ao);
                if (NPASS == 3) LDSM4(al4[mi], ao + TILEA);
            }
            uint32_t brow = (uint32_t)(wn * 32 + (lane & 7) + ((lane >> 4) & 1) * 8);
            uint32_t bcol = (uint32_t)(k16 + ((lane >> 3) & 1) * 8);
#pragma unroll
            for (int g = 0; g < 2; g++) {
                uint32_t t4[4];
                uint32_t bo = s0 + NA * TILEA + (brow + g * 16) * 80 + bcol * 2;
                LDSM4(t4, bo);
                bh[g * 2][0] = t4[0]; bh[g * 2][1] = t4[1];
                bh[g * 2 + 1][0] = t4[2]; bh[g * 2 + 1][1] = t4[3];
                LDSM4(t4, bo + TILEB);
                bl4[g * 2][0] = t4[0]; bl4[g * 2][1] = t4[1];
                bl4[g * 2 + 1][0] = t4[2]; bl4[g * 2 + 1][1] = t4[3];
            }
#pragma unroll
            for (int mi = 0; mi < 4; mi++)
#pragma unroll
                for (int ni = 0; ni < 4; ni++) {
                    MMA(acc[mi][ni], ah[mi], bh[ni]);
                    MMA(acc[mi][ni], ah[mi], bl4[ni]);
                    if (NPASS == 3) MMA(acc[mi][ni], al4[mi], bh[ni]);
                }
        }
        __syncthreads();
    }

    int gID = lane >> 2, tig = lane & 3;
#pragma unroll
    for (int mi = 0; mi < 4; mi++) {
#pragma unroll
        for (int ni = 0; ni < 4; ni++) {
            int rloc = wm * 64 + mi * 16 + gID;
            int coll = wn * 32 + ni * 8 + tig * 2;
            int row0 = m0 + rloc;
            int col  = n0 + coll;
            if (MODE == 0) {
                float* Cf = (float*)Cv;
                if (col < Ncols) {
                    float b0 = bias ? bias[col] : 0.f;
                    float b1 = bias ? bias[col + 1] : 0.f;
                    float* p0 = Cf + zo_c + (long)row0 * ldc + col;
                    float* p1 = Cf + zo_c + (long)(row0 + 8) * ldc + col;
                    *(float2*)p0 = make_float2(acc[mi][ni][0] * scale + b0, acc[mi][ni][1] * scale + b1);
                    *(float2*)p1 = make_float2(acc[mi][ni][2] * scale + b0, acc[mi][ni][3] * scale + b1);
                }
            } else {
                float* Cf = (float*)Cv;
                int k0a = n0 + coll + rloc - 127;
                int k0b = k0a + 8;
                float* r0p = Cf + zo_c + (long)row0 * ldc;
                float* r1p = r0p + 8L * ldc;
                if (k0a >= 0     && k0a < Tn)     r0p[k0a]     = acc[mi][ni][0];
                if (k0a + 1 >= 0 && k0a + 1 < Tn) r0p[k0a + 1] = acc[mi][ni][1];
                if (k0b >= 0     && k0b < Tn)     r1p[k0b]     = acc[mi][ni][2];
                if (k0b + 1 >= 0 && k0b + 1 < Tn) r1p[k0b + 1] = acc[mi][ni][3];
            }
        }
    }
}

// ============================================================
// fused Q+K projection (R7 winner, unchanged)
// ============================================================
__global__ void __launch_bounds__(256) qkproj_kernel(
    const half* __restrict__ Ah, const half* __restrict__ Al,
    const half* __restrict__ Bh, const half* __restrict__ Bl,
    const float* __restrict__ rwb, const float* __restrict__ rrb,
    half* __restrict__ qwh, half* __restrict__ qwl,
    half* __restrict__ qrh, half* __restrict__ qrl,
    half* __restrict__ kh,  half* __restrict__ kl)
{
    constexpr int TILEA = 128 * 80;
    constexpr int TILEB = 128 * 80;
    constexpr int STAGE = 2 * TILEA + 2 * TILEB;

    extern __shared__ char smem[];
    uint32_t sb = smem_u32(smem);
    int tid = threadIdx.x, lane = tid & 31, wid = tid >> 5;
    int wm = wid >> 2, wn = wid & 3;
    int m0 = blockIdx.y * 128, n0 = blockIdx.x * 128;
    int bIdx = m0 / Tn, t0 = m0 % Tn;

    const half* pAh = Ah + (long)m0 * Cin;
    const half* pAl = Al + (long)m0 * Cin;
    const half* pBh = Bh + (long)n0 * Cin;
    const half* pBl = Bl + (long)n0 * Cin;

    float acc[4][4][4] = {};
    const int NC = Cin >> 5;

    auto prefetch = [&](int kc) {
        int k0 = kc * 32;
        uint32_t s0 = sb + (kc & 1) * STAGE;
        for (int i = tid; i < 512; i += 256) {
            int r = i >> 2, c = i & 3;
            uint32_t so = (uint32_t)(r * 80 + c * 16);
            long go = (long)r * Cin + k0 + c * 8;
            cp16(s0 + so,         pAh + go);
            cp16(s0 + TILEA + so, pAl + go);
            cp16(s0 + 2 * TILEA + so,         pBh + go);
            cp16(s0 + 2 * TILEA + TILEB + so, pBl + go);
        }
        CP_COMMIT();
    };

    prefetch(0);
    for (int kc = 0; kc < NC; kc++) {
        CP_WAIT(0);
        __syncthreads();
        if (kc + 1 < NC) prefetch(kc + 1);
        uint32_t s0 = sb + (kc & 1) * STAGE;

#pragma unroll
        for (int kk = 0; kk < 2; kk++) {
            int k16 = kk * 16;
            uint32_t ah[4][4], al4[4][4], bh[4][2], bl4[4][2];
            uint32_t arow = (uint32_t)(wm * 64 + (lane & 15));
            uint32_t acol = (uint32_t)(k16 + (lane >> 4) * 8);
#pragma unroll
            for (int mi = 0; mi < 4; mi++) {
                uint32_t ao = s0 + (arow + mi * 16) * 80 + acol * 2;
                LDSM4(ah[mi], ao);
                LDSM4(al4[mi], ao + TILEA);
            }
            uint32_t brow = (uint32_t)(wn * 32 + (lane & 7) + ((lane >> 4) & 1) * 8);
            uint32_t bcol = (uint32_t)(k16 + ((lane >> 3) & 1) * 8);
#pragma unroll
            for (int g = 0; g < 2; g++) {
                uint32_t t4[4];
                uint32_t bo = s0 + 2 * TILEA + (brow + g * 16) * 80 + bcol * 2;
                LDSM4(t4, bo);
                bh[g * 2][0] = t4[0]; bh[g * 2][1] = t4[1];
                bh[g * 2 + 1][0] = t4[2]; bh[g * 2 + 1][1] = t4[3];
                LDSM4(t4, bo + TILEB);
                bl4[g * 2][0] = t4[0]; bl4[g * 2][1] = t4[1];
                bl4[g * 2 + 1][0] = t4[2]; bl4[g * 2 + 1][1] = t4[3];
            }
#pragma unroll
            for (int mi = 0; mi < 4; mi++)
#pragma unroll
                for (int ni = 0; ni < 4; ni++) {
                    MMA(acc[mi][ni], ah[mi], bh[ni]);
                    MMA(acc[mi][ni], ah[mi], bl4[ni]);
                    MMA(acc[mi][ni], al4[mi], bh[ni]);
                }
        }
        __syncthreads();
    }

    int gID = lane >> 2, tig = lane & 3;
#pragma unroll
    for (int mi = 0; mi < 4; mi++) {
#pragma unroll
        for (int ni = 0; ni < 4; ni++) {
            int rloc = wm * 64 + mi * 16 + gID;
            int coll = wn * 32 + ni * 8 + tig * 2;
            int col  = n0 + coll;
#pragma unroll
            for (int half_i = 0; half_i < 2; half_i++) {
                int t = t0 + rloc + half_i * 8;
                float v0 = acc[mi][ni][half_i * 2 + 0];
                float v1 = acc[mi][ni][half_i * 2 + 1];
                if (col < 512) {
                    int h = col >> 6, d = col & 63;
                    long o = ((long)(bIdx * 8 + h) * Tn + t) * 64 + d;
                    float q0 = v0 * 0.125f, q1 = v1 * 0.125f;
                    float w0 = q0 + rwb[col], w1 = q1 + rwb[col + 1];
                    float r0 = q0 + rrb[col], r1 = q1 + rrb[col + 1];
                    half wh0 = __float2half_rn(w0), wh1 = __float2half_rn(w1);
                    half rh0 = __float2half_rn(r0), rh1 = __float2half_rn(r1);
                    *(half2*)(qwh + o) = __halves2half2(wh0, wh1);
                    *(half2*)(qwl + o) = __floats2half2_rn(w0 - __half2float(wh0), w1 - __half2float(wh1));
                    *(half2*)(qrh + o) = __halves2half2(rh0, rh1);
                    *(half2*)(qrl + o) = __floats2half2_rn(r0 - __half2float(rh0), r1 - __half2float(rh1));
                } else {
                    int ck = col - 512;
                    int h = ck >> 6, d = ck & 63;
                    long o = ((long)(bIdx * 8 + h) * Tn + t) * 64 + d;
                    half kh0 = __float2half_rn(v0), kh1 = __float2half_rn(v1);
                    *(half2*)(kh + o) = __halves2half2(kh0, kh1);
                    *(half2*)(kl + o) = __floats2half2_rn(v0 - __half2float(kh0), v1 - __half2float(kh1));
                }
            }
        }
    }
}

// ============================================================
// flash kernel (R6/R7 winner; z0 offset added for split launch)
// ============================================================
__global__ void __launch_bounds__(256) flash_kernel(
    const half* __restrict__ qwh_, const half* __restrict__ qwl_,
    const half* __restrict__ kh_,  const half* __restrict__ kl_,
    const half* __restrict__ vth_, const half* __restrict__ vtl_,
    const float* __restrict__ logits, half* __restrict__ aoh, int z0)
{
    extern __shared__ char smem[];
    uint32_t sb = smem_u32(smem);
    const uint32_t QB = sb, KB = sb + 40960, PB = sb + 81920, VB = sb + 122880;
    float* mArr = (float*)(smem + 184320);
    float* lArr = mArr + 128;
    float* aArr = lArr + 128;
    float* red  = aArr + 128;   // [128][4]

    int tid = threadIdx.x, lane = tid & 31, wid = tid >> 5;
    int wm = wid >> 2, wn = wid & 3;
    int wm2 = wid >> 1, wn2 = wid & 1;
    int gID = lane >> 2, tig = lane & 3;
    int z = blockIdx.z + z0;
    int q0 = blockIdx.y * 128;
    int h = z & 7, b = z >> 3;

    long zq = (long)z * Tn * DKn;
    const half* pQh = qwh_ + zq + (long)q0 * DKn;
    const half* pQl = qwl_ + zq + (long)q0 * DKn;
    const half* pKh = kh_ + zq;
    const half* pKl = kl_ + zq;
    long zv = (long)z * DVn * Tn;
    const float* pL = logits + (long)z * Tn * Tn + (long)q0 * Tn;

    for (int r = tid; r < 128; r += 256) { mArr[r] = -1e30f; lArr[r] = 0.f; }

    for (int i = tid; i < 1024; i += 256) {
        int r = i >> 3, c = i & 7;
        uint32_t off = (uint32_t)((c >> 2) * 10240 + r * 80 + (c & 3) * 16);
        cp16(QB + off,         pQh + (long)r * DKn + c * 8);
        cp16(QB + 20480 + off, pQl + (long)r * DKn + c * 8);
        cp16(KB + off,         pKh + (long)r * DKn + c * 8);
        cp16(KB + 20480 + off, pKl + (long)r * DKn + c * 8);
    }
    CP_COMMIT();

    float O[2][12][4] = {};

    auto loadK = [&](int kn) {
        const half* gh = pKh + (long)kn * 128 * DKn;
        const half* gl = pKl + (long)kn * 128 * DKn;
        for (int i = tid; i < 1024; i += 256) {
            int r = i >> 3, c = i & 7;
            uint32_t off = (uint32_t)((c >> 2) * 10240 + r * 80 + (c & 3) * 16);
            cp16(KB + off,         gh + (long)r * DKn + c * 8);
            cp16(KB + 20480 + off, gl + (long)r * DKn + c * 8);
        }
        CP_COMMIT();
    };

    for (int kt = 0; kt < 12; kt++) {
        CP_WAIT(0);
        __syncthreads();

        float S[4][4][4] = {};
#pragma unroll
        for (int chunk = 0; chunk < 2; chunk++) {
            uint32_t qbase = QB + chunk * 10240;
            uint32_t kbase = KB + chunk * 10240;
#pragma unroll
            for (int kk = 0; kk < 2; kk++) {
                int k16 = kk * 16;
                uint32_t ah[4][4], al4[4][4], bh[4][2], bl4[4][2];
                uint32_t arow = (uint32_t)(wm * 64 + (lane & 15));
                uint32_t acol = (uint32_t)(k16 + (lane >> 4) * 8);
#pragma unroll
                for (int mi = 0; mi < 4; mi++) {
                    uint32_t ao = qbase + (arow + mi * 16) * 80 + acol * 2;
                    LDSM4(ah[mi], ao);
                    LDSM4(al4[mi], ao + 20480);
                }
                uint32_t brow = (uint32_t)(wn * 32 + (lane & 7) + ((lane >> 4) & 1) * 8);
                uint32_t bcol = (uint32_t)(k16 + ((lane >> 3) & 1) * 8);
#pragma unroll
                for (int g = 0; g < 2; g++) {
                    uint32_t t4[4];
                    uint32_t bo = kbase + (brow + g * 16) * 80 + bcol * 2;
                    LDSM4(t4, bo);
                    bh[g * 2][0] = t4[0]; bh[g * 2][1] = t4[1];
                    bh[g * 2 + 1][0] = t4[2]; bh[g * 2 + 1][1] = t4[3];
                    LDSM4(t4, bo + 20480);
                    bl4[g * 2][0] = t4[0]; bl4[g * 2][1] = t4[1];
                    bl4[g * 2 + 1][0] = t4[2]; bl4[g * 2 + 1][1] = t4[3];
                }
#pragma unroll
                for (int mi = 0; mi < 4; mi++)
#pragma unroll
                    for (int ni = 0; ni < 4; ni++) {
                        MMA(S[mi][ni], ah[mi], bh[ni]);
                        MMA(S[mi][ni], ah[mi], bl4[ni]);
                        MMA(S[mi][ni], al4[mi], bh[ni]);
                    }
            }
        }

#pragma unroll
        for (int mi = 0; mi < 4; mi++) {
            int r0 = wm * 64 + mi * 16 + gID;
#pragma unroll
            for (int ni = 0; ni < 4; ni++) {
                long coff = (long)kt * 128 + wn * 32 + ni * 8 + tig * 2;
                float2 v0 = *(const float2*)(pL + (long)r0 * Tn + coff);
                float2 v1 = *(const float2*)(pL + (long)(r0 + 8) * Tn + coff);
                S[mi][ni][0] += v0.x; S[mi][ni][1] += v0.y;
                S[mi][ni][2] += v1.x; S[mi][ni][3] += v1.y;
            }
        }

#pragma unroll
        for (int mi = 0; mi < 4; mi++) {
            float m0v = -1e30f, m1v = -1e30f;
#pragma unroll
            for (int ni = 0; ni < 4; ni++) {
                m0v = fmaxf(m0v, fmaxf(S[mi][ni][0], S[mi][ni][1]));
                m1v = fmaxf(m1v, fmaxf(S[mi][ni][2], S[mi][ni][3]));
            }
            m0v = fmaxf(m0v, __shfl_xor_sync(0xffffffffu, m0v, 1));
            m0v = fmaxf(m0v, __shfl_xor_sync(0xffffffffu, m0v, 2));
            m1v = fmaxf(m1v, __shfl_xor_sync(0xffffffffu, m1v, 1));
            m1v = fmaxf(m1v, __shfl_xor_sync(0xffffffffu, m1v, 2));
            if (tig == 0) {
                int r0 = wm * 64 + mi * 16 + gID;
                red[r0 * 4 + wn] = m0v;
                red[(r0 + 8) * 4 + wn] = m1v;
            }
        }
        __syncthreads();

        float mns0[4], mns1[4], alp0[4], alp1[4], sum0[4], sum1[4];
#pragma unroll
        for (int mi = 0; mi < 4; mi++) {
            int r0 = wm * 64 + mi * 16 + gID, r1 = r0 + 8;
            float mo0 = mArr[r0], mo1 = mArr[r1];
            float mn0 = mo0, mn1 = mo1;
#pragma unroll
            for (int w = 0; w < 4; w++) {
                mn0 = fmaxf(mn0, red[r0 * 4 + w]);
                mn1 = fmaxf(mn1, red[r1 * 4 + w]);
            }
            float s0 = 0.f, s1 = 0.f;
#pragma unroll
            for (int ni = 0; ni < 4; ni++) {
                S[mi][ni][0] = __expf(S[mi][ni][0] - mn0);
                S[mi][ni][1] = __expf(S[mi][ni][1] - mn0);
                S[mi][ni][2] = __expf(S[mi][ni][2] - mn1);
                S[mi][ni][3] = __expf(S[mi][ni][3] - mn1);
                s0 += S[mi][ni][0] + S[mi][ni][1];
                s1 += S[mi][ni][2] + S[mi][ni][3];
            }
            s0 += __shfl_xor_sync(0xffffffffu, s0, 1);
            s0 += __shfl_xor_sync(0xffffffffu, s0, 2);
            s1 += __shfl_xor_sync(0xffffffffu, s1, 1);
            s1 += __shfl_xor_sync(0xffffffffu, s1, 2);
            mns0[mi] = mn0; mns1[mi] = mn1;
            alp0[mi] = __expf(mo0 - mn0); alp1[mi] = __expf(mo1 - mn1);
            sum0[mi] = s0; sum1[mi] = s1;
        }
        __syncthreads();

#pragma unroll
        for (int mi = 0; mi < 4; mi++) {
            int r0 = wm * 64 + mi * 16 + gID, r1 = r0 + 8;
            if (tig == 0) {
                red[r0 * 4 + wn] = sum0[mi];
                red[r1 * 4 + wn] = sum1[mi];
                if (wn == 0) { aArr[r0] = alp0[mi]; aArr[r1] = alp1[mi]; }
            }
#pragma unroll
            for (int ni = 0; ni < 4; ni++) {
                int colin = ni * 8 + tig * 2;
                half2 h0 = __floats2half2_rn(S[mi][ni][0], S[mi][ni][1]);
                half2 h1 = __floats2half2_rn(S[mi][ni][2], S[mi][ni][3]);
                uint32_t p0 = PB + wn * 10240 + r0 * 80 + colin * 2;
                uint32_t p1 = PB + wn * 10240 + r1 * 80 + colin * 2;
                STS32(p0, *(uint32_t*)&h0);
                STS32(p1, *(uint32_t*)&h1);
            }
        }
        __syncthreads();

        if (wn == 0 && tig == 0) {
#pragma unroll
            for (int mi = 0; mi < 4; mi++) {
                int r0 = wm * 64 + mi * 16 + gID, r1 = r0 + 8;
                lArr[r0] = lArr[r0] * alp0[mi] + red[r0 * 4 + 0] + red[r0 * 4 + 1] + red[r0 * 4 + 2] + red[r0 * 4 + 3];
                lArr[r1] = lArr[r1] * alp1[mi] + red[r1 * 4 + 0] + red[r1 * 4 + 1] + red[r1 * 4 + 2] + red[r1 * 4 + 3];
                mArr[r0] = mns0[mi];
                mArr[r1] = mns1[mi];
            }
        }

        {
            const half* gh = vth_ + zv + (long)kt * 128;
            const half* gl = vtl_ + zv + (long)kt * 128;
            for (int cc2 = 0; cc2 < 2; cc2++) {
                uint32_t vb = VB + cc2 * 30720;
                for (int i = tid; i < 768; i += 256) {
                    int r = i >> 2, c4 = i & 3;
                    uint32_t off = (uint32_t)(r * 80 + c4 * 16);
                    cp16(vb + off,         gh + (long)r * Tn + cc2 * 32 + c4 * 8);
                    cp16(vb + 15360 + off, gl + (long)r * Tn + cc2 * 32 + c4 * 8);
                }
                CP_COMMIT();
            }
            loadK((kt + 1 < 12) ? kt + 1 : 11);
        }

#pragma unroll
        for (int mi = 0; mi < 2; mi++) {
            float a0 = aArr[wm2 * 32 + mi * 16 + gID];
            float a1 = aArr[wm2 * 32 + mi * 16 + gID + 8];
#pragma unroll
            for (int ni = 0; ni < 12; ni++) {
                O[mi][ni][0] *= a0; O[mi][ni][1] *= a0;
                O[mi][ni][2] *= a1; O[mi][ni][3] *= a1;
            }
        }

        auto pvChunk = [&](int c) {
            uint32_t pb = PB + c * 10240;
            uint32_t vb = VB + (c & 1) * 30720;
#pragma unroll
            for (int kk = 0; kk < 2; kk++) {
                int k16 = kk * 16;
                uint32_t pa[2][4], vh[12][2], vl[12][2];
                uint32_t arow = (uint32_t)(wm2 * 32 + (lane & 15));
                uint32_t acol = (uint32_t)(k16 + (lane >> 4) * 8);
#pragma unroll
                for (int mi = 0; mi < 2; mi++)
                    LDSM4(pa[mi], pb + (arow + mi * 16) * 80 + acol * 2);
                uint32_t brow = (uint32_t)(wn2 * 96 + (lane & 7) + ((lane >> 4) & 1) * 8);
                uint32_t bcol = (uint32_t)(k16 + ((lane >> 3) & 1) * 8);
#pragma unroll
                for (int g = 0; g < 6; g++) {
                    uint32_t t4[4];
                    uint32_t bo = vb + (brow + g * 16) * 80 + bcol * 2;
                    LDSM4(t4, bo);
                    vh[g * 2][0] = t4[0]; vh[g * 2][1] = t4[1];
                    vh[g * 2 + 1][0] = t4[2]; vh[g * 2 + 1][1] = t4[3];
                    LDSM4(t4, bo + 15360);
                    vl[g * 2][0] = t4[0]; vl[g * 2][1] = t4[1];
                    vl[g * 2 + 1][0] = t4[2]; vl[g * 2 + 1][1] = t4[3];
                }
#pragma unroll
                for (int mi = 0; mi < 2; mi++)
#pragma unroll
                    for (int ni = 0; ni < 12; ni++) {
                        MMA(O[mi][ni], pa[mi], vh[ni]);
                        MMA(O[mi][ni], pa[mi], vl[ni]);
                    }
            }
        };
        auto loadV = [&](int c) {
            uint32_t vb = VB + (c & 1) * 30720;
            const half* gh = vth_ + zv + (long)kt * 128 + c * 32;
            const half* gl = vtl_ + zv + (long)kt * 128 + c * 32;
            for (int i = tid; i < 768; i += 256) {
                int r = i >> 2, c4 = i & 3;
                uint32_t off = (uint32_t)(r * 80 + c4 * 16);
                cp16(vb + off,         gh + (long)r * Tn + c4 * 8);
                cp16(vb + 15360 + off, gl + (long)r * Tn + c4 * 8);
            }
            CP_COMMIT();
        };

        CP_WAIT(2); __syncthreads();
        pvChunk(0);
        __syncthreads(); loadV(2);
        CP_WAIT(2); __syncthreads();
        pvChunk(1);
        __syncthreads(); loadV(3);
        CP_WAIT(1); __syncthreads();
        pvChunk(2);
        CP_WAIT(0); __syncthreads();
        pvChunk(3);
    }

    __syncthreads();
#pragma unroll
    for (int mi = 0; mi < 2; mi++) {
        int rl0 = wm2 * 32 + mi * 16 + gID, rl1 = rl0 + 8;
        float i0 = 1.f / lArr[rl0], i1 = 1.f / lArr[rl1];
        long base0 = ((long)(b * Tn + q0 + rl0)) * HDV + h * 192;
        long base1 = ((long)(b * Tn + q0 + rl1)) * HDV + h * 192;
#pragma unroll
        for (int ni = 0; ni < 12; ni++) {
            int col = wn2 * 96 + ni * 8 + tig * 2;
            *(half2*)(aoh + base0 + col) = __floats2half2_rn(O[mi][ni][0] * i0, O[mi][ni][1] * i0);
            *(half2*)(aoh + base1 + col) = __floats2half2_rn(O[mi][ni][2] * i1, O[mi][ni][3] * i1);
        }
    }
}

// ---------------- launch: forked-stream DAG ----------------
extern "C" void kernel_launch(void* const* d_in, const int* in_sizes, int n_in,
                              void* d_out, int out_size) {
    const float* x       = (const float*)d_in[0];
    const float* W_q     = (const float*)d_in[1];
    const float* W_k     = (const float*)d_in[2];
    const float* W_v     = (const float*)d_in[3];
    const float* W_rel_k = (const float*)d_in[4];
    const float* W_out   = (const float*)d_in[5];
    const float* b_out   = (const float*)d_in[6];
    const float* rwb     = (const float*)d_in[7];
    const float* rrb     = (const float*)d_in[8];
    float* out = (float*)d_out;

    float *pe, *rK, *Vf, *logits;
    double* gmax;
    half *xh, *xl, *wqkh, *wqkl, *wvth, *wvtl, *woth, *wotl;
    half *qwh, *qwl, *qrh, *qrl, *kh, *kl, *rkth, *rktl, *vth, *vtl, *aoh;
    cudaGetSymbolAddress((void**)&pe, g_pe);
    cudaGetSymbolAddress((void**)&rK, g_rK);
    cudaGetSymbolAddress((void**)&gmax, g_gmax);
    cudaGetSymbolAddress((void**)&Vf, g_Vf);
    cudaGetSymbolAddress((void**)&xh, g_xh);   cudaGetSymbolAddress((void**)&xl, g_xl);
    cudaGetSymbolAddress((void**)&wqkh, g_wqkh); cudaGetSymbolAddress((void**)&wqkl, g_wqkl);
    cudaGetSymbolAddress((void**)&wvth, g_wvth); cudaGetSymbolAddress((void**)&wvtl, g_wvtl);
    cudaGetSymbolAddress((void**)&woth, g_woth); cudaGetSymbolAddress((void**)&wotl, g_wotl);
    cudaGetSymbolAddress((void**)&qwh, g_qwh); cudaGetSymbolAddress((void**)&qwl, g_qwl);
    cudaGetSymbolAddress((void**)&qrh, g_qrh); cudaGetSymbolAddress((void**)&qrl, g_qrl);
    cudaGetSymbolAddress((void**)&kh, g_kh);   cudaGetSymbolAddress((void**)&kl, g_kl);
    cudaGetSymbolAddress((void**)&rkth, g_rkth); cudaGetSymbolAddress((void**)&rktl, g_rktl);
    cudaGetSymbolAddress((void**)&vth, g_vth); cudaGetSymbolAddress((void**)&vtl, g_vtl);
    cudaGetSymbolAddress((void**)&logits, g_logits);
    cudaGetSymbolAddress((void**)&aoh, g_aoh);

    const int SM_3 = 2 * (2 * 128 * 80 + 2 * 128 * 80);  // 81920
    const int SM_2 = 2 * (1 * 128 * 80 + 2 * 128 * 80);  // 61440
    const int SM_F = 187904;

    static bool inited = false;
    static cudaStream_t s1, s2;
    static cudaEvent_t evStart, evX, evRK, evVT, evRel, evD2;
    if (!inited) {
        cudaStreamCreateWithFlags(&s1, cudaStreamNonBlocking);
        cudaStreamCreateWithFlags(&s2, cudaStreamNonBlocking);
        cudaEventCreateWithFlags(&evStart, cudaEventDisableTiming);
        cudaEventCreateWithFlags(&evX, cudaEventDisableTiming);
        cudaEventCreateWithFlags(&evRK, cudaEventDisableTiming);
        cudaEventCreateWithFlags(&evVT, cudaEventDisableTiming);
        cudaEventCreateWithFlags(&evRel, cudaEventDisableTiming);
        cudaEventCreateWithFlags(&evD2, cudaEventDisableTiming);
        cudaFuncSetAttribute(gemm_mma<3, 2>, cudaFuncAttributeMaxDynamicSharedMemorySize, SM_3);
        cudaFuncSetAttribute(gemm_mma<2, 0>, cudaFuncAttributeMaxDynamicSharedMemorySize, SM_2);
        cudaFuncSetAttribute(qkproj_kernel, cudaFuncAttributeMaxDynamicSharedMemorySize, SM_3);
        cudaFuncSetAttribute(flash_kernel, cudaFuncAttributeMaxDynamicSharedMemorySize, SM_F);
        inited = true;
    }

    long sQ = (long)Tn * DKn;
    long sR = (long)Lp * DKn;

    // ---- fork ----
    cudaEventRecord(evStart, 0);
    cudaStreamWaitEvent(s1, evStart, 0);
    cudaStreamWaitEvent(s2, evStart, 0);

    // s1: positional basis chain -> rkt  (independent until rel)
    gamma_max_kernel<<<32, 256, 0, s1>>>(gmax);
    pe_kernel<<<(Ln * 32 + 255) / 256, 256, 0, s1>>>(gmax, pe);
    sgemm_kernel<<<dim3(HDK / 64, (Ln + 63) / 64), 256, 0, s1>>>(
        pe, 192, W_rel_k, HDK, rK, HDK, Ln, HDK, 192);
    rkt_kernel<<<(int)(((long)Hn * Lp * DKn + 255) / 256), 256, 0, s1>>>(rK, rkth, rktl);
    cudaEventRecord(evRK, s1);

    // s2: W_v tsplit (no deps)
    tsplit_kernel<<<dim3(HDV / 32, Cin / 32), 256, 0, s2>>>(W_v, Cin, HDV, wvth, wvtl);

    // s0: x split
    split_kernel<<<(BT * Cin / 4 + 255) / 256, 256>>>(
        (const float4*)x, (uint2*)xh, (uint2*)xl, BT * Cin / 4);
    cudaEventRecord(evX, 0);
    cudaStreamWaitEvent(s2, evX, 0);

    // s2: V projection (2-pass) + head transpose
    gemm_mma<2, 0><<<dim3(HDV / 128, BT / 128, 1), 256, SM_2, s2>>>(
        xh, xh, Cin, 0, 0, wvth, wvtl, Cin, 0, 0, Vf, HDV, 0, 0, Cin, HDV, 1.0f, nullptr);
    vt_kernel<<<dim3(Tn / 32, DVn / 32, NBH), 256, 0, s2>>>(Vf, vth, vtl);
    cudaEventRecord(evVT, s2);

    // s0: weight tsplits + fused QK projection
    tsplit_kernel<<<dim3(HDK / 32, Cin / 32), 256>>>(W_q, Cin, HDK, wqkh, wqkl);
    tsplit_kernel<<<dim3(HDK / 32, Cin / 32), 256>>>(W_k, Cin, HDK,
                                                     wqkh + (long)512 * Cin, wqkl + (long)512 * Cin);
    tsplit_kernel<<<dim3(HDV / 32, HDV / 32), 256>>>(W_out, HDV, HDV, woth, wotl);
    qkproj_kernel<<<dim3(1024 / 128, BT / 128, 1), 256, SM_3>>>(
        xh, xl, wqkh, wqkl, rwb, rrb, qwh, qwl, qrh, qrl, kh, kl);

    // s0: rel (needs rkt from s1)
    cudaStreamWaitEvent(0, evRK, 0);
    gemm_mma<3, 2><<<dim3(13, Tn / 128, NBH), 256, SM_3>>>(
        qrh, qrl, DKn, 8 * sQ, sQ, rkth, rktl, DKn, 0, sR,
        logits, Tn, 8L * Tn * Tn, (long)Tn * Tn, DKn, Tn, 1.0f, nullptr);
    cudaEventRecord(evRel, 0);

    // s0: flash for b=0,1 (z 0..15), then its out-proj half
    cudaStreamWaitEvent(0, evVT, 0);
    flash_kernel<<<dim3(1, Tn / 128, 16), 256, SM_F>>>(
        qwh, qwl, kh, kl, vth, vtl, logits, aoh, 0);
    gemm_mma<2, 0><<<dim3(HDV / 128, 2 * Tn / 128, 1), 256, SM_2>>>(
        aoh, aoh, HDV, 0, 0, woth, wotl, HDV, 0, 0, out, HDV, 0, 0, HDV, HDV, 1.0f, b_out);

    // s2: flash for b=2,3 (z 16..31), then its out-proj half
    cudaStreamWaitEvent(s2, evRel, 0);
    flash_kernel<<<dim3(1, Tn / 128, 16), 256, SM_F, s2>>>(
        qwh, qwl, kh, kl, vth, vtl, logits, aoh, 16);
    gemm_mma<2, 0><<<dim3(HDV / 128, 2 * Tn / 128, 1), 256, SM_2, s2>>>(
        aoh + (long)2 * Tn * HDV, aoh + (long)2 * Tn * HDV, HDV, 0, 0,
        woth, wotl, HDV, 0, 0,
        out + (long)2 * Tn * HDV, HDV, 0, 0, HDV, HDV, 1.0f, b_out);
    cudaEventRecord(evD2, s2);

    // ---- join ----
    cudaStreamWaitEvent(0, evD2, 0);
}